// round 7
// baseline (speedup 1.0000x reference)
#include <cuda_runtime.h>
#include <cstdint>
#include <cstddef>

#define NTHREADS 256
#define BATCH 8192

// ---------------------------------------------------------------------------
// Scratch arena (word offsets, 4B words; lifetimes verified):
//  c1    [0, 209715200)            float   conv1 out [b][64][20][20]
//  p1    [209715200, 262144000)    split32 pool1 out [b][64][10][10]
//  c2    [0, 104857600)            float   conv2 out [b][128][10][10]
//  p2    [104857600, 131072000)    split32 pool2 out
//  c3    [131072000, 183500800)    split32 conv3 out [b][256][5][5]
//  featsH[0, 26214400) featsL[26214400, 52428800)  pair-packed [25][8192][128w]
//  H     [52428800, 175308800)     float   [25][8192][600]
//  preds [183500800, 185548800)    float   [25][8192][10]
//  in2H  [185548800, 219955200) in2L [219955200, 254361600) [25][8192][168w]
// ---------------------------------------------------------------------------
__device__ float g_arena[262144000];     // 1.049 GB

static const size_t OFF_C1      = 0;
static const size_t OFF_P1      = 209715200;
static const size_t OFF_C2      = 0;
static const size_t OFF_P2      = 104857600;
static const size_t OFF_C3      = 131072000;
static const size_t OFF_FEATS_H = 0;
static const size_t OFF_FEATS_L = 26214400;
static const size_t OFF_H       = 52428800;
static const size_t OFF_PREDS   = 183500800;
static const size_t OFF_IN2_H   = 185548800;
static const size_t OFF_IN2_L   = 219955200;

// pre-split weight planes, pair-packed along k: word(kp,n) = bf16(k=2kp+1)<<16 | bf16(k=2kp)
__device__ uint32_t g_w2h[288 * 128],  g_w2l[288 * 128];
__device__ uint32_t g_w3h[576 * 256],  g_w3l[576 * 256];
__device__ uint32_t g_w4h[1152 * 256], g_w4l[1152 * 256];
__device__ uint32_t g_wah[25 * 168 * 600], g_wal[25 * 168 * 600];
__device__ float g_sc2[128], g_sh2[128];
__device__ float g_sc3[256], g_sh3[256];
__device__ float g_sc4[256], g_sh4[256];

// ---------------------------------------------------------------------------
// bf16 helpers
// ---------------------------------------------------------------------------
__device__ __forceinline__ uint32_t f2bf(float x)
{
    unsigned short h;
    asm("cvt.rn.bf16.f32 %0, %1;" : "=h"(h) : "f"(x));
    return (uint32_t)h;
}

// element-split32: hi bf16 in high halfword, lo bf16 in low halfword
__device__ __forceinline__ uint32_t split32(float x)
{
    uint32_t hb = f2bf(x);
    float r = x - __uint_as_float(hb << 16);
    uint32_t lb = f2bf(r);
    return (hb << 16) | lb;
}

// pair-pack two floats into (h-plane word, l-plane word)
__device__ __forceinline__ void packpair(float x0, float x1, uint32_t& wh, uint32_t& wl)
{
    uint32_t s0 = split32(x0), s1 = split32(x1);
    wh = __byte_perm(s0, s1, 0x7632);   // [s0.hi16, s1.hi16]
    wl = __byte_perm(s0, s1, 0x5410);   // [s0.lo16, s1.lo16]
}

__device__ __forceinline__ void mma16(float d[4], const uint32_t a[4],
                                      uint32_t b0, uint32_t b1)
{
    asm volatile(
        "mma.sync.aligned.m16n8k16.row.col.f32.bf16.bf16.f32 "
        "{%0,%1,%2,%3}, {%4,%5,%6,%7}, {%8,%9}, {%0,%1,%2,%3};\n"
        : "+f"(d[0]), "+f"(d[1]), "+f"(d[2]), "+f"(d[3])
        : "r"(a[0]), "r"(a[1]), "r"(a[2]), "r"(a[3]), "r"(b0), "r"(b1));
}

// ---------------------------------------------------------------------------
// prep: split+pack weights into bf16 planes + BN folds
// ---------------------------------------------------------------------------
__global__ __launch_bounds__(NTHREADS) void prep_kernel(
    const float* __restrict__ W2, const float* __restrict__ W3,
    const float* __restrict__ W4, const float* __restrict__ Wa,
    const float* __restrict__ b2, const float* __restrict__ g2, const float* __restrict__ be2,
    const float* __restrict__ m2, const float* __restrict__ v2,
    const float* __restrict__ b3, const float* __restrict__ g3, const float* __restrict__ be3,
    const float* __restrict__ m3, const float* __restrict__ v3,
    const float* __restrict__ b4, const float* __restrict__ g4, const float* __restrict__ be4,
    const float* __restrict__ m4, const float* __restrict__ v4)
{
    int i = blockIdx.x * NTHREADS + threadIdx.x;
    if (i < 36864) {                                   // w2: [288kp][128n]
        int kp = i >> 7, n = i & 127;
        packpair(W2[n * 576 + 2 * kp], W2[n * 576 + 2 * kp + 1], g_w2h[i], g_w2l[i]);
    }
    int i3 = i - 36864;
    if (i3 >= 0 && i3 < 147456) {                      // w3: [576kp][256n]
        int kp = i3 >> 8, n = i3 & 255;
        packpair(W3[n * 1152 + 2 * kp], W3[n * 1152 + 2 * kp + 1], g_w3h[i3], g_w3l[i3]);
    }
    int i4 = i - 36864 - 147456;
    if (i4 >= 0 && i4 < 294912) {                      // w4: [1152kp][256n]
        int kp = i4 >> 8, n = i4 & 255;
        packpair(W4[n * 2304 + 2 * kp], W4[n * 2304 + 2 * kp + 1], g_w4h[i4], g_w4l[i4]);
    }
    int ia = i - 36864 - 147456 - 294912;
    if (ia >= 0 && ia < 2520000) {                     // wa: [25z][168kp][600j]
        int z = ia / 100800, r = ia % 100800;
        int kp = r / 600, j = r % 600;
        const float* w = Wa + ((size_t)z * 336 + 2 * kp) * 600 + j;
        packpair(w[0], w[600], g_wah[ia], g_wal[ia]);
    }
    int ib = i - 36864 - 147456 - 294912 - 2520000;
    if (ib >= 0 && ib < 128) {
        float s = g2[ib] * rsqrtf(v2[ib] + 1e-5f);
        g_sc2[ib] = s; g_sh2[ib] = (b2[ib] - m2[ib]) * s + be2[ib];
    } else if (ib >= 128 && ib < 384) {
        int c = ib - 128;
        float s = g3[c] * rsqrtf(v3[c] + 1e-5f);
        g_sc3[c] = s; g_sh3[c] = (b3[c] - m3[c]) * s + be3[c];
    } else if (ib >= 384 && ib < 640) {
        int c = ib - 384;
        float s = g4[c] * rsqrtf(v4[c] + 1e-5f);
        g_sc4[c] = s; g_sh4[c] = (b4[c] - m4[c]) * s + be4[c];
    }
}

// ---------------------------------------------------------------------------
// conv1: 3 -> 64, 20x20, fused BN+ReLU, float out. One block per image.
// ---------------------------------------------------------------------------
__global__ __launch_bounds__(NTHREADS) void conv1_kernel(
    const float* __restrict__ x, const float* __restrict__ W,
    const float* __restrict__ bias, const float* __restrict__ gam,
    const float* __restrict__ bet, const float* __restrict__ mu,
    const float* __restrict__ var, float* __restrict__ out)
{
    __shared__ float sIn[3 * 22 * 22];
    __shared__ float sW[64 * 27];
    __shared__ float sScale[64], sShift[64];
    int b = blockIdx.x, tid = threadIdx.x;

    for (int i = tid; i < 3 * 22 * 22; i += NTHREADS) sIn[i] = 0.f;
    __syncthreads();
    const float* xb = x + (size_t)b * 1200;
    for (int i = tid; i < 1200; i += NTHREADS) {
        int ci = i / 400, p = i % 400, y = p / 20, xx = p % 20;
        sIn[ci * 484 + (y + 1) * 22 + (xx + 1)] = xb[i];
    }
    for (int i = tid; i < 1728; i += NTHREADS) sW[i] = W[i];
    if (tid < 64) {
        float sc = gam[tid] * rsqrtf(var[tid] + 1e-5f);
        sScale[tid] = sc;
        sShift[tid] = (bias[tid] - mu[tid]) * sc + bet[tid];
    }
    __syncthreads();

    int co = tid & 63, q = tid >> 6;
    float scale = sScale[co], shift = sShift[co];
    float* ob = out + ((size_t)b * 64 + co) * 400;
    for (int r = 0; r < 5; r++) {
        int y = q * 5 + r;
        float acc[20];
        #pragma unroll
        for (int xx = 0; xx < 20; xx++) acc[xx] = 0.f;
        #pragma unroll
        for (int ci = 0; ci < 3; ci++) {
            float w[9];
            #pragma unroll
            for (int k = 0; k < 9; k++) w[k] = sW[co * 27 + ci * 9 + k];
            const float* base = sIn + ci * 484 + y * 22;
            #pragma unroll
            for (int dy = 0; dy < 3; dy++) {
                const float* row = base + dy * 22;
                #pragma unroll
                for (int xx = 0; xx < 20; xx++)
                    acc[xx] += row[xx] * w[dy * 3] + row[xx + 1] * w[dy * 3 + 1]
                             + row[xx + 2] * w[dy * 3 + 2];
            }
        }
        #pragma unroll
        for (int xx = 0; xx < 20; xx++)
            ob[y * 20 + xx] = fmaxf(acc[xx] * scale + shift, 0.f);
    }
}

// ---------------------------------------------------------------------------
// maxpool 3x3 s2 p1, float in -> element-split32 out
// ---------------------------------------------------------------------------
__global__ __launch_bounds__(NTHREADS) void pool_split_kernel(
    const float* __restrict__ in, uint32_t* __restrict__ out,
    int C, int H, int OH, long long total)
{
    long long idx = (long long)blockIdx.x * NTHREADS + threadIdx.x;
    if (idx >= total) return;
    int W = H, OW = OH;
    int ox = (int)(idx % OW); long long t = idx / OW;
    int oy = (int)(t % OH);  t /= OH;
    int c  = (int)(t % C);   int b = (int)(t / C);
    const float* p = in + ((size_t)b * C + c) * H * W;
    float m = -3.402823466e38f;
    #pragma unroll
    for (int dy = 0; dy < 3; dy++) {
        int iy = 2 * oy - 1 + dy;
        if (iy < 0 || iy >= H) continue;
        #pragma unroll
        for (int dx = 0; dx < 3; dx++) {
            int ix = 2 * ox - 1 + dx;
            if (ix < 0 || ix >= W) continue;
            m = fmaxf(m, p[iy * W + ix]);
        }
    }
    out[idx] = split32(m);
}

// ---------------------------------------------------------------------------
// bf16 tensor-core GEMM, 3-product (Ah·Bh + Al·Bh + Ah·Bl) scheme.
// Tile 128x128x16, 8 warps (4x2), m16n8k16. smem: interleaved uint2{h,l}
// planes, stride 12 uint2/row (conflict-free LDS.64), double-buffered,
// ONE __syncthreads per k-chunk.
// EPI: 0 float [b][128][100]; 1 split32 [b][256][25];
//      2 pair-packed feats h/l [n][b][128w]; 3 float tanh H[z][8192][600]
// ---------------------------------------------------------------------------
#define GEMM_FETCH(kc_)                                                          \
    {                                                                            \
        int kc__ = (kc_);                                                        \
        if (CC == 0) {                                                           \
            uint4 h4 = *(const uint4*)(Abh + (size_t)(mBase + lm) * aw           \
                                       + (kc__ >> 1) + (lkq >> 1));              \
            uint4 l4 = *(const uint4*)(Abl + (size_t)(mBase + lm) * aw           \
                                       + (kc__ >> 1) + (lkq >> 1));              \
            avh[0] = h4.x; avh[1] = h4.y; avh[2] = h4.z; avh[3] = h4.w;          \
            avl[0] = l4.x; avl[1] = l4.y; avl[2] = l4.z; avl[3] = l4.w;          \
        } else {                                                                 \
            uint32_t e[8];                                                       \
            _Pragma("unroll")                                                    \
            for (int j = 0; j < 8; j++) {                                        \
                int k = kc__ + lkq + j;                                          \
                int ci = k / 9, q = k - ci * 9;                                  \
                int iy = py - 1 + q / 3, ix = px - 1 + q % 3;                    \
                uint32_t v = 0u;                                                 \
                if (iy >= 0 && iy < S && ix >= 0 && ix < S)                      \
                    v = A[ib_off + ci * S * S + iy * S + ix];                    \
                e[j] = v;                                                        \
            }                                                                    \
            _Pragma("unroll")                                                    \
            for (int tt = 0; tt < 4; tt++) {                                     \
                avh[tt] = __byte_perm(e[2 * tt], e[2 * tt + 1], 0x7632);         \
                avl[tt] = __byte_perm(e[2 * tt], e[2 * tt + 1], 0x5410);         \
            }                                                                    \
        }                                                                        \
        _Pragma("unroll")                                                        \
        for (int jj = 0; jj < 4; jj++) {                                         \
            int kp = (kc__ >> 1) + (lkq >> 1) + jj;                              \
            bvh[jj] = (gn < N) ? Bbh[(size_t)kp * ldb + gn] : 0u;                \
            bvl[jj] = (gn < N) ? Bbl[(size_t)kp * ldb + gn] : 0u;                \
        }                                                                        \
    }

template <int EPI, int CC, int S>
__global__ __launch_bounds__(NTHREADS, 2) void gemm_bf16(
    const uint32_t* __restrict__ A, const uint32_t* __restrict__ A2,
    const uint32_t* __restrict__ Bh, const uint32_t* __restrict__ Bl,
    void* __restrict__ Cv, void* __restrict__ C2v,
    const float* __restrict__ sc, const float* __restrict__ sh,
    const float* __restrict__ bias,
    int K, int N, int ldb, int aw, int bStrideZ, int kpOff)
{
    // dynamic smem: [bufA0 | bufA1 | bufB0 | bufB1], each 128*12 uint2
    extern __shared__ uint2 smem[];
    uint2* sAb[2] = { smem,              smem + 1536 };
    uint2* sBb[2] = { smem + 3072,       smem + 4608 };

    int z = blockIdx.z;
    const uint32_t* Abh = A;
    const uint32_t* Abl = A2;
    const uint32_t* Bbh = Bh + (size_t)kpOff * ldb;
    const uint32_t* Bbl = Bl + (size_t)kpOff * ldb;
    if (EPI == 3) {
        Abh += (size_t)z * 8192 * aw;
        Abl += (size_t)z * 8192 * aw;
        Bbh += (size_t)z * bStrideZ;
        Bbl += (size_t)z * bStrideZ;
    }
    int mBase = blockIdx.y * 128, nBase = blockIdx.x * 128;
    int t = threadIdx.x, lane = t & 31, wid = t >> 5;
    int wm = (wid & 3) * 32, wn = (wid >> 2) * 64;
    int lc = lane & 3, lr = lane >> 2;

    int lm = t & 127, lkq = (t >> 7) * 8;
    int gn = nBase + lm;

    int ib_off = 0, py = 0, px = 0;
    if (CC > 0) {
        const int SS = S * S;
        int r = mBase + lm;
        int b = r / SS, p = r - b * SS;
        py = p / S; px = p - py * S;
        ib_off = b * CC * SS;
    }

    float acc[2][8][4];
    #pragma unroll
    for (int mt = 0; mt < 2; mt++)
        #pragma unroll
        for (int nt = 0; nt < 8; nt++)
            #pragma unroll
            for (int e = 0; e < 4; e++) acc[mt][nt][e] = 0.f;

    uint32_t avh[4], avl[4], bvh[4], bvl[4];
    GEMM_FETCH(0);

    int nch = K / 16;
    for (int ch = 0; ch < nch; ch++) {
        int buf = ch & 1;
        {
            uint2* pa = sAb[buf] + lm * 12 + (lkq >> 1);
            uint2* pb = sBb[buf] + lm * 12 + (lkq >> 1);
            #pragma unroll
            for (int j = 0; j < 4; j++) {
                pa[j] = make_uint2(avh[j], avl[j]);
                pb[j] = make_uint2(bvh[j], bvl[j]);
            }
        }
        __syncthreads();

        int kcn = (ch + 1 < nch) ? (ch + 1) * 16 : 0;
        GEMM_FETCH(kcn);

        const uint2* bA = sAb[buf];
        const uint2* bB = sBb[buf];
        uint32_t fah[2][4], fal[2][4];
        #pragma unroll
        for (int mt = 0; mt < 2; mt++) {
            int mr = wm + mt * 16 + lr;
            uint2 q0 = bA[mr * 12 + lc];
            uint2 q1 = bA[(mr + 8) * 12 + lc];
            uint2 q2 = bA[mr * 12 + lc + 4];
            uint2 q3 = bA[(mr + 8) * 12 + lc + 4];
            fah[mt][0] = q0.x; fal[mt][0] = q0.y;
            fah[mt][1] = q1.x; fal[mt][1] = q1.y;
            fah[mt][2] = q2.x; fal[mt][2] = q2.y;
            fah[mt][3] = q3.x; fal[mt][3] = q3.y;
        }
        #pragma unroll
        for (int nt = 0; nt < 8; nt++) {
            int nc = wn + nt * 8 + lr;
            uint2 g0 = bB[nc * 12 + lc];
            uint2 g1 = bB[nc * 12 + lc + 4];
            #pragma unroll
            for (int mt = 0; mt < 2; mt++) {
                mma16(acc[mt][nt], fah[mt], g0.x, g1.x);
                mma16(acc[mt][nt], fal[mt], g0.x, g1.x);
                mma16(acc[mt][nt], fah[mt], g0.y, g1.y);
            }
        }
    }

    // epilogue
    #pragma unroll
    for (int mt = 0; mt < 2; mt++) {
        #pragma unroll
        for (int nt = 0; nt < 8; nt++) {
            if (EPI == 2) {
                #pragma unroll
                for (int rr = 0; rr < 2; rr++) {
                    int row = mBase + wm + mt * 16 + lr + rr * 8;
                    int col = nBase + wn + nt * 8 + 2 * lc;
                    float v0 = acc[mt][nt][rr * 2 + 0];
                    float v1 = acc[mt][nt][rr * 2 + 1];
                    v0 = fmaxf(v0 * sc[col] + sh[col], 0.f);
                    v1 = fmaxf(v1 * sc[col + 1] + sh[col + 1], 0.f);
                    int b = row / 25, p = row - b * 25;
                    uint32_t wh, wl;
                    packpair(v0, v1, wh, wl);
                    size_t o = ((size_t)p * 8192 + b) * 128 + (col >> 1);
                    ((uint32_t*)Cv)[o]  = wh;
                    ((uint32_t*)C2v)[o] = wl;
                }
            } else {
                #pragma unroll
                for (int e = 0; e < 4; e++) {
                    int row = mBase + wm + mt * 16 + lr + (e >> 1) * 8;
                    int col = nBase + wn + nt * 8 + 2 * lc + (e & 1);
                    float v = acc[mt][nt][e];
                    if (EPI == 0) {
                        int b = row / 100, p = row - b * 100;
                        ((float*)Cv)[((size_t)b * 128 + col) * 100 + p] =
                            fmaxf(v * sc[col] + sh[col], 0.f);
                    } else if (EPI == 1) {
                        int b = row / 25, p = row - b * 25;
                        ((uint32_t*)Cv)[((size_t)b * 256 + col) * 25 + p] =
                            split32(fmaxf(v * sc[col] + sh[col], 0.f));
                    } else {
                        if (col < N)
                            ((float*)Cv)[((size_t)z * 8192 + row) * 600 + col] =
                                tanhf(v + bias[(size_t)z * 600 + col]);
                    }
                }
            }
        }
    }
}

// ---------------------------------------------------------------------------
// GEMM2 + softmax (600 -> 10), warp per row, Wb in smem (pad 11)
// ---------------------------------------------------------------------------
__global__ __launch_bounds__(NTHREADS) void gemm2_softmax_kernel(
    const float* __restrict__ H, const float* __restrict__ Wb,
    const float* __restrict__ bb, float* __restrict__ out)
{
    __shared__ float sW[600 * 11];
    __shared__ float sb[10];
    int n = blockIdx.y, tid = threadIdx.x;
    const float* Wn = Wb + (size_t)n * 6000;
    for (int i = tid; i < 6000; i += NTHREADS) {
        int k = i / 10, c = i % 10;
        sW[k * 11 + c] = Wn[i];
    }
    if (tid < 10) sb[tid] = bb[n * 10 + tid];
    __syncthreads();

    int warp = tid >> 5, lane = tid & 31;
    int b = blockIdx.x * 8 + warp;
    const float* hr = H + ((size_t)n * 8192 + b) * 600;
    float acc[10];
    #pragma unroll
    for (int c = 0; c < 10; c++) acc[c] = 0.f;
    for (int k = lane; k < 600; k += 32) {
        float v = hr[k];
        #pragma unroll
        for (int c = 0; c < 10; c++) acc[c] += v * sW[k * 11 + c];
    }
    #pragma unroll
    for (int c = 0; c < 10; c++) {
        #pragma unroll
        for (int off = 16; off > 0; off >>= 1)
            acc[c] += __shfl_down_sync(0xffffffffu, acc[c], off);
    }
    if (lane == 0) {
        float l[10], mx = -3.402823466e38f;
        #pragma unroll
        for (int c = 0; c < 10; c++) { l[c] = acc[c] + sb[c]; mx = fmaxf(mx, l[c]); }
        float s = 0.f;
        #pragma unroll
        for (int c = 0; c < 10; c++) { l[c] = expf(l[c] - mx); s += l[c]; }
        float inv = 1.f / s;
        float* o = out + ((size_t)n * 8192 + b) * 10;
        #pragma unroll
        for (int c = 0; c < 10; c++) o[c] = l[c] * inv;
    }
}

// ---------------------------------------------------------------------------
// neighbor gather -> pair-packed in2 planes
// ---------------------------------------------------------------------------
__device__ __forceinline__ int nei_of(int i, int slot)
{
    int nb[8];
    #pragma unroll
    for (int t = 0; t < 8; t++) nb[t] = -1;
    int cnt = 0;
    bool l = (i % 5 != 0), r = ((i + 1) % 5 != 0), u = (i >= 5), d = (i + 5 < 25);
    if (u)      nb[cnt++] = i - 5;
    if (l)      nb[cnt++] = i - 1;
    if (r)      nb[cnt++] = i + 1;
    if (d)      nb[cnt++] = i + 5;
    if (u && l) nb[cnt++] = i - 6;
    if (u && r) nb[cnt++] = i - 4;
    if (d && l) nb[cnt++] = i + 4;
    if (d && r) nb[cnt++] = i + 6;
    return nb[slot];
}

__global__ __launch_bounds__(NTHREADS) void gather_kernel(
    const float* __restrict__ preds,
    const uint32_t* __restrict__ fh, const uint32_t* __restrict__ fl,
    uint32_t* __restrict__ ih, uint32_t* __restrict__ il)
{
    long long idx = (long long)blockIdx.x * NTHREADS + threadIdx.x;
    if (idx >= 25LL * 8192 * 168) return;
    int j = (int)(idx % 168);
    long long t = idx / 168;
    int b = (int)(t % 8192);
    int n = (int)(t / 8192);
    uint32_t wh, wl;
    if (j >= 40) {
        size_t src = ((size_t)n * 8192 + b) * 128 + (j - 40);
        wh = fh[src]; wl = fl[src];
    } else {
        int c0 = (2 * j) % 10, s = (2 * j) / 10;
        int nei = nei_of(n, s);
        float p0 = 0.f, p1 = 0.f;
        if (nei >= 0) {
            const float* pp = preds + ((size_t)nei * 8192 + b) * 10 + c0;
            p0 = pp[0]; p1 = pp[1];
        }
        packpair(p0, p1, wh, wl);
    }
    ih[idx] = wh;
    il[idx] = wl;
}

__global__ __launch_bounds__(NTHREADS) void mean_kernel(
    const float* __restrict__ second, float* __restrict__ mean)
{
    int idx = blockIdx.x * NTHREADS + threadIdx.x;
    if (idx >= 81920) return;
    float s = 0.f;
    #pragma unroll
    for (int n = 0; n < 25; n++) s += second[(size_t)n * 81920 + idx];
    mean[idx] = s * 0.04f;
}

// ---------------------------------------------------------------------------
// launch
// ---------------------------------------------------------------------------
extern "C" void kernel_launch(void* const* d_in, const int* in_sizes, int n_in,
                              void* d_out, int out_size)
{
    (void)in_sizes; (void)n_in; (void)out_size;
    const int SMEM_GEMM = 6144 * 8;    // 49,152 B: 2 bufs x (A+B) x 128x12 uint2
    float* arena = nullptr;
    uint32_t *w2h, *w2l, *w3h, *w3l, *w4h, *w4l, *wah, *wal;
    float *sc2, *sh2, *sc3, *sh3, *sc4, *sh4;
    cudaGetSymbolAddress((void**)&arena, g_arena);
    cudaGetSymbolAddress((void**)&w2h, g_w2h);  cudaGetSymbolAddress((void**)&w2l, g_w2l);
    cudaGetSymbolAddress((void**)&w3h, g_w3h);  cudaGetSymbolAddress((void**)&w3l, g_w3l);
    cudaGetSymbolAddress((void**)&w4h, g_w4h);  cudaGetSymbolAddress((void**)&w4l, g_w4l);
    cudaGetSymbolAddress((void**)&wah, g_wah);  cudaGetSymbolAddress((void**)&wal, g_wal);
    cudaGetSymbolAddress((void**)&sc2, g_sc2);  cudaGetSymbolAddress((void**)&sh2, g_sh2);
    cudaGetSymbolAddress((void**)&sc3, g_sc3);  cudaGetSymbolAddress((void**)&sh3, g_sh3);
    cudaGetSymbolAddress((void**)&sc4, g_sc4);  cudaGetSymbolAddress((void**)&sh4, g_sh4);
    uint32_t* arenau = (uint32_t*)arena;

    cudaFuncSetAttribute(gemm_bf16<0, 64, 10>,
                         cudaFuncAttributeMaxDynamicSharedMemorySize, SMEM_GEMM);
    cudaFuncSetAttribute(gemm_bf16<1, 128, 5>,
                         cudaFuncAttributeMaxDynamicSharedMemorySize, SMEM_GEMM);
    cudaFuncSetAttribute(gemm_bf16<2, 256, 5>,
                         cudaFuncAttributeMaxDynamicSharedMemorySize, SMEM_GEMM);
    cudaFuncSetAttribute(gemm_bf16<3, 0, 0>,
                         cudaFuncAttributeMaxDynamicSharedMemorySize, SMEM_GEMM);

    const float* x   = (const float*)d_in[0];
    const float* W1  = (const float*)d_in[1];
    const float* b1  = (const float*)d_in[2];
    const float* g1  = (const float*)d_in[3];
    const float* be1 = (const float*)d_in[4];
    const float* m1  = (const float*)d_in[5];
    const float* v1  = (const float*)d_in[6];
    const float* W2  = (const float*)d_in[7];
    const float* b2  = (const float*)d_in[8];
    const float* g2  = (const float*)d_in[9];
    const float* be2 = (const float*)d_in[10];
    const float* m2  = (const float*)d_in[11];
    const float* v2  = (const float*)d_in[12];
    const float* W3  = (const float*)d_in[13];
    const float* b3  = (const float*)d_in[14];
    const float* g3  = (const float*)d_in[15];
    const float* be3 = (const float*)d_in[16];
    const float* m3  = (const float*)d_in[17];
    const float* v3  = (const float*)d_in[18];
    const float* W4  = (const float*)d_in[19];
    const float* b4  = (const float*)d_in[20];
    const float* g4  = (const float*)d_in[21];
    const float* be4 = (const float*)d_in[22];
    const float* m4  = (const float*)d_in[23];
    const float* v4  = (const float*)d_in[24];
    const float* Wa  = (const float*)d_in[25];
    const float* ba  = (const float*)d_in[26];
    const float* Wb  = (const float*)d_in[27];
    const float* bb  = (const float*)d_in[28];
    float* out = (float*)d_out;

    // prep: weight splits + BN folds
    prep_kernel<<<11719, NTHREADS>>>(W2, W3, W4, Wa,
        b2, g2, be2, m2, v2, b3, g3, be3, m3, v3, b4, g4, be4, m4, v4);

    // conv1 (float) + pool1 (split32)
    conv1_kernel<<<BATCH, NTHREADS>>>(x, W1, b1, g1, be1, m1, v1, arena + OFF_C1);
    {
        long long total = (long long)BATCH * 64 * 100;
        pool_split_kernel<<<(int)((total + NTHREADS - 1) / NTHREADS), NTHREADS>>>(
            arena + OFF_C1, arenau + OFF_P1, 64, 20, 10, total);
    }
    // conv2: implicit-im2col bf16 GEMM (K=576, N=128) -> float c2
    gemm_bf16<0, 64, 10><<<dim3(1, 6400, 1), NTHREADS, SMEM_GEMM>>>(
        arenau + OFF_P1, nullptr, w2h, w2l, arena + OFF_C2, nullptr,
        sc2, sh2, nullptr, 576, 128, 128, 0, 0, 0);
    // pool2 (split32)
    {
        long long total = (long long)BATCH * 128 * 25;
        pool_split_kernel<<<(int)((total + NTHREADS - 1) / NTHREADS), NTHREADS>>>(
            arena + OFF_C2, arenau + OFF_P2, 128, 10, 5, total);
    }
    // conv3 (K=1152, N=256) -> split32 c3
    gemm_bf16<1, 128, 5><<<dim3(2, 1600, 1), NTHREADS, SMEM_GEMM>>>(
        arenau + OFF_P2, nullptr, w3h, w3l, arenau + OFF_C3, nullptr,
        sc3, sh3, nullptr, 1152, 256, 256, 0, 0, 0);
    // conv4 (K=2304, N=256) -> pair-packed feats h/l
    gemm_bf16<2, 256, 5><<<dim3(2, 1600, 1), NTHREADS, SMEM_GEMM>>>(
        arenau + OFF_C3, nullptr, w4h, w4l,
        arenau + OFF_FEATS_H, arenau + OFF_FEATS_L,
        sc4, sh4, nullptr, 2304, 256, 256, 0, 0, 0);
    // stage 1 MLP (K=256, Wa rows 80:336 -> kpOff=40) -> float H
    gemm_bf16<3, 0, 0><<<dim3(5, 64, 25), NTHREADS, SMEM_GEMM>>>(
        arenau + OFF_FEATS_H, arenau + OFF_FEATS_L, wah, wal,
        arena + OFF_H, nullptr, nullptr, nullptr, ba,
        256, 600, 600, 128, 100800, 40);
    gemm2_softmax_kernel<<<dim3(1024, 25), NTHREADS>>>(arena + OFF_H, Wb, bb,
                                                       arena + OFF_PREDS);
    // gather -> pair-packed in2 h/l
    {
        long long total = 25LL * 8192 * 168;
        gather_kernel<<<(int)((total + NTHREADS - 1) / NTHREADS), NTHREADS>>>(
            arena + OFF_PREDS, arenau + OFF_FEATS_H, arenau + OFF_FEATS_L,
            arenau + OFF_IN2_H, arenau + OFF_IN2_L);
    }
    // stage 2 MLP (K=336)
    gemm_bf16<3, 0, 0><<<dim3(5, 64, 25), NTHREADS, SMEM_GEMM>>>(
        arenau + OFF_IN2_H, arenau + OFF_IN2_L, wah, wal,
        arena + OFF_H, nullptr, nullptr, nullptr, ba,
        336, 600, 600, 168, 100800, 0);
    gemm2_softmax_kernel<<<dim3(1024, 25), NTHREADS>>>(arena + OFF_H, Wb, bb,
                                                       out + 81920);
    mean_kernel<<<320, NTHREADS>>>(out + 81920, out);
}

// round 8
// speedup vs baseline: 1.2680x; 1.2680x over previous
#include <cuda_runtime.h>
#include <cstdint>
#include <cstddef>

#define NTHREADS 256
#define BATCH 8192

// ---------------------------------------------------------------------------
// Scratch arena (word offsets, 4B words; lifetimes verified):
//  c1    [0, 209715200)            float   conv1 out [b][64][20][20]
//  p1    [209715200, 262144000)    split32 pool1 out [b][64][10][10]
//  c2    [0, 104857600)            float   conv2 out [b][128][10][10]
//  p2    [104857600, 131072000)    split32 pool2 out
//  c3    [131072000, 183500800)    split32 conv3 out [b][256][5][5]
//  featsH[0, 26214400) featsL[26214400, 52428800)  pair-packed [25][8192][128w]
//  H     [52428800, 175308800)     float   [25][8192][600]
//  preds [183500800, 185548800)    float   [25][8192][10]
//  in2H  [185548800, 219955200) in2L [219955200, 254361600) [25][8192][168w]
// ---------------------------------------------------------------------------
__device__ float g_arena[262144000];     // 1.049 GB

static const size_t OFF_C1      = 0;
static const size_t OFF_P1      = 209715200;
static const size_t OFF_C2      = 0;
static const size_t OFF_P2      = 104857600;
static const size_t OFF_C3      = 131072000;
static const size_t OFF_FEATS_H = 0;
static const size_t OFF_FEATS_L = 26214400;
static const size_t OFF_H       = 52428800;
static const size_t OFF_PREDS   = 183500800;
static const size_t OFF_IN2_H   = 185548800;
static const size_t OFF_IN2_L   = 219955200;

// pre-split weight planes, pair-packed along k: word(kp,n) = bf16(k=2kp+1)<<16 | bf16(k=2kp)
__device__ uint32_t g_w2h[288 * 128],  g_w2l[288 * 128];
__device__ uint32_t g_w3h[576 * 256],  g_w3l[576 * 256];
__device__ uint32_t g_w4h[1152 * 256], g_w4l[1152 * 256];
__device__ uint32_t g_wah[25 * 168 * 600], g_wal[25 * 168 * 600];
__device__ float g_sc2[128], g_sh2[128];
__device__ float g_sc3[256], g_sh3[256];
__device__ float g_sc4[256], g_sh4[256];

// ---------------------------------------------------------------------------
// bf16 helpers
// ---------------------------------------------------------------------------
__device__ __forceinline__ uint32_t f2bf(float x)
{
    unsigned short h;
    asm("cvt.rn.bf16.f32 %0, %1;" : "=h"(h) : "f"(x));
    return (uint32_t)h;
}

// element-split32: hi bf16 in high halfword, lo bf16 in low halfword
__device__ __forceinline__ uint32_t split32(float x)
{
    uint32_t hb = f2bf(x);
    float r = x - __uint_as_float(hb << 16);
    uint32_t lb = f2bf(r);
    return (hb << 16) | lb;
}

// pair-pack two floats into (h-plane word, l-plane word)
__device__ __forceinline__ void packpair(float x0, float x1, uint32_t& wh, uint32_t& wl)
{
    uint32_t s0 = split32(x0), s1 = split32(x1);
    wh = __byte_perm(s0, s1, 0x7632);   // [s0.hi16, s1.hi16]
    wl = __byte_perm(s0, s1, 0x5410);   // [s0.lo16, s1.lo16]
}

__device__ __forceinline__ void mma16(float d[4], const uint32_t a[4], const uint32_t b[2])
{
    asm volatile(
        "mma.sync.aligned.m16n8k16.row.col.f32.bf16.bf16.f32 "
        "{%0,%1,%2,%3}, {%4,%5,%6,%7}, {%8,%9}, {%0,%1,%2,%3};\n"
        : "+f"(d[0]), "+f"(d[1]), "+f"(d[2]), "+f"(d[3])
        : "r"(a[0]), "r"(a[1]), "r"(a[2]), "r"(a[3]), "r"(b[0]), "r"(b[1]));
}

// ---------------------------------------------------------------------------
// prep: split+pack weights into bf16 planes + BN folds
// ---------------------------------------------------------------------------
__global__ __launch_bounds__(NTHREADS) void prep_kernel(
    const float* __restrict__ W2, const float* __restrict__ W3,
    const float* __restrict__ W4, const float* __restrict__ Wa,
    const float* __restrict__ b2, const float* __restrict__ g2, const float* __restrict__ be2,
    const float* __restrict__ m2, const float* __restrict__ v2,
    const float* __restrict__ b3, const float* __restrict__ g3, const float* __restrict__ be3,
    const float* __restrict__ m3, const float* __restrict__ v3,
    const float* __restrict__ b4, const float* __restrict__ g4, const float* __restrict__ be4,
    const float* __restrict__ m4, const float* __restrict__ v4)
{
    int i = blockIdx.x * NTHREADS + threadIdx.x;
    if (i < 36864) {                                   // w2: [288kp][128n]
        int kp = i >> 7, n = i & 127;
        packpair(W2[n * 576 + 2 * kp], W2[n * 576 + 2 * kp + 1], g_w2h[i], g_w2l[i]);
    }
    int i3 = i - 36864;
    if (i3 >= 0 && i3 < 147456) {                      // w3: [576kp][256n]
        int kp = i3 >> 8, n = i3 & 255;
        packpair(W3[n * 1152 + 2 * kp], W3[n * 1152 + 2 * kp + 1], g_w3h[i3], g_w3l[i3]);
    }
    int i4 = i - 36864 - 147456;
    if (i4 >= 0 && i4 < 294912) {                      // w4: [1152kp][256n]
        int kp = i4 >> 8, n = i4 & 255;
        packpair(W4[n * 2304 + 2 * kp], W4[n * 2304 + 2 * kp + 1], g_w4h[i4], g_w4l[i4]);
    }
    int ia = i - 36864 - 147456 - 294912;
    if (ia >= 0 && ia < 2520000) {                     // wa: [25z][168kp][600j]
        int z = ia / 100800, r = ia % 100800;
        int kp = r / 600, j = r % 600;
        const float* w = Wa + ((size_t)z * 336 + 2 * kp) * 600 + j;
        packpair(w[0], w[600], g_wah[ia], g_wal[ia]);
    }
    int ib = i - 36864 - 147456 - 294912 - 2520000;
    if (ib >= 0 && ib < 128) {
        float s = g2[ib] * rsqrtf(v2[ib] + 1e-5f);
        g_sc2[ib] = s; g_sh2[ib] = (b2[ib] - m2[ib]) * s + be2[ib];
    } else if (ib >= 128 && ib < 384) {
        int c = ib - 128;
        float s = g3[c] * rsqrtf(v3[c] + 1e-5f);
        g_sc3[c] = s; g_sh3[c] = (b3[c] - m3[c]) * s + be3[c];
    } else if (ib >= 384 && ib < 640) {
        int c = ib - 384;
        float s = g4[c] * rsqrtf(v4[c] + 1e-5f);
        g_sc4[c] = s; g_sh4[c] = (b4[c] - m4[c]) * s + be4[c];
    }
}

// ---------------------------------------------------------------------------
// conv1: 3 -> 64, 20x20, fused BN+ReLU, float out. One block per image.
// ---------------------------------------------------------------------------
__global__ __launch_bounds__(NTHREADS) void conv1_kernel(
    const float* __restrict__ x, const float* __restrict__ W,
    const float* __restrict__ bias, const float* __restrict__ gam,
    const float* __restrict__ bet, const float* __restrict__ mu,
    const float* __restrict__ var, float* __restrict__ out)
{
    __shared__ float sIn[3 * 22 * 22];
    __shared__ float sW[64 * 27];
    __shared__ float sScale[64], sShift[64];
    int b = blockIdx.x, tid = threadIdx.x;

    for (int i = tid; i < 3 * 22 * 22; i += NTHREADS) sIn[i] = 0.f;
    __syncthreads();
    const float* xb = x + (size_t)b * 1200;
    for (int i = tid; i < 1200; i += NTHREADS) {
        int ci = i / 400, p = i % 400, y = p / 20, xx = p % 20;
        sIn[ci * 484 + (y + 1) * 22 + (xx + 1)] = xb[i];
    }
    for (int i = tid; i < 1728; i += NTHREADS) sW[i] = W[i];
    if (tid < 64) {
        float sc = gam[tid] * rsqrtf(var[tid] + 1e-5f);
        sScale[tid] = sc;
        sShift[tid] = (bias[tid] - mu[tid]) * sc + bet[tid];
    }
    __syncthreads();

    int co = tid & 63, q = tid >> 6;
    float scale = sScale[co], shift = sShift[co];
    float* ob = out + ((size_t)b * 64 + co) * 400;
    for (int r = 0; r < 5; r++) {
        int y = q * 5 + r;
        float acc[20];
        #pragma unroll
        for (int xx = 0; xx < 20; xx++) acc[xx] = 0.f;
        #pragma unroll
        for (int ci = 0; ci < 3; ci++) {
            float w[9];
            #pragma unroll
            for (int k = 0; k < 9; k++) w[k] = sW[co * 27 + ci * 9 + k];
            const float* base = sIn + ci * 484 + y * 22;
            #pragma unroll
            for (int dy = 0; dy < 3; dy++) {
                const float* row = base + dy * 22;
                #pragma unroll
                for (int xx = 0; xx < 20; xx++)
                    acc[xx] += row[xx] * w[dy * 3] + row[xx + 1] * w[dy * 3 + 1]
                             + row[xx + 2] * w[dy * 3 + 2];
            }
        }
        #pragma unroll
        for (int xx = 0; xx < 20; xx++)
            ob[y * 20 + xx] = fmaxf(acc[xx] * scale + shift, 0.f);
    }
}

// ---------------------------------------------------------------------------
// maxpool 3x3 s2 p1, float in -> element-split32 out
// ---------------------------------------------------------------------------
__global__ __launch_bounds__(NTHREADS) void pool_split_kernel(
    const float* __restrict__ in, uint32_t* __restrict__ out,
    int C, int H, int OH, long long total)
{
    long long idx = (long long)blockIdx.x * NTHREADS + threadIdx.x;
    if (idx >= total) return;
    int W = H, OW = OH;
    int ox = (int)(idx % OW); long long t = idx / OW;
    int oy = (int)(t % OH);  t /= OH;
    int c  = (int)(t % C);   int b = (int)(t / C);
    const float* p = in + ((size_t)b * C + c) * H * W;
    float m = -3.402823466e38f;
    #pragma unroll
    for (int dy = 0; dy < 3; dy++) {
        int iy = 2 * oy - 1 + dy;
        if (iy < 0 || iy >= H) continue;
        #pragma unroll
        for (int dx = 0; dx < 3; dx++) {
            int ix = 2 * ox - 1 + dx;
            if (ix < 0 || ix >= W) continue;
            m = fmaxf(m, p[iy * W + ix]);
        }
    }
    out[idx] = split32(m);
}

// ---------------------------------------------------------------------------
// bf16 tensor-core GEMM, 3-product (Ah·Bh + Al·Bh + Ah·Bl) scheme.
// Tile 128x128x16, 8 warps (4x2), m16n8k16. All operands pre-split:
//  CC>0 : A = element-split32 activations, implicit im2col
//  CC==0: A/A2 = pair-packed h/l planes (MLP), aw = words per row
//  Bh/Bl: pair-packed weight planes [K/2][ldb]
// EPI: 0 float [b][128][100]; 1 split32 [b][256][25];
//      2 pair-packed feats h/l [n][b][128w]; 3 float tanh H[z][8192][600]
// ---------------------------------------------------------------------------
#define GEMM_FETCH(kc_)                                                          \
    {                                                                            \
        int kc__ = (kc_);                                                        \
        if (CC == 0) {                                                           \
            uint4 h4 = *(const uint4*)(Abh + (size_t)(mBase + lm) * aw           \
                                       + (kc__ >> 1) + (lkq >> 1));              \
            uint4 l4 = *(const uint4*)(Abl + (size_t)(mBase + lm) * aw           \
                                       + (kc__ >> 1) + (lkq >> 1));              \
            avh[0] = h4.x; avh[1] = h4.y; avh[2] = h4.z; avh[3] = h4.w;          \
            avl[0] = l4.x; avl[1] = l4.y; avl[2] = l4.z; avl[3] = l4.w;          \
        } else {                                                                 \
            uint32_t e[8];                                                       \
            _Pragma("unroll")                                                    \
            for (int j = 0; j < 8; j++) {                                        \
                int k = kc__ + lkq + j;                                          \
                int ci = k / 9, q = k - ci * 9;                                  \
                int iy = py - 1 + q / 3, ix = px - 1 + q % 3;                    \
                uint32_t v = 0u;                                                 \
                if (iy >= 0 && iy < S && ix >= 0 && ix < S)                      \
                    v = A[ib_off + ci * S * S + iy * S + ix];                    \
                e[j] = v;                                                        \
            }                                                                    \
            _Pragma("unroll")                                                    \
            for (int tt = 0; tt < 4; tt++) {                                     \
                avh[tt] = __byte_perm(e[2 * tt], e[2 * tt + 1], 0x7632);         \
                avl[tt] = __byte_perm(e[2 * tt], e[2 * tt + 1], 0x5410);         \
            }                                                                    \
        }                                                                        \
        _Pragma("unroll")                                                        \
        for (int jj = 0; jj < 4; jj++) {                                         \
            int kp = (kc__ >> 1) + (lkq >> 1) + jj;                              \
            bvh[jj] = (gn < N) ? Bbh[(size_t)kp * ldb + gn] : 0u;                \
            bvl[jj] = (gn < N) ? Bbl[(size_t)kp * ldb + gn] : 0u;                \
        }                                                                        \
    }

template <int EPI, int CC, int S>
__global__ __launch_bounds__(NTHREADS, 2) void gemm_bf16(
    const uint32_t* __restrict__ A, const uint32_t* __restrict__ A2,
    const uint32_t* __restrict__ Bh, const uint32_t* __restrict__ Bl,
    void* __restrict__ Cv, void* __restrict__ C2v,
    const float* __restrict__ sc, const float* __restrict__ sh,
    const float* __restrict__ bias,
    int K, int N, int ldb, int aw, int bStrideZ, int kpOff)
{
    __shared__ uint32_t sAh[128 * 12], sAl[128 * 12];
    __shared__ uint32_t sBh[128 * 12], sBl[128 * 12];

    int z = blockIdx.z;
    const uint32_t* Abh = A;
    const uint32_t* Abl = A2;
    const uint32_t* Bbh = Bh + (size_t)kpOff * ldb;
    const uint32_t* Bbl = Bl + (size_t)kpOff * ldb;
    if (EPI == 3) {
        Abh += (size_t)z * 8192 * aw;
        Abl += (size_t)z * 8192 * aw;
        Bbh += (size_t)z * bStrideZ;
        Bbl += (size_t)z * bStrideZ;
    }
    int mBase = blockIdx.y * 128, nBase = blockIdx.x * 128;
    int t = threadIdx.x, lane = t & 31, wid = t >> 5;
    int wm = (wid & 3) * 32, wn = (wid >> 2) * 64;
    int lc = lane & 3, lr = lane >> 2;

    int lm = t & 127, lkq = (t >> 7) * 8;
    int gn = nBase + lm;

    int ib_off = 0, py = 0, px = 0;
    if (CC > 0) {
        const int SS = S * S;
        int r = mBase + lm;
        int b = r / SS, p = r - b * SS;
        py = p / S; px = p - py * S;
        ib_off = b * CC * SS;
    }

    float acc[2][8][4];
    #pragma unroll
    for (int mt = 0; mt < 2; mt++)
        #pragma unroll
        for (int nt = 0; nt < 8; nt++)
            #pragma unroll
            for (int e = 0; e < 4; e++) acc[mt][nt][e] = 0.f;

    uint32_t avh[4], avl[4], bvh[4], bvl[4];
    GEMM_FETCH(0);

    int nch = K / 16;
    for (int ch = 0; ch < nch; ch++) {
        *(uint4*)&sAh[lm * 12 + (lkq >> 1)] = make_uint4(avh[0], avh[1], avh[2], avh[3]);
        *(uint4*)&sAl[lm * 12 + (lkq >> 1)] = make_uint4(avl[0], avl[1], avl[2], avl[3]);
        *(uint4*)&sBh[lm * 12 + (lkq >> 1)] = make_uint4(bvh[0], bvh[1], bvh[2], bvh[3]);
        *(uint4*)&sBl[lm * 12 + (lkq >> 1)] = make_uint4(bvl[0], bvl[1], bvl[2], bvl[3]);
        __syncthreads();

        int kcn = (ch + 1 < nch) ? (ch + 1) * 16 : 0;
        GEMM_FETCH(kcn);

        uint32_t fah[2][4], fal[2][4];
        #pragma unroll
        for (int mt = 0; mt < 2; mt++) {
            int mr = wm + mt * 16 + lr;
            fah[mt][0] = sAh[mr * 12 + lc];
            fah[mt][1] = sAh[(mr + 8) * 12 + lc];
            fah[mt][2] = sAh[mr * 12 + lc + 4];
            fah[mt][3] = sAh[(mr + 8) * 12 + lc + 4];
            fal[mt][0] = sAl[mr * 12 + lc];
            fal[mt][1] = sAl[(mr + 8) * 12 + lc];
            fal[mt][2] = sAl[mr * 12 + lc + 4];
            fal[mt][3] = sAl[(mr + 8) * 12 + lc + 4];
        }
        #pragma unroll
        for (int nt = 0; nt < 8; nt++) {
            int nc = wn + nt * 8 + lr;
            uint32_t bhf[2] = { sBh[nc * 12 + lc], sBh[nc * 12 + lc + 4] };
            uint32_t blf[2] = { sBl[nc * 12 + lc], sBl[nc * 12 + lc + 4] };
            #pragma unroll
            for (int mt = 0; mt < 2; mt++) {
                mma16(acc[mt][nt], fah[mt], bhf);
                mma16(acc[mt][nt], fal[mt], bhf);
                mma16(acc[mt][nt], fah[mt], blf);
            }
        }
        __syncthreads();
    }

    // epilogue
    #pragma unroll
    for (int mt = 0; mt < 2; mt++) {
        #pragma unroll
        for (int nt = 0; nt < 8; nt++) {
            if (EPI == 2) {
                #pragma unroll
                for (int rr = 0; rr < 2; rr++) {
                    int row = mBase + wm + mt * 16 + lr + rr * 8;
                    int col = nBase + wn + nt * 8 + 2 * lc;
                    float v0 = acc[mt][nt][rr * 2 + 0];
                    float v1 = acc[mt][nt][rr * 2 + 1];
                    v0 = fmaxf(v0 * sc[col] + sh[col], 0.f);
                    v1 = fmaxf(v1 * sc[col + 1] + sh[col + 1], 0.f);
                    int b = row / 25, p = row - b * 25;
                    uint32_t wh, wl;
                    packpair(v0, v1, wh, wl);
                    size_t o = ((size_t)p * 8192 + b) * 128 + (col >> 1);
                    ((uint32_t*)Cv)[o]  = wh;
                    ((uint32_t*)C2v)[o] = wl;
                }
            } else {
                #pragma unroll
                for (int e = 0; e < 4; e++) {
                    int row = mBase + wm + mt * 16 + lr + (e >> 1) * 8;
                    int col = nBase + wn + nt * 8 + 2 * lc + (e & 1);
                    float v = acc[mt][nt][e];
                    if (EPI == 0) {
                        int b = row / 100, p = row - b * 100;
                        ((float*)Cv)[((size_t)b * 128 + col) * 100 + p] =
                            fmaxf(v * sc[col] + sh[col], 0.f);
                    } else if (EPI == 1) {
                        int b = row / 25, p = row - b * 25;
                        ((uint32_t*)Cv)[((size_t)b * 256 + col) * 25 + p] =
                            split32(fmaxf(v * sc[col] + sh[col], 0.f));
                    } else {
                        if (col < N)
                            ((float*)Cv)[((size_t)z * 8192 + row) * 600 + col] =
                                tanhf(v + bias[(size_t)z * 600 + col]);
                    }
                }
            }
        }
    }
}

// ---------------------------------------------------------------------------
// GEMM2 + softmax (600 -> 10), warp per row, Wb in smem (pad 11)
// ---------------------------------------------------------------------------
__global__ __launch_bounds__(NTHREADS) void gemm2_softmax_kernel(
    const float* __restrict__ H, const float* __restrict__ Wb,
    const float* __restrict__ bb, float* __restrict__ out)
{
    __shared__ float sW[600 * 11];
    __shared__ float sb[10];
    int n = blockIdx.y, tid = threadIdx.x;
    const float* Wn = Wb + (size_t)n * 6000;
    for (int i = tid; i < 6000; i += NTHREADS) {
        int k = i / 10, c = i % 10;
        sW[k * 11 + c] = Wn[i];
    }
    if (tid < 10) sb[tid] = bb[n * 10 + tid];
    __syncthreads();

    int warp = tid >> 5, lane = tid & 31;
    int b = blockIdx.x * 8 + warp;
    const float* hr = H + ((size_t)n * 8192 + b) * 600;
    float acc[10];
    #pragma unroll
    for (int c = 0; c < 10; c++) acc[c] = 0.f;
    for (int k = lane; k < 600; k += 32) {
        float v = hr[k];
        #pragma unroll
        for (int c = 0; c < 10; c++) acc[c] += v * sW[k * 11 + c];
    }
    #pragma unroll
    for (int c = 0; c < 10; c++) {
        #pragma unroll
        for (int off = 16; off > 0; off >>= 1)
            acc[c] += __shfl_down_sync(0xffffffffu, acc[c], off);
    }
    if (lane == 0) {
        float l[10], mx = -3.402823466e38f;
        #pragma unroll
        for (int c = 0; c < 10; c++) { l[c] = acc[c] + sb[c]; mx = fmaxf(mx, l[c]); }
        float s = 0.f;
        #pragma unroll
        for (int c = 0; c < 10; c++) { l[c] = expf(l[c] - mx); s += l[c]; }
        float inv = 1.f / s;
        float* o = out + ((size_t)n * 8192 + b) * 10;
        #pragma unroll
        for (int c = 0; c < 10; c++) o[c] = l[c] * inv;
    }
}

// ---------------------------------------------------------------------------
// neighbor gather -> pair-packed in2 planes
// ---------------------------------------------------------------------------
__device__ __forceinline__ int nei_of(int i, int slot)
{
    int nb[8];
    #pragma unroll
    for (int t = 0; t < 8; t++) nb[t] = -1;
    int cnt = 0;
    bool l = (i % 5 != 0), r = ((i + 1) % 5 != 0), u = (i >= 5), d = (i + 5 < 25);
    if (u)      nb[cnt++] = i - 5;
    if (l)      nb[cnt++] = i - 1;
    if (r)      nb[cnt++] = i + 1;
    if (d)      nb[cnt++] = i + 5;
    if (u && l) nb[cnt++] = i - 6;
    if (u && r) nb[cnt++] = i - 4;
    if (d && l) nb[cnt++] = i + 4;
    if (d && r) nb[cnt++] = i + 6;
    return nb[slot];
}

__global__ __launch_bounds__(NTHREADS) void gather_kernel(
    const float* __restrict__ preds,
    const uint32_t* __restrict__ fh, const uint32_t* __restrict__ fl,
    uint32_t* __restrict__ ih, uint32_t* __restrict__ il)
{
    long long idx = (long long)blockIdx.x * NTHREADS + threadIdx.x;
    if (idx >= 25LL * 8192 * 168) return;
    int j = (int)(idx % 168);
    long long t = idx / 168;
    int b = (int)(t % 8192);
    int n = (int)(t / 8192);
    uint32_t wh, wl;
    if (j >= 40) {
        size_t src = ((size_t)n * 8192 + b) * 128 + (j - 40);
        wh = fh[src]; wl = fl[src];
    } else {
        int c0 = (2 * j) % 10, s = (2 * j) / 10;
        int nei = nei_of(n, s);
        float p0 = 0.f, p1 = 0.f;
        if (nei >= 0) {
            const float* pp = preds + ((size_t)nei * 8192 + b) * 10 + c0;
            p0 = pp[0]; p1 = pp[1];
        }
        packpair(p0, p1, wh, wl);
    }
    ih[idx] = wh;
    il[idx] = wl;
}

__global__ __launch_bounds__(NTHREADS) void mean_kernel(
    const float* __restrict__ second, float* __restrict__ mean)
{
    int idx = blockIdx.x * NTHREADS + threadIdx.x;
    if (idx >= 81920) return;
    float s = 0.f;
    #pragma unroll
    for (int n = 0; n < 25; n++) s += second[(size_t)n * 81920 + idx];
    mean[idx] = s * 0.04f;
}

// ---------------------------------------------------------------------------
// launch
// ---------------------------------------------------------------------------
extern "C" void kernel_launch(void* const* d_in, const int* in_sizes, int n_in,
                              void* d_out, int out_size)
{
    (void)in_sizes; (void)n_in; (void)out_size;
    float* arena = nullptr;
    uint32_t *w2h, *w2l, *w3h, *w3l, *w4h, *w4l, *wah, *wal;
    float *sc2, *sh2, *sc3, *sh3, *sc4, *sh4;
    cudaGetSymbolAddress((void**)&arena, g_arena);
    cudaGetSymbolAddress((void**)&w2h, g_w2h);  cudaGetSymbolAddress((void**)&w2l, g_w2l);
    cudaGetSymbolAddress((void**)&w3h, g_w3h);  cudaGetSymbolAddress((void**)&w3l, g_w3l);
    cudaGetSymbolAddress((void**)&w4h, g_w4h);  cudaGetSymbolAddress((void**)&w4l, g_w4l);
    cudaGetSymbolAddress((void**)&wah, g_wah);  cudaGetSymbolAddress((void**)&wal, g_wal);
    cudaGetSymbolAddress((void**)&sc2, g_sc2);  cudaGetSymbolAddress((void**)&sh2, g_sh2);
    cudaGetSymbolAddress((void**)&sc3, g_sc3);  cudaGetSymbolAddress((void**)&sh3, g_sh3);
    cudaGetSymbolAddress((void**)&sc4, g_sc4);  cudaGetSymbolAddress((void**)&sh4, g_sh4);
    uint32_t* arenau = (uint32_t*)arena;

    const float* x   = (const float*)d_in[0];
    const float* W1  = (const float*)d_in[1];
    const float* b1  = (const float*)d_in[2];
    const float* g1  = (const float*)d_in[3];
    const float* be1 = (const float*)d_in[4];
    const float* m1  = (const float*)d_in[5];
    const float* v1  = (const float*)d_in[6];
    const float* W2  = (const float*)d_in[7];
    const float* b2  = (const float*)d_in[8];
    const float* g2  = (const float*)d_in[9];
    const float* be2 = (const float*)d_in[10];
    const float* m2  = (const float*)d_in[11];
    const float* v2  = (const float*)d_in[12];
    const float* W3  = (const float*)d_in[13];
    const float* b3  = (const float*)d_in[14];
    const float* g3  = (const float*)d_in[15];
    const float* be3 = (const float*)d_in[16];
    const float* m3  = (const float*)d_in[17];
    const float* v3  = (const float*)d_in[18];
    const float* W4  = (const float*)d_in[19];
    const float* b4  = (const float*)d_in[20];
    const float* g4  = (const float*)d_in[21];
    const float* be4 = (const float*)d_in[22];
    const float* m4  = (const float*)d_in[23];
    const float* v4  = (const float*)d_in[24];
    const float* Wa  = (const float*)d_in[25];
    const float* ba  = (const float*)d_in[26];
    const float* Wb  = (const float*)d_in[27];
    const float* bb  = (const float*)d_in[28];
    float* out = (float*)d_out;

    // prep: weight splits + BN folds
    prep_kernel<<<11719, NTHREADS>>>(W2, W3, W4, Wa,
        b2, g2, be2, m2, v2, b3, g3, be3, m3, v3, b4, g4, be4, m4, v4);

    // conv1 (float) + pool1 (split32)
    conv1_kernel<<<BATCH, NTHREADS>>>(x, W1, b1, g1, be1, m1, v1, arena + OFF_C1);
    {
        long long total = (long long)BATCH * 64 * 100;
        pool_split_kernel<<<(int)((total + NTHREADS - 1) / NTHREADS), NTHREADS>>>(
            arena + OFF_C1, arenau + OFF_P1, 64, 20, 10, total);
    }
    // conv2: implicit-im2col bf16 GEMM (K=576, N=128) -> float c2
    gemm_bf16<0, 64, 10><<<dim3(1, 6400, 1), NTHREADS>>>(
        arenau + OFF_P1, nullptr, w2h, w2l, arena + OFF_C2, nullptr,
        sc2, sh2, nullptr, 576, 128, 128, 0, 0, 0);
    // pool2 (split32)
    {
        long long total = (long long)BATCH * 128 * 25;
        pool_split_kernel<<<(int)((total + NTHREADS - 1) / NTHREADS), NTHREADS>>>(
            arena + OFF_C2, arenau + OFF_P2, 128, 10, 5, total);
    }
    // conv3 (K=1152, N=256) -> split32 c3
    gemm_bf16<1, 128, 5><<<dim3(2, 1600, 1), NTHREADS>>>(
        arenau + OFF_P2, nullptr, w3h, w3l, arenau + OFF_C3, nullptr,
        sc3, sh3, nullptr, 1152, 256, 256, 0, 0, 0);
    // conv4 (K=2304, N=256) -> pair-packed feats h/l
    gemm_bf16<2, 256, 5><<<dim3(2, 1600, 1), NTHREADS>>>(
        arenau + OFF_C3, nullptr, w4h, w4l,
        arenau + OFF_FEATS_H, arenau + OFF_FEATS_L,
        sc4, sh4, nullptr, 2304, 256, 256, 0, 0, 0);
    // stage 1 MLP (K=256, Wa rows 80:336 -> kpOff=40) -> float H
    gemm_bf16<3, 0, 0><<<dim3(5, 64, 25), NTHREADS>>>(
        arenau + OFF_FEATS_H, arenau + OFF_FEATS_L, wah, wal,
        arena + OFF_H, nullptr, nullptr, nullptr, ba,
        256, 600, 600, 128, 100800, 40);
    gemm2_softmax_kernel<<<dim3(1024, 25), NTHREADS>>>(arena + OFF_H, Wb, bb,
                                                       arena + OFF_PREDS);
    // gather -> pair-packed in2 h/l
    {
        long long total = 25LL * 8192 * 168;
        gather_kernel<<<(int)((total + NTHREADS - 1) / NTHREADS), NTHREADS>>>(
            arena + OFF_PREDS, arenau + OFF_FEATS_H, arenau + OFF_FEATS_L,
            arenau + OFF_IN2_H, arenau + OFF_IN2_L);
    }
    // stage 2 MLP (K=336)
    gemm_bf16<3, 0, 0><<<dim3(5, 64, 25), NTHREADS>>>(
        arenau + OFF_IN2_H, arenau + OFF_IN2_L, wah, wal,
        arena + OFF_H, nullptr, nullptr, nullptr, ba,
        336, 600, 600, 168, 100800, 0);
    gemm2_softmax_kernel<<<dim3(1024, 25), NTHREADS>>>(arena + OFF_H, Wb, bb,
                                                       out + 81920);
    mean_kernel<<<320, NTHREADS>>>(out + 81920, out);
}

// round 9
// speedup vs baseline: 1.2927x; 1.0195x over previous
#include <cuda_runtime.h>
#include <cstdint>
#include <cstddef>

#define NTHREADS 256
#define BATCH 8192

// ---------------------------------------------------------------------------
// Scratch arena (word offsets, 4B words; lifetimes verified):
//  c1    [0, 209715200)            float   conv1 out [b][64][20][20]
//  p1    [209715200, 262144000)    split32 pool1 out [b][64][10][10]
//  c2    [0, 104857600)            float   conv2 out [b][128][10][10]
//  p2    [104857600, 131072000)    split32 pool2 out
//  c3    [131072000, 183500800)    split32 conv3 out [b][256][5][5]
//  featsH[0, 26214400) featsL[26214400, 52428800)  pair-packed [25][8192][128w]
//  H     [52428800, 175308800)     float   [25][8192][600]
//  preds [183500800, 185548800)    float   [25][8192][10]
//  in2H  [185548800, 219955200) in2L [219955200, 254361600) [25][8192][168w]
// ---------------------------------------------------------------------------
__device__ float g_arena[262144000];     // 1.049 GB

static const size_t OFF_C1      = 0;
static const size_t OFF_P1      = 209715200;
static const size_t OFF_C2      = 0;
static const size_t OFF_P2      = 104857600;
static const size_t OFF_C3      = 131072000;
static const size_t OFF_FEATS_H = 0;
static const size_t OFF_FEATS_L = 26214400;
static const size_t OFF_H       = 52428800;
static const size_t OFF_PREDS   = 183500800;
static const size_t OFF_IN2_H   = 185548800;
static const size_t OFF_IN2_L   = 219955200;

// pre-split weight planes, pair-packed along k: word(kp,n) = bf16(k=2kp+1)<<16 | bf16(k=2kp)
__device__ uint32_t g_w2h[288 * 128],  g_w2l[288 * 128];
__device__ uint32_t g_w3h[576 * 256],  g_w3l[576 * 256];
__device__ uint32_t g_w4h[1152 * 256], g_w4l[1152 * 256];
__device__ uint32_t g_wah[25 * 168 * 600], g_wal[25 * 168 * 600];
__device__ float g_sc2[128], g_sh2[128];
__device__ float g_sc3[256], g_sh3[256];
__device__ float g_sc4[256], g_sh4[256];

// ---------------------------------------------------------------------------
// bf16 helpers
// ---------------------------------------------------------------------------
__device__ __forceinline__ uint32_t f2bf(float x)
{
    unsigned short h;
    asm("cvt.rn.bf16.f32 %0, %1;" : "=h"(h) : "f"(x));
    return (uint32_t)h;
}

// element-split32: hi bf16 in high halfword, lo bf16 in low halfword
__device__ __forceinline__ uint32_t split32(float x)
{
    uint32_t hb = f2bf(x);
    float r = x - __uint_as_float(hb << 16);
    uint32_t lb = f2bf(r);
    return (hb << 16) | lb;
}

// pair-pack two floats into (h-plane word, l-plane word)
__device__ __forceinline__ void packpair(float x0, float x1, uint32_t& wh, uint32_t& wl)
{
    uint32_t s0 = split32(x0), s1 = split32(x1);
    wh = __byte_perm(s0, s1, 0x7632);   // [s0.hi16, s1.hi16]
    wl = __byte_perm(s0, s1, 0x5410);   // [s0.lo16, s1.lo16]
}

__device__ __forceinline__ void mma16(float d[4], const uint32_t a[4], const uint32_t b[2])
{
    asm volatile(
        "mma.sync.aligned.m16n8k16.row.col.f32.bf16.bf16.f32 "
        "{%0,%1,%2,%3}, {%4,%5,%6,%7}, {%8,%9}, {%0,%1,%2,%3};\n"
        : "+f"(d[0]), "+f"(d[1]), "+f"(d[2]), "+f"(d[3])
        : "r"(a[0]), "r"(a[1]), "r"(a[2]), "r"(a[3]), "r"(b[0]), "r"(b[1]));
}

#define LDSM_X4(r0, r1, r2, r3, addr)                                            \
    asm volatile("ldmatrix.sync.aligned.m8n8.x4.shared.b16 {%0,%1,%2,%3}, [%4];" \
                 : "=r"(r0), "=r"(r1), "=r"(r2), "=r"(r3) : "r"(addr))

// ---------------------------------------------------------------------------
// prep: split+pack weights into bf16 planes + BN folds
// ---------------------------------------------------------------------------
__global__ __launch_bounds__(NTHREADS) void prep_kernel(
    const float* __restrict__ W2, const float* __restrict__ W3,
    const float* __restrict__ W4, const float* __restrict__ Wa,
    const float* __restrict__ b2, const float* __restrict__ g2, const float* __restrict__ be2,
    const float* __restrict__ m2, const float* __restrict__ v2,
    const float* __restrict__ b3, const float* __restrict__ g3, const float* __restrict__ be3,
    const float* __restrict__ m3, const float* __restrict__ v3,
    const float* __restrict__ b4, const float* __restrict__ g4, const float* __restrict__ be4,
    const float* __restrict__ m4, const float* __restrict__ v4)
{
    int i = blockIdx.x * NTHREADS + threadIdx.x;
    if (i < 36864) {                                   // w2: [288kp][128n]
        int kp = i >> 7, n = i & 127;
        packpair(W2[n * 576 + 2 * kp], W2[n * 576 + 2 * kp + 1], g_w2h[i], g_w2l[i]);
    }
    int i3 = i - 36864;
    if (i3 >= 0 && i3 < 147456) {                      // w3: [576kp][256n]
        int kp = i3 >> 8, n = i3 & 255;
        packpair(W3[n * 1152 + 2 * kp], W3[n * 1152 + 2 * kp + 1], g_w3h[i3], g_w3l[i3]);
    }
    int i4 = i - 36864 - 147456;
    if (i4 >= 0 && i4 < 294912) {                      // w4: [1152kp][256n]
        int kp = i4 >> 8, n = i4 & 255;
        packpair(W4[n * 2304 + 2 * kp], W4[n * 2304 + 2 * kp + 1], g_w4h[i4], g_w4l[i4]);
    }
    int ia = i - 36864 - 147456 - 294912;
    if (ia >= 0 && ia < 2520000) {                     // wa: [25z][168kp][600j]
        int z = ia / 100800, r = ia % 100800;
        int kp = r / 600, j = r % 600;
        const float* w = Wa + ((size_t)z * 336 + 2 * kp) * 600 + j;
        packpair(w[0], w[600], g_wah[ia], g_wal[ia]);
    }
    int ib = i - 36864 - 147456 - 294912 - 2520000;
    if (ib >= 0 && ib < 128) {
        float s = g2[ib] * rsqrtf(v2[ib] + 1e-5f);
        g_sc2[ib] = s; g_sh2[ib] = (b2[ib] - m2[ib]) * s + be2[ib];
    } else if (ib >= 128 && ib < 384) {
        int c = ib - 128;
        float s = g3[c] * rsqrtf(v3[c] + 1e-5f);
        g_sc3[c] = s; g_sh3[c] = (b3[c] - m3[c]) * s + be3[c];
    } else if (ib >= 384 && ib < 640) {
        int c = ib - 384;
        float s = g4[c] * rsqrtf(v4[c] + 1e-5f);
        g_sc4[c] = s; g_sh4[c] = (b4[c] - m4[c]) * s + be4[c];
    }
}

// ---------------------------------------------------------------------------
// conv1: 3 -> 64, 20x20, fused BN+ReLU, float out. One block per image.
// ---------------------------------------------------------------------------
__global__ __launch_bounds__(NTHREADS) void conv1_kernel(
    const float* __restrict__ x, const float* __restrict__ W,
    const float* __restrict__ bias, const float* __restrict__ gam,
    const float* __restrict__ bet, const float* __restrict__ mu,
    const float* __restrict__ var, float* __restrict__ out)
{
    __shared__ float sIn[3 * 22 * 22];
    __shared__ float sW[64 * 27];
    __shared__ float sScale[64], sShift[64];
    int b = blockIdx.x, tid = threadIdx.x;

    for (int i = tid; i < 3 * 22 * 22; i += NTHREADS) sIn[i] = 0.f;
    __syncthreads();
    const float* xb = x + (size_t)b * 1200;
    for (int i = tid; i < 1200; i += NTHREADS) {
        int ci = i / 400, p = i % 400, y = p / 20, xx = p % 20;
        sIn[ci * 484 + (y + 1) * 22 + (xx + 1)] = xb[i];
    }
    for (int i = tid; i < 1728; i += NTHREADS) sW[i] = W[i];
    if (tid < 64) {
        float sc = gam[tid] * rsqrtf(var[tid] + 1e-5f);
        sScale[tid] = sc;
        sShift[tid] = (bias[tid] - mu[tid]) * sc + bet[tid];
    }
    __syncthreads();

    int co = tid & 63, q = tid >> 6;
    float scale = sScale[co], shift = sShift[co];
    float* ob = out + ((size_t)b * 64 + co) * 400;
    for (int r = 0; r < 5; r++) {
        int y = q * 5 + r;
        float acc[20];
        #pragma unroll
        for (int xx = 0; xx < 20; xx++) acc[xx] = 0.f;
        #pragma unroll
        for (int ci = 0; ci < 3; ci++) {
            float w[9];
            #pragma unroll
            for (int k = 0; k < 9; k++) w[k] = sW[co * 27 + ci * 9 + k];
            const float* base = sIn + ci * 484 + y * 22;
            #pragma unroll
            for (int dy = 0; dy < 3; dy++) {
                const float* row = base + dy * 22;
                #pragma unroll
                for (int xx = 0; xx < 20; xx++)
                    acc[xx] += row[xx] * w[dy * 3] + row[xx + 1] * w[dy * 3 + 1]
                             + row[xx + 2] * w[dy * 3 + 2];
            }
        }
        #pragma unroll
        for (int xx = 0; xx < 20; xx++)
            ob[y * 20 + xx] = fmaxf(acc[xx] * scale + shift, 0.f);
    }
}

// ---------------------------------------------------------------------------
// maxpool 3x3 s2 p1, float in -> element-split32 out
// ---------------------------------------------------------------------------
__global__ __launch_bounds__(NTHREADS) void pool_split_kernel(
    const float* __restrict__ in, uint32_t* __restrict__ out,
    int C, int H, int OH, long long total)
{
    long long idx = (long long)blockIdx.x * NTHREADS + threadIdx.x;
    if (idx >= total) return;
    int W = H, OW = OH;
    int ox = (int)(idx % OW); long long t = idx / OW;
    int oy = (int)(t % OH);  t /= OH;
    int c  = (int)(t % C);   int b = (int)(t / C);
    const float* p = in + ((size_t)b * C + c) * H * W;
    float m = -3.402823466e38f;
    #pragma unroll
    for (int dy = 0; dy < 3; dy++) {
        int iy = 2 * oy - 1 + dy;
        if (iy < 0 || iy >= H) continue;
        #pragma unroll
        for (int dx = 0; dx < 3; dx++) {
            int ix = 2 * ox - 1 + dx;
            if (ix < 0 || ix >= W) continue;
            m = fmaxf(m, p[iy * W + ix]);
        }
    }
    out[idx] = split32(m);
}

// ---------------------------------------------------------------------------
// bf16 tensor-core GEMM, 3-product (Ah·Bh + Al·Bh + Ah·Bl) scheme.
// Tile 128x128x16, 8 warps (4x2), m16n8k16. Fragments loaded via
// ldmatrix.x4 (12 LDSM per chunk instead of 48 LDS.32).
// EPI: 0 float [b][128][100]; 1 split32 [b][256][25];
//      2 pair-packed feats h/l [n][b][128w]; 3 float tanh H[z][8192][600]
// ---------------------------------------------------------------------------
#define GEMM_FETCH(kc_)                                                          \
    {                                                                            \
        int kc__ = (kc_);                                                        \
        if (CC == 0) {                                                           \
            uint4 h4 = *(const uint4*)(Abh + (size_t)(mBase + lm) * aw           \
                                       + (kc__ >> 1) + (lkq >> 1));              \
            uint4 l4 = *(const uint4*)(Abl + (size_t)(mBase + lm) * aw           \
                                       + (kc__ >> 1) + (lkq >> 1));              \
            avh[0] = h4.x; avh[1] = h4.y; avh[2] = h4.z; avh[3] = h4.w;          \
            avl[0] = l4.x; avl[1] = l4.y; avl[2] = l4.z; avl[3] = l4.w;          \
        } else {                                                                 \
            uint32_t e[8];                                                       \
            _Pragma("unroll")                                                    \
            for (int j = 0; j < 8; j++) {                                        \
                int k = kc__ + lkq + j;                                          \
                int ci = k / 9, q = k - ci * 9;                                  \
                int iy = py - 1 + q / 3, ix = px - 1 + q % 3;                    \
                uint32_t v = 0u;                                                 \
                if (iy >= 0 && iy < S && ix >= 0 && ix < S)                      \
                    v = A[ib_off + ci * S * S + iy * S + ix];                    \
                e[j] = v;                                                        \
            }                                                                    \
            _Pragma("unroll")                                                    \
            for (int tt = 0; tt < 4; tt++) {                                     \
                avh[tt] = __byte_perm(e[2 * tt], e[2 * tt + 1], 0x7632);         \
                avl[tt] = __byte_perm(e[2 * tt], e[2 * tt + 1], 0x5410);         \
            }                                                                    \
        }                                                                        \
        _Pragma("unroll")                                                        \
        for (int jj = 0; jj < 4; jj++) {                                         \
            int kp = (kc__ >> 1) + (lkq >> 1) + jj;                              \
            bvh[jj] = (gn < N) ? Bbh[(size_t)kp * ldb + gn] : 0u;                \
            bvl[jj] = (gn < N) ? Bbl[(size_t)kp * ldb + gn] : 0u;                \
        }                                                                        \
    }

template <int EPI, int CC, int S>
__global__ __launch_bounds__(NTHREADS, 2) void gemm_bf16(
    const uint32_t* __restrict__ A, const uint32_t* __restrict__ A2,
    const uint32_t* __restrict__ Bh, const uint32_t* __restrict__ Bl,
    void* __restrict__ Cv, void* __restrict__ C2v,
    const float* __restrict__ sc, const float* __restrict__ sh,
    const float* __restrict__ bias,
    int K, int N, int ldb, int aw, int bStrideZ, int kpOff)
{
    __shared__ uint32_t sAh[128 * 12], sAl[128 * 12];
    __shared__ uint32_t sBh[128 * 12], sBl[128 * 12];

    int z = blockIdx.z;
    const uint32_t* Abh = A;
    const uint32_t* Abl = A2;
    const uint32_t* Bbh = Bh + (size_t)kpOff * ldb;
    const uint32_t* Bbl = Bl + (size_t)kpOff * ldb;
    if (EPI == 3) {
        Abh += (size_t)z * 8192 * aw;
        Abl += (size_t)z * 8192 * aw;
        Bbh += (size_t)z * bStrideZ;
        Bbl += (size_t)z * bStrideZ;
    }
    int mBase = blockIdx.y * 128, nBase = blockIdx.x * 128;
    int t = threadIdx.x, lane = t & 31, wid = t >> 5;
    int wm = (wid & 3) * 32, wn = (wid >> 2) * 64;
    int lc = lane & 3, lr = lane >> 2;
    (void)lc; (void)lr;

    int lm = t & 127, lkq = (t >> 7) * 8;
    int gn = nBase + lm;

    int ib_off = 0, py = 0, px = 0;
    if (CC > 0) {
        const int SS = S * S;
        int r = mBase + lm;
        int b = r / SS, p = r - b * SS;
        py = p / S; px = p - py * S;
        ib_off = b * CC * SS;
    }

    // ldmatrix per-lane source addresses (invariant across chunks)
    // A tiles: t = lane>>3: T0(m0-7,kp0-3) T1(m8-15,kp0-3) T2(m0-7,kp4-7) T3(m8-15,kp4-7)
    // B tiles: T0(n0-7,kp0-3) T1(n0-7,kp4-7) T2(n8-15,kp0-3) T3(n8-15,kp4-7)
    uint32_t sAh_u = (uint32_t)__cvta_generic_to_shared(sAh);
    uint32_t sAl_u = (uint32_t)__cvta_generic_to_shared(sAl);
    uint32_t sBh_u = (uint32_t)__cvta_generic_to_shared(sBh);
    uint32_t sBl_u = (uint32_t)__cvta_generic_to_shared(sBl);
    int lt = lane >> 3, lrow = lane & 7;
    uint32_t aOff = (uint32_t)(((wm + ((lt & 1) << 3) + lrow) * 12 + ((lt >> 1) << 2)) * 4);
    uint32_t bOff = (uint32_t)(((wn + ((lt >> 1) << 3) + lrow) * 12 + ((lt & 1) << 2)) * 4);
    uint32_t adrAh = sAh_u + aOff, adrAl = sAl_u + aOff;
    uint32_t adrBh = sBh_u + bOff, adrBl = sBl_u + bOff;

    float acc[2][8][4];
    #pragma unroll
    for (int mt = 0; mt < 2; mt++)
        #pragma unroll
        for (int nt = 0; nt < 8; nt++)
            #pragma unroll
            for (int e = 0; e < 4; e++) acc[mt][nt][e] = 0.f;

    uint32_t avh[4], avl[4], bvh[4], bvl[4];
    GEMM_FETCH(0);

    int nch = K / 16;
    for (int ch = 0; ch < nch; ch++) {
        *(uint4*)&sAh[lm * 12 + (lkq >> 1)] = make_uint4(avh[0], avh[1], avh[2], avh[3]);
        *(uint4*)&sAl[lm * 12 + (lkq >> 1)] = make_uint4(avl[0], avl[1], avl[2], avl[3]);
        *(uint4*)&sBh[lm * 12 + (lkq >> 1)] = make_uint4(bvh[0], bvh[1], bvh[2], bvh[3]);
        *(uint4*)&sBl[lm * 12 + (lkq >> 1)] = make_uint4(bvl[0], bvl[1], bvl[2], bvl[3]);
        __syncthreads();

        int kcn = (ch + 1 < nch) ? (ch + 1) * 16 : 0;
        GEMM_FETCH(kcn);

        // A fragments via ldmatrix (mt stride = 16 rows * 48B = 768B)
        uint32_t fah[2][4], fal[2][4];
        LDSM_X4(fah[0][0], fah[0][1], fah[0][2], fah[0][3], adrAh);
        LDSM_X4(fah[1][0], fah[1][1], fah[1][2], fah[1][3], adrAh + 768u);
        LDSM_X4(fal[0][0], fal[0][1], fal[0][2], fal[0][3], adrAl);
        LDSM_X4(fal[1][0], fal[1][1], fal[1][2], fal[1][3], adrAl + 768u);

        // B fragments in 2 batches of 4 n-tiles (batch stride 32 cols = 1536B,
        // sub stride 16 cols = 768B)
        #pragma unroll
        for (int bt = 0; bt < 2; bt++) {
            uint32_t bh[8], bl[8];
            LDSM_X4(bh[0], bh[1], bh[2], bh[3], adrBh + bt * 1536u);
            LDSM_X4(bh[4], bh[5], bh[6], bh[7], adrBh + bt * 1536u + 768u);
            LDSM_X4(bl[0], bl[1], bl[2], bl[3], adrBl + bt * 1536u);
            LDSM_X4(bl[4], bl[5], bl[6], bl[7], adrBl + bt * 1536u + 768u);
            #pragma unroll
            for (int n4 = 0; n4 < 4; n4++) {
                int nt = bt * 4 + n4;
                uint32_t bhf[2] = { bh[n4 * 2], bh[n4 * 2 + 1] };
                uint32_t blf[2] = { bl[n4 * 2], bl[n4 * 2 + 1] };
                #pragma unroll
                for (int mt = 0; mt < 2; mt++) {
                    mma16(acc[mt][nt], fah[mt], bhf);
                    mma16(acc[mt][nt], fal[mt], bhf);
                    mma16(acc[mt][nt], fah[mt], blf);
                }
            }
        }
        __syncthreads();
    }

    // epilogue
    int elc = lane & 3, elr = lane >> 2;
    #pragma unroll
    for (int mt = 0; mt < 2; mt++) {
        #pragma unroll
        for (int nt = 0; nt < 8; nt++) {
            if (EPI == 2) {
                #pragma unroll
                for (int rr = 0; rr < 2; rr++) {
                    int row = mBase + wm + mt * 16 + elr + rr * 8;
                    int col = nBase + wn + nt * 8 + 2 * elc;
                    float v0 = acc[mt][nt][rr * 2 + 0];
                    float v1 = acc[mt][nt][rr * 2 + 1];
                    v0 = fmaxf(v0 * sc[col] + sh[col], 0.f);
                    v1 = fmaxf(v1 * sc[col + 1] + sh[col + 1], 0.f);
                    int b = row / 25, p = row - b * 25;
                    uint32_t wh, wl;
                    packpair(v0, v1, wh, wl);
                    size_t o = ((size_t)p * 8192 + b) * 128 + (col >> 1);
                    ((uint32_t*)Cv)[o]  = wh;
                    ((uint32_t*)C2v)[o] = wl;
                }
            } else {
                #pragma unroll
                for (int e = 0; e < 4; e++) {
                    int row = mBase + wm + mt * 16 + elr + (e >> 1) * 8;
                    int col = nBase + wn + nt * 8 + 2 * elc + (e & 1);
                    float v = acc[mt][nt][e];
                    if (EPI == 0) {
                        int b = row / 100, p = row - b * 100;
                        ((float*)Cv)[((size_t)b * 128 + col) * 100 + p] =
                            fmaxf(v * sc[col] + sh[col], 0.f);
                    } else if (EPI == 1) {
                        int b = row / 25, p = row - b * 25;
                        ((uint32_t*)Cv)[((size_t)b * 256 + col) * 25 + p] =
                            split32(fmaxf(v * sc[col] + sh[col], 0.f));
                    } else {
                        if (col < N)
                            ((float*)Cv)[((size_t)z * 8192 + row) * 600 + col] =
                                tanhf(v + bias[(size_t)z * 600 + col]);
                    }
                }
            }
        }
    }
}

// ---------------------------------------------------------------------------
// GEMM2 + softmax (600 -> 10), warp per row, Wb in smem (pad 11)
// ---------------------------------------------------------------------------
__global__ __launch_bounds__(NTHREADS) void gemm2_softmax_kernel(
    const float* __restrict__ H, const float* __restrict__ Wb,
    const float* __restrict__ bb, float* __restrict__ out)
{
    __shared__ float sW[600 * 11];
    __shared__ float sb[10];
    int n = blockIdx.y, tid = threadIdx.x;
    const float* Wn = Wb + (size_t)n * 6000;
    for (int i = tid; i < 6000; i += NTHREADS) {
        int k = i / 10, c = i % 10;
        sW[k * 11 + c] = Wn[i];
    }
    if (tid < 10) sb[tid] = bb[n * 10 + tid];
    __syncthreads();

    int warp = tid >> 5, lane = tid & 31;
    int b = blockIdx.x * 8 + warp;
    const float* hr = H + ((size_t)n * 8192 + b) * 600;
    float acc[10];
    #pragma unroll
    for (int c = 0; c < 10; c++) acc[c] = 0.f;
    for (int k = lane; k < 600; k += 32) {
        float v = hr[k];
        #pragma unroll
        for (int c = 0; c < 10; c++) acc[c] += v * sW[k * 11 + c];
    }
    #pragma unroll
    for (int c = 0; c < 10; c++) {
        #pragma unroll
        for (int off = 16; off > 0; off >>= 1)
            acc[c] += __shfl_down_sync(0xffffffffu, acc[c], off);
    }
    if (lane == 0) {
        float l[10], mx = -3.402823466e38f;
        #pragma unroll
        for (int c = 0; c < 10; c++) { l[c] = acc[c] + sb[c]; mx = fmaxf(mx, l[c]); }
        float s = 0.f;
        #pragma unroll
        for (int c = 0; c < 10; c++) { l[c] = expf(l[c] - mx); s += l[c]; }
        float inv = 1.f / s;
        float* o = out + ((size_t)n * 8192 + b) * 10;
        #pragma unroll
        for (int c = 0; c < 10; c++) o[c] = l[c] * inv;
    }
}

// ---------------------------------------------------------------------------
// neighbor gather -> pair-packed in2 planes
// ---------------------------------------------------------------------------
__device__ __forceinline__ int nei_of(int i, int slot)
{
    int nb[8];
    #pragma unroll
    for (int t = 0; t < 8; t++) nb[t] = -1;
    int cnt = 0;
    bool l = (i % 5 != 0), r = ((i + 1) % 5 != 0), u = (i >= 5), d = (i + 5 < 25);
    if (u)      nb[cnt++] = i - 5;
    if (l)      nb[cnt++] = i - 1;
    if (r)      nb[cnt++] = i + 1;
    if (d)      nb[cnt++] = i + 5;
    if (u && l) nb[cnt++] = i - 6;
    if (u && r) nb[cnt++] = i - 4;
    if (d && l) nb[cnt++] = i + 4;
    if (d && r) nb[cnt++] = i + 6;
    return nb[slot];
}

__global__ __launch_bounds__(NTHREADS) void gather_kernel(
    const float* __restrict__ preds,
    const uint32_t* __restrict__ fh, const uint32_t* __restrict__ fl,
    uint32_t* __restrict__ ih, uint32_t* __restrict__ il)
{
    long long idx = (long long)blockIdx.x * NTHREADS + threadIdx.x;
    if (idx >= 25LL * 8192 * 168) return;
    int j = (int)(idx % 168);
    long long t = idx / 168;
    int b = (int)(t % 8192);
    int n = (int)(t / 8192);
    uint32_t wh, wl;
    if (j >= 40) {
        size_t src = ((size_t)n * 8192 + b) * 128 + (j - 40);
        wh = fh[src]; wl = fl[src];
    } else {
        int c0 = (2 * j) % 10, s = (2 * j) / 10;
        int nei = nei_of(n, s);
        float p0 = 0.f, p1 = 0.f;
        if (nei >= 0) {
            const float* pp = preds + ((size_t)nei * 8192 + b) * 10 + c0;
            p0 = pp[0]; p1 = pp[1];
        }
        packpair(p0, p1, wh, wl);
    }
    ih[idx] = wh;
    il[idx] = wl;
}

__global__ __launch_bounds__(NTHREADS) void mean_kernel(
    const float* __restrict__ second, float* __restrict__ mean)
{
    int idx = blockIdx.x * NTHREADS + threadIdx.x;
    if (idx >= 81920) return;
    float s = 0.f;
    #pragma unroll
    for (int n = 0; n < 25; n++) s += second[(size_t)n * 81920 + idx];
    mean[idx] = s * 0.04f;
}

// ---------------------------------------------------------------------------
// launch
// ---------------------------------------------------------------------------
extern "C" void kernel_launch(void* const* d_in, const int* in_sizes, int n_in,
                              void* d_out, int out_size)
{
    (void)in_sizes; (void)n_in; (void)out_size;
    float* arena = nullptr;
    uint32_t *w2h, *w2l, *w3h, *w3l, *w4h, *w4l, *wah, *wal;
    float *sc2, *sh2, *sc3, *sh3, *sc4, *sh4;
    cudaGetSymbolAddress((void**)&arena, g_arena);
    cudaGetSymbolAddress((void**)&w2h, g_w2h);  cudaGetSymbolAddress((void**)&w2l, g_w2l);
    cudaGetSymbolAddress((void**)&w3h, g_w3h);  cudaGetSymbolAddress((void**)&w3l, g_w3l);
    cudaGetSymbolAddress((void**)&w4h, g_w4h);  cudaGetSymbolAddress((void**)&w4l, g_w4l);
    cudaGetSymbolAddress((void**)&wah, g_wah);  cudaGetSymbolAddress((void**)&wal, g_wal);
    cudaGetSymbolAddress((void**)&sc2, g_sc2);  cudaGetSymbolAddress((void**)&sh2, g_sh2);
    cudaGetSymbolAddress((void**)&sc3, g_sc3);  cudaGetSymbolAddress((void**)&sh3, g_sh3);
    cudaGetSymbolAddress((void**)&sc4, g_sc4);  cudaGetSymbolAddress((void**)&sh4, g_sh4);
    uint32_t* arenau = (uint32_t*)arena;

    const float* x   = (const float*)d_in[0];
    const float* W1  = (const float*)d_in[1];
    const float* b1  = (const float*)d_in[2];
    const float* g1  = (const float*)d_in[3];
    const float* be1 = (const float*)d_in[4];
    const float* m1  = (const float*)d_in[5];
    const float* v1  = (const float*)d_in[6];
    const float* W2  = (const float*)d_in[7];
    const float* b2  = (const float*)d_in[8];
    const float* g2  = (const float*)d_in[9];
    const float* be2 = (const float*)d_in[10];
    const float* m2  = (const float*)d_in[11];
    const float* v2  = (const float*)d_in[12];
    const float* W3  = (const float*)d_in[13];
    const float* b3  = (const float*)d_in[14];
    const float* g3  = (const float*)d_in[15];
    const float* be3 = (const float*)d_in[16];
    const float* m3  = (const float*)d_in[17];
    const float* v3  = (const float*)d_in[18];
    const float* W4  = (const float*)d_in[19];
    const float* b4  = (const float*)d_in[20];
    const float* g4  = (const float*)d_in[21];
    const float* be4 = (const float*)d_in[22];
    const float* m4  = (const float*)d_in[23];
    const float* v4  = (const float*)d_in[24];
    const float* Wa  = (const float*)d_in[25];
    const float* ba  = (const float*)d_in[26];
    const float* Wb  = (const float*)d_in[27];
    const float* bb  = (const float*)d_in[28];
    float* out = (float*)d_out;

    // prep: weight splits + BN folds
    prep_kernel<<<11719, NTHREADS>>>(W2, W3, W4, Wa,
        b2, g2, be2, m2, v2, b3, g3, be3, m3, v3, b4, g4, be4, m4, v4);

    // conv1 (float) + pool1 (split32)
    conv1_kernel<<<BATCH, NTHREADS>>>(x, W1, b1, g1, be1, m1, v1, arena + OFF_C1);
    {
        long long total = (long long)BATCH * 64 * 100;
        pool_split_kernel<<<(int)((total + NTHREADS - 1) / NTHREADS), NTHREADS>>>(
            arena + OFF_C1, arenau + OFF_P1, 64, 20, 10, total);
    }
    // conv2: implicit-im2col bf16 GEMM (K=576, N=128) -> float c2
    gemm_bf16<0, 64, 10><<<dim3(1, 6400, 1), NTHREADS>>>(
        arenau + OFF_P1, nullptr, w2h, w2l, arena + OFF_C2, nullptr,
        sc2, sh2, nullptr, 576, 128, 128, 0, 0, 0);
    // pool2 (split32)
    {
        long long total = (long long)BATCH * 128 * 25;
        pool_split_kernel<<<(int)((total + NTHREADS - 1) / NTHREADS), NTHREADS>>>(
            arena + OFF_C2, arenau + OFF_P2, 128, 10, 5, total);
    }
    // conv3 (K=1152, N=256) -> split32 c3
    gemm_bf16<1, 128, 5><<<dim3(2, 1600, 1), NTHREADS>>>(
        arenau + OFF_P2, nullptr, w3h, w3l, arenau + OFF_C3, nullptr,
        sc3, sh3, nullptr, 1152, 256, 256, 0, 0, 0);
    // conv4 (K=2304, N=256) -> pair-packed feats h/l
    gemm_bf16<2, 256, 5><<<dim3(2, 1600, 1), NTHREADS>>>(
        arenau + OFF_C3, nullptr, w4h, w4l,
        arenau + OFF_FEATS_H, arenau + OFF_FEATS_L,
        sc4, sh4, nullptr, 2304, 256, 256, 0, 0, 0);
    // stage 1 MLP (K=256, Wa rows 80:336 -> kpOff=40) -> float H
    gemm_bf16<3, 0, 0><<<dim3(5, 64, 25), NTHREADS>>>(
        arenau + OFF_FEATS_H, arenau + OFF_FEATS_L, wah, wal,
        arena + OFF_H, nullptr, nullptr, nullptr, ba,
        256, 600, 600, 128, 100800, 40);
    gemm2_softmax_kernel<<<dim3(1024, 25), NTHREADS>>>(arena + OFF_H, Wb, bb,
                                                       arena + OFF_PREDS);
    // gather -> pair-packed in2 h/l
    {
        long long total = 25LL * 8192 * 168;
        gather_kernel<<<(int)((total + NTHREADS - 1) / NTHREADS), NTHREADS>>>(
            arena + OFF_PREDS, arenau + OFF_FEATS_H, arenau + OFF_FEATS_L,
            arenau + OFF_IN2_H, arenau + OFF_IN2_L);
    }
    // stage 2 MLP (K=336)
    gemm_bf16<3, 0, 0><<<dim3(5, 64, 25), NTHREADS>>>(
        arenau + OFF_IN2_H, arenau + OFF_IN2_L, wah, wal,
        arena + OFF_H, nullptr, nullptr, nullptr, ba,
        336, 600, 600, 168, 100800, 0);
    gemm2_softmax_kernel<<<dim3(1024, 25), NTHREADS>>>(arena + OFF_H, Wb, bb,
                                                       out + 81920);
    mean_kernel<<<320, NTHREADS>>>(out + 81920, out);
}

// round 10
// speedup vs baseline: 1.3331x; 1.0312x over previous
#include <cuda_runtime.h>
#include <cstdint>
#include <cstddef>

#define NTHREADS 256
#define BATCH 8192

// ---------------------------------------------------------------------------
// Scratch arena (word offsets, 4B words; lifetimes verified):
//  c1    [0, 209715200)            float   conv1 out [b][64][20][20]
//  p1    [209715200, 262144000)    split32 pool1 out [b][64][10][10]
//  c2    [0, 104857600)            float   conv2 out [b][128][10][10]
//  p2    [104857600, 131072000)    split32 pool2 out
//  c3    [131072000, 183500800)    split32 conv3 out [b][256][5][5]
//  featsH[0, 26214400) featsL[26214400, 52428800)  pair-packed [25][8192][128w]
//  H     [52428800, 175308800)     float   [25][8192][600]
//  preds [183500800, 185548800)    float   [25][8192][10]
//  in2H  [185548800, 221593600) in2L [221593600, 257638400) [25][8192][176w]
// ---------------------------------------------------------------------------
__device__ float g_arena[262144000];     // 1.049 GB

static const size_t OFF_C1      = 0;
static const size_t OFF_P1      = 209715200;
static const size_t OFF_C2      = 0;
static const size_t OFF_P2      = 104857600;
static const size_t OFF_C3      = 131072000;
static const size_t OFF_FEATS_H = 0;
static const size_t OFF_FEATS_L = 26214400;
static const size_t OFF_H       = 52428800;
static const size_t OFF_PREDS   = 183500800;
static const size_t OFF_IN2_H   = 185548800;
static const size_t OFF_IN2_L   = 221593600;

// pre-split weight planes, pair-packed along k: word(kp,n) = bf16(k=2kp+1)<<16 | bf16(k=2kp)
// wa planes padded to 176 kp-rows per node (rows 168..175 are zero) so MLP2 K=352 (even chunks)
__device__ uint32_t g_w2h[288 * 128],  g_w2l[288 * 128];
__device__ uint32_t g_w3h[576 * 256],  g_w3l[576 * 256];
__device__ uint32_t g_w4h[1152 * 256], g_w4l[1152 * 256];
__device__ uint32_t g_wah[25 * 176 * 600], g_wal[25 * 176 * 600];
__device__ float g_sc2[128], g_sh2[128];
__device__ float g_sc3[256], g_sh3[256];
__device__ float g_sc4[256], g_sh4[256];

// ---------------------------------------------------------------------------
// bf16 helpers
// ---------------------------------------------------------------------------
__device__ __forceinline__ uint32_t f2bf(float x)
{
    unsigned short h;
    asm("cvt.rn.bf16.f32 %0, %1;" : "=h"(h) : "f"(x));
    return (uint32_t)h;
}

// element-split32: hi bf16 in high halfword, lo bf16 in low halfword
__device__ __forceinline__ uint32_t split32(float x)
{
    uint32_t hb = f2bf(x);
    float r = x - __uint_as_float(hb << 16);
    uint32_t lb = f2bf(r);
    return (hb << 16) | lb;
}

// pair-pack two floats into (h-plane word, l-plane word)
__device__ __forceinline__ void packpair(float x0, float x1, uint32_t& wh, uint32_t& wl)
{
    uint32_t s0 = split32(x0), s1 = split32(x1);
    wh = __byte_perm(s0, s1, 0x7632);   // [s0.hi16, s1.hi16]
    wl = __byte_perm(s0, s1, 0x5410);   // [s0.lo16, s1.lo16]
}

__device__ __forceinline__ void mma16(float d[4], const uint32_t a[4], const uint32_t b[2])
{
    asm volatile(
        "mma.sync.aligned.m16n8k16.row.col.f32.bf16.bf16.f32 "
        "{%0,%1,%2,%3}, {%4,%5,%6,%7}, {%8,%9}, {%0,%1,%2,%3};\n"
        : "+f"(d[0]), "+f"(d[1]), "+f"(d[2]), "+f"(d[3])
        : "r"(a[0]), "r"(a[1]), "r"(a[2]), "r"(a[3]), "r"(b[0]), "r"(b[1]));
}

#define LDSM_X4(r0, r1, r2, r3, addr)                                            \
    asm volatile("ldmatrix.sync.aligned.m8n8.x4.shared.b16 {%0,%1,%2,%3}, [%4];" \
                 : "=r"(r0), "=r"(r1), "=r"(r2), "=r"(r3) : "r"(addr))

// ---------------------------------------------------------------------------
// prep: split+pack weights into bf16 planes + BN folds
// ---------------------------------------------------------------------------
__global__ __launch_bounds__(NTHREADS) void prep_kernel(
    const float* __restrict__ W2, const float* __restrict__ W3,
    const float* __restrict__ W4, const float* __restrict__ Wa,
    const float* __restrict__ b2, const float* __restrict__ g2, const float* __restrict__ be2,
    const float* __restrict__ m2, const float* __restrict__ v2,
    const float* __restrict__ b3, const float* __restrict__ g3, const float* __restrict__ be3,
    const float* __restrict__ m3, const float* __restrict__ v3,
    const float* __restrict__ b4, const float* __restrict__ g4, const float* __restrict__ be4,
    const float* __restrict__ m4, const float* __restrict__ v4)
{
    int i = blockIdx.x * NTHREADS + threadIdx.x;
    if (i < 36864) {                                   // w2: [288kp][128n]
        int kp = i >> 7, n = i & 127;
        packpair(W2[n * 576 + 2 * kp], W2[n * 576 + 2 * kp + 1], g_w2h[i], g_w2l[i]);
    }
    int i3 = i - 36864;
    if (i3 >= 0 && i3 < 147456) {                      // w3: [576kp][256n]
        int kp = i3 >> 8, n = i3 & 255;
        packpair(W3[n * 1152 + 2 * kp], W3[n * 1152 + 2 * kp + 1], g_w3h[i3], g_w3l[i3]);
    }
    int i4 = i - 36864 - 147456;
    if (i4 >= 0 && i4 < 294912) {                      // w4: [1152kp][256n]
        int kp = i4 >> 8, n = i4 & 255;
        packpair(W4[n * 2304 + 2 * kp], W4[n * 2304 + 2 * kp + 1], g_w4h[i4], g_w4l[i4]);
    }
    int ia = i - 36864 - 147456 - 294912;
    if (ia >= 0 && ia < 2640000) {                     // wa: [25z][176kp][600j]
        int z = ia / 105600, r = ia % 105600;
        int kp = r / 600, j = r % 600;
        if (kp < 168) {
            const float* w = Wa + ((size_t)z * 336 + 2 * kp) * 600 + j;
            packpair(w[0], w[600], g_wah[ia], g_wal[ia]);
        } else {
            g_wah[ia] = 0u; g_wal[ia] = 0u;
        }
    }
    int ib = i - 36864 - 147456 - 294912 - 2640000;
    if (ib >= 0 && ib < 128) {
        float s = g2[ib] * rsqrtf(v2[ib] + 1e-5f);
        g_sc2[ib] = s; g_sh2[ib] = (b2[ib] - m2[ib]) * s + be2[ib];
    } else if (ib >= 128 && ib < 384) {
        int c = ib - 128;
        float s = g3[c] * rsqrtf(v3[c] + 1e-5f);
        g_sc3[c] = s; g_sh3[c] = (b3[c] - m3[c]) * s + be3[c];
    } else if (ib >= 384 && ib < 640) {
        int c = ib - 384;
        float s = g4[c] * rsqrtf(v4[c] + 1e-5f);
        g_sc4[c] = s; g_sh4[c] = (b4[c] - m4[c]) * s + be4[c];
    }
}

// ---------------------------------------------------------------------------
// conv1: 3 -> 64, 20x20, fused BN+ReLU, float out. One block per image.
// ---------------------------------------------------------------------------
__global__ __launch_bounds__(NTHREADS) void conv1_kernel(
    const float* __restrict__ x, const float* __restrict__ W,
    const float* __restrict__ bias, const float* __restrict__ gam,
    const float* __restrict__ bet, const float* __restrict__ mu,
    const float* __restrict__ var, float* __restrict__ out)
{
    __shared__ float sIn[3 * 22 * 22];
    __shared__ float sW[64 * 27];
    __shared__ float sScale[64], sShift[64];
    int b = blockIdx.x, tid = threadIdx.x;

    for (int i = tid; i < 3 * 22 * 22; i += NTHREADS) sIn[i] = 0.f;
    __syncthreads();
    const float* xb = x + (size_t)b * 1200;
    for (int i = tid; i < 1200; i += NTHREADS) {
        int ci = i / 400, p = i % 400, y = p / 20, xx = p % 20;
        sIn[ci * 484 + (y + 1) * 22 + (xx + 1)] = xb[i];
    }
    for (int i = tid; i < 1728; i += NTHREADS) sW[i] = W[i];
    if (tid < 64) {
        float sc = gam[tid] * rsqrtf(var[tid] + 1e-5f);
        sScale[tid] = sc;
        sShift[tid] = (bias[tid] - mu[tid]) * sc + bet[tid];
    }
    __syncthreads();

    int co = tid & 63, q = tid >> 6;
    float scale = sScale[co], shift = sShift[co];
    float* ob = out + ((size_t)b * 64 + co) * 400;
    for (int r = 0; r < 5; r++) {
        int y = q * 5 + r;
        float acc[20];
        #pragma unroll
        for (int xx = 0; xx < 20; xx++) acc[xx] = 0.f;
        #pragma unroll
        for (int ci = 0; ci < 3; ci++) {
            float w[9];
            #pragma unroll
            for (int k = 0; k < 9; k++) w[k] = sW[co * 27 + ci * 9 + k];
            const float* base = sIn + ci * 484 + y * 22;
            #pragma unroll
            for (int dy = 0; dy < 3; dy++) {
                const float* row = base + dy * 22;
                #pragma unroll
                for (int xx = 0; xx < 20; xx++)
                    acc[xx] += row[xx] * w[dy * 3] + row[xx + 1] * w[dy * 3 + 1]
                             + row[xx + 2] * w[dy * 3 + 2];
            }
        }
        #pragma unroll
        for (int xx = 0; xx < 20; xx++)
            ob[y * 20 + xx] = fmaxf(acc[xx] * scale + shift, 0.f);
    }
}

// ---------------------------------------------------------------------------
// maxpool 3x3 s2 p1, float in -> element-split32 out
// ---------------------------------------------------------------------------
__global__ __launch_bounds__(NTHREADS) void pool_split_kernel(
    const float* __restrict__ in, uint32_t* __restrict__ out,
    int C, int H, int OH, long long total)
{
    long long idx = (long long)blockIdx.x * NTHREADS + threadIdx.x;
    if (idx >= total) return;
    int W = H, OW = OH;
    int ox = (int)(idx % OW); long long t = idx / OW;
    int oy = (int)(t % OH);  t /= OH;
    int c  = (int)(t % C);   int b = (int)(t / C);
    const float* p = in + ((size_t)b * C + c) * H * W;
    float m = -3.402823466e38f;
    #pragma unroll
    for (int dy = 0; dy < 3; dy++) {
        int iy = 2 * oy - 1 + dy;
        if (iy < 0 || iy >= H) continue;
        #pragma unroll
        for (int dx = 0; dx < 3; dx++) {
            int ix = 2 * ox - 1 + dx;
            if (ix < 0 || ix >= W) continue;
            m = fmaxf(m, p[iy * W + ix]);
        }
    }
    out[idx] = split32(m);
}

// ---------------------------------------------------------------------------
// bf16 tensor-core GEMM, 3-product (Ah·Bh + Al·Bh + Ah·Bl) scheme.
// Tile 128x128x16, 8 warps (4x2), m16n8k16, ldmatrix fragment loads.
// Double-buffered smem (compile-time buffer offsets via unroll-by-2),
// ONE __syncthreads per k-chunk. nch guaranteed EVEN for all call sites.
// EPI: 0 float [b][128][100]; 1 split32 [b][256][25];
//      2 pair-packed feats h/l [n][b][128w]; 3 float tanh H[z][8192][600]
// ---------------------------------------------------------------------------
#define GEMM_FETCH(kc_)                                                          \
    {                                                                            \
        int kc__ = (kc_);                                                        \
        if (CC == 0) {                                                           \
            uint4 h4 = *(const uint4*)(Abh + (size_t)(mBase + lm) * aw           \
                                       + (kc__ >> 1) + (lkq >> 1));              \
            uint4 l4 = *(const uint4*)(Abl + (size_t)(mBase + lm) * aw           \
                                       + (kc__ >> 1) + (lkq >> 1));              \
            avh[0] = h4.x; avh[1] = h4.y; avh[2] = h4.z; avh[3] = h4.w;          \
            avl[0] = l4.x; avl[1] = l4.y; avl[2] = l4.z; avl[3] = l4.w;          \
        } else {                                                                 \
            uint32_t e[8];                                                       \
            _Pragma("unroll")                                                    \
            for (int j = 0; j < 8; j++) {                                        \
                int k = kc__ + lkq + j;                                          \
                int ci = k / 9, q = k - ci * 9;                                  \
                int iy = py - 1 + q / 3, ix = px - 1 + q % 3;                    \
                uint32_t v = 0u;                                                 \
                if (iy >= 0 && iy < S && ix >= 0 && ix < S)                      \
                    v = A[ib_off + ci * S * S + iy * S + ix];                    \
                e[j] = v;                                                        \
            }                                                                    \
            _Pragma("unroll")                                                    \
            for (int tt = 0; tt < 4; tt++) {                                     \
                avh[tt] = __byte_perm(e[2 * tt], e[2 * tt + 1], 0x7632);         \
                avl[tt] = __byte_perm(e[2 * tt], e[2 * tt + 1], 0x5410);         \
            }                                                                    \
        }                                                                        \
        _Pragma("unroll")                                                        \
        for (int jj = 0; jj < 4; jj++) {                                         \
            int kp = (kc__ >> 1) + (lkq >> 1) + jj;                              \
            bvh[jj] = (gn < N) ? Bbh[(size_t)kp * ldb + gn] : 0u;                \
            bvl[jj] = (gn < N) ? Bbl[(size_t)kp * ldb + gn] : 0u;                \
        }                                                                        \
    }

// store staged regs into buffer at word offset BUFW (0 or 6144)
#define GEMM_STORE(BUFW)                                                         \
    {                                                                            \
        *(uint4*)&smemAll[(BUFW) + 0    + sIdx] = make_uint4(avh[0], avh[1], avh[2], avh[3]); \
        *(uint4*)&smemAll[(BUFW) + 1536 + sIdx] = make_uint4(avl[0], avl[1], avl[2], avl[3]); \
        *(uint4*)&smemAll[(BUFW) + 3072 + sIdx] = make_uint4(bvh[0], bvh[1], bvh[2], bvh[3]); \
        *(uint4*)&smemAll[(BUFW) + 4608 + sIdx] = make_uint4(bvl[0], bvl[1], bvl[2], bvl[3]); \
    }

// compute from buffer at byte offset BUFB (0u or 24576u)
#define GEMM_COMPUTE(BUFB)                                                       \
    {                                                                            \
        uint32_t fah[2][4], fal[2][4];                                           \
        LDSM_X4(fah[0][0], fah[0][1], fah[0][2], fah[0][3], adrAh + (BUFB));     \
        LDSM_X4(fah[1][0], fah[1][1], fah[1][2], fah[1][3], adrAh + (BUFB) + 768u); \
        LDSM_X4(fal[0][0], fal[0][1], fal[0][2], fal[0][3], adrAl + (BUFB));     \
        LDSM_X4(fal[1][0], fal[1][1], fal[1][2], fal[1][3], adrAl + (BUFB) + 768u); \
        _Pragma("unroll")                                                        \
        for (int bt = 0; bt < 2; bt++) {                                         \
            uint32_t bh[8], bl[8];                                               \
            LDSM_X4(bh[0], bh[1], bh[2], bh[3], adrBh + (BUFB) + bt * 1536u);    \
            LDSM_X4(bh[4], bh[5], bh[6], bh[7], adrBh + (BUFB) + bt * 1536u + 768u); \
            LDSM_X4(bl[0], bl[1], bl[2], bl[3], adrBl + (BUFB) + bt * 1536u);    \
            LDSM_X4(bl[4], bl[5], bl[6], bl[7], adrBl + (BUFB) + bt * 1536u + 768u); \
            _Pragma("unroll")                                                    \
            for (int n4 = 0; n4 < 4; n4++) {                                     \
                int nt = bt * 4 + n4;                                            \
                uint32_t bhf[2] = { bh[n4 * 2], bh[n4 * 2 + 1] };                \
                uint32_t blf[2] = { bl[n4 * 2], bl[n4 * 2 + 1] };                \
                _Pragma("unroll")                                                \
                for (int mt = 0; mt < 2; mt++) {                                 \
                    mma16(acc[mt][nt], fah[mt], bhf);                            \
                    mma16(acc[mt][nt], fal[mt], bhf);                            \
                    mma16(acc[mt][nt], fah[mt], blf);                            \
                }                                                                \
            }                                                                    \
        }                                                                        \
    }

template <int EPI, int CC, int S>
__global__ __launch_bounds__(NTHREADS, 2) void gemm_bf16(
    const uint32_t* __restrict__ A, const uint32_t* __restrict__ A2,
    const uint32_t* __restrict__ Bh, const uint32_t* __restrict__ Bl,
    void* __restrict__ Cv, void* __restrict__ C2v,
    const float* __restrict__ sc, const float* __restrict__ sh,
    const float* __restrict__ bias,
    int K, int N, int ldb, int aw, int bStrideZ, int kpOff)
{
    // plane order (1536 words each): Ah0 Al0 Bh0 Bl0 | Ah1 Al1 Bh1 Bl1
    __shared__ uint32_t smemAll[12288];   // 48 KB

    int z = blockIdx.z;
    const uint32_t* Abh = A;
    const uint32_t* Abl = A2;
    const uint32_t* Bbh = Bh + (size_t)kpOff * ldb;
    const uint32_t* Bbl = Bl + (size_t)kpOff * ldb;
    if (EPI == 3) {
        Abh += (size_t)z * 8192 * aw;
        Abl += (size_t)z * 8192 * aw;
        Bbh += (size_t)z * bStrideZ;
        Bbl += (size_t)z * bStrideZ;
    }
    int mBase = blockIdx.y * 128, nBase = blockIdx.x * 128;
    int t = threadIdx.x, lane = t & 31, wid = t >> 5;
    int wm = (wid & 3) * 32, wn = (wid >> 2) * 64;

    int lm = t & 127, lkq = (t >> 7) * 8;
    int gn = nBase + lm;
    uint32_t sIdx = (uint32_t)(lm * 12 + (lkq >> 1));

    int ib_off = 0, py = 0, px = 0;
    if (CC > 0) {
        const int SS = S * S;
        int r = mBase + lm;
        int b = r / SS, p = r - b * SS;
        py = p / S; px = p - py * S;
        ib_off = b * CC * SS;
    }

    // ldmatrix per-lane source addresses (buffer-0 bases; buffer 1 = +24576B)
    uint32_t base_u = (uint32_t)__cvta_generic_to_shared(smemAll);
    int lt = lane >> 3, lrow = lane & 7;
    uint32_t aOff = (uint32_t)(((wm + ((lt & 1) << 3) + lrow) * 12 + ((lt >> 1) << 2)) * 4);
    uint32_t bOff = (uint32_t)(((wn + ((lt >> 1) << 3) + lrow) * 12 + ((lt & 1) << 2)) * 4);
    uint32_t adrAh = base_u + aOff;
    uint32_t adrAl = base_u + 6144u + aOff;
    uint32_t adrBh = base_u + 12288u + bOff;
    uint32_t adrBl = base_u + 18432u + bOff;

    float acc[2][8][4];
    #pragma unroll
    for (int mt = 0; mt < 2; mt++)
        #pragma unroll
        for (int nt = 0; nt < 8; nt++)
            #pragma unroll
            for (int e = 0; e < 4; e++) acc[mt][nt][e] = 0.f;

    uint32_t avh[4], avl[4], bvh[4], bvl[4];
    GEMM_FETCH(0);

    int nch = K / 16;   // even by construction at every call site
    for (int ch = 0; ch < nch; ch += 2) {
        // chunk ch -> buffer 0
        GEMM_STORE(0);
        __syncthreads();
        GEMM_FETCH((ch + 1) * 16);
        GEMM_COMPUTE(0u);
        // chunk ch+1 -> buffer 1
        GEMM_STORE(6144);
        __syncthreads();
        {
            int kcn = (ch + 2 < nch) ? (ch + 2) * 16 : 0;
            GEMM_FETCH(kcn);
        }
        GEMM_COMPUTE(24576u);
    }

    // epilogue
    int elc = lane & 3, elr = lane >> 2;
    #pragma unroll
    for (int mt = 0; mt < 2; mt++) {
        #pragma unroll
        for (int nt = 0; nt < 8; nt++) {
            if (EPI == 2) {
                #pragma unroll
                for (int rr = 0; rr < 2; rr++) {
                    int row = mBase + wm + mt * 16 + elr + rr * 8;
                    int col = nBase + wn + nt * 8 + 2 * elc;
                    float v0 = acc[mt][nt][rr * 2 + 0];
                    float v1 = acc[mt][nt][rr * 2 + 1];
                    v0 = fmaxf(v0 * sc[col] + sh[col], 0.f);
                    v1 = fmaxf(v1 * sc[col + 1] + sh[col + 1], 0.f);
                    int b = row / 25, p = row - b * 25;
                    uint32_t wh, wl;
                    packpair(v0, v1, wh, wl);
                    size_t o = ((size_t)p * 8192 + b) * 128 + (col >> 1);
                    ((uint32_t*)Cv)[o]  = wh;
                    ((uint32_t*)C2v)[o] = wl;
                }
            } else {
                #pragma unroll
                for (int e = 0; e < 4; e++) {
                    int row = mBase + wm + mt * 16 + elr + (e >> 1) * 8;
                    int col = nBase + wn + nt * 8 + 2 * elc + (e & 1);
                    float v = acc[mt][nt][e];
                    if (EPI == 0) {
                        int b = row / 100, p = row - b * 100;
                        ((float*)Cv)[((size_t)b * 128 + col) * 100 + p] =
                            fmaxf(v * sc[col] + sh[col], 0.f);
                    } else if (EPI == 1) {
                        int b = row / 25, p = row - b * 25;
                        ((uint32_t*)Cv)[((size_t)b * 256 + col) * 25 + p] =
                            split32(fmaxf(v * sc[col] + sh[col], 0.f));
                    } else {
                        if (col < N)
                            ((float*)Cv)[((size_t)z * 8192 + row) * 600 + col] =
                                tanhf(v + bias[(size_t)z * 600 + col]);
                    }
                }
            }
        }
    }
}

// ---------------------------------------------------------------------------
// GEMM2 + softmax (600 -> 10), warp per row, Wb in smem (pad 11)
// ---------------------------------------------------------------------------
__global__ __launch_bounds__(NTHREADS) void gemm2_softmax_kernel(
    const float* __restrict__ H, const float* __restrict__ Wb,
    const float* __restrict__ bb, float* __restrict__ out)
{
    __shared__ float sW[600 * 11];
    __shared__ float sb[10];
    int n = blockIdx.y, tid = threadIdx.x;
    const float* Wn = Wb + (size_t)n * 6000;
    for (int i = tid; i < 6000; i += NTHREADS) {
        int k = i / 10, c = i % 10;
        sW[k * 11 + c] = Wn[i];
    }
    if (tid < 10) sb[tid] = bb[n * 10 + tid];
    __syncthreads();

    int warp = tid >> 5, lane = tid & 31;
    int b = blockIdx.x * 8 + warp;
    const float* hr = H + ((size_t)n * 8192 + b) * 600;
    float acc[10];
    #pragma unroll
    for (int c = 0; c < 10; c++) acc[c] = 0.f;
    for (int k = lane; k < 600; k += 32) {
        float v = hr[k];
        #pragma unroll
        for (int c = 0; c < 10; c++) acc[c] += v * sW[k * 11 + c];
    }
    #pragma unroll
    for (int c = 0; c < 10; c++) {
        #pragma unroll
        for (int off = 16; off > 0; off >>= 1)
            acc[c] += __shfl_down_sync(0xffffffffu, acc[c], off);
    }
    if (lane == 0) {
        float l[10], mx = -3.402823466e38f;
        #pragma unroll
        for (int c = 0; c < 10; c++) { l[c] = acc[c] + sb[c]; mx = fmaxf(mx, l[c]); }
        float s = 0.f;
        #pragma unroll
        for (int c = 0; c < 10; c++) { l[c] = expf(l[c] - mx); s += l[c]; }
        float inv = 1.f / s;
        float* o = out + ((size_t)n * 8192 + b) * 10;
        #pragma unroll
        for (int c = 0; c < 10; c++) o[c] = l[c] * inv;
    }
}

// ---------------------------------------------------------------------------
// neighbor gather -> pair-packed in2 planes (176 words/row; 168..175 zero pad)
// ---------------------------------------------------------------------------
__device__ __forceinline__ int nei_of(int i, int slot)
{
    int nb[8];
    #pragma unroll
    for (int t = 0; t < 8; t++) nb[t] = -1;
    int cnt = 0;
    bool l = (i % 5 != 0), r = ((i + 1) % 5 != 0), u = (i >= 5), d = (i + 5 < 25);
    if (u)      nb[cnt++] = i - 5;
    if (l)      nb[cnt++] = i - 1;
    if (r)      nb[cnt++] = i + 1;
    if (d)      nb[cnt++] = i + 5;
    if (u && l) nb[cnt++] = i - 6;
    if (u && r) nb[cnt++] = i - 4;
    if (d && l) nb[cnt++] = i + 4;
    if (d && r) nb[cnt++] = i + 6;
    return nb[slot];
}

__global__ __launch_bounds__(NTHREADS) void gather_kernel(
    const float* __restrict__ preds,
    const uint32_t* __restrict__ fh, const uint32_t* __restrict__ fl,
    uint32_t* __restrict__ ih, uint32_t* __restrict__ il)
{
    long long idx = (long long)blockIdx.x * NTHREADS + threadIdx.x;
    if (idx >= 25LL * 8192 * 176) return;
    int j = (int)(idx % 176);
    long long t = idx / 176;
    int b = (int)(t % 8192);
    int n = (int)(t / 8192);
    uint32_t wh = 0u, wl = 0u;
    if (j >= 168) {
        // zero pad
    } else if (j >= 40) {
        size_t src = ((size_t)n * 8192 + b) * 128 + (j - 40);
        wh = fh[src]; wl = fl[src];
    } else {
        int c0 = (2 * j) % 10, s = (2 * j) / 10;
        int nei = nei_of(n, s);
        float p0 = 0.f, p1 = 0.f;
        if (nei >= 0) {
            const float* pp = preds + ((size_t)nei * 8192 + b) * 10 + c0;
            p0 = pp[0]; p1 = pp[1];
        }
        packpair(p0, p1, wh, wl);
    }
    ih[idx] = wh;
    il[idx] = wl;
}

__global__ __launch_bounds__(NTHREADS) void mean_kernel(
    const float* __restrict__ second, float* __restrict__ mean)
{
    int idx = blockIdx.x * NTHREADS + threadIdx.x;
    if (idx >= 81920) return;
    float s = 0.f;
    #pragma unroll
    for (int n = 0; n < 25; n++) s += second[(size_t)n * 81920 + idx];
    mean[idx] = s * 0.04f;
}

// ---------------------------------------------------------------------------
// launch
// ---------------------------------------------------------------------------
extern "C" void kernel_launch(void* const* d_in, const int* in_sizes, int n_in,
                              void* d_out, int out_size)
{
    (void)in_sizes; (void)n_in; (void)out_size;
    float* arena = nullptr;
    uint32_t *w2h, *w2l, *w3h, *w3l, *w4h, *w4l, *wah, *wal;
    float *sc2, *sh2, *sc3, *sh3, *sc4, *sh4;
    cudaGetSymbolAddress((void**)&arena, g_arena);
    cudaGetSymbolAddress((void**)&w2h, g_w2h);  cudaGetSymbolAddress((void**)&w2l, g_w2l);
    cudaGetSymbolAddress((void**)&w3h, g_w3h);  cudaGetSymbolAddress((void**)&w3l, g_w3l);
    cudaGetSymbolAddress((void**)&w4h, g_w4h);  cudaGetSymbolAddress((void**)&w4l, g_w4l);
    cudaGetSymbolAddress((void**)&wah, g_wah);  cudaGetSymbolAddress((void**)&wal, g_wal);
    cudaGetSymbolAddress((void**)&sc2, g_sc2);  cudaGetSymbolAddress((void**)&sh2, g_sh2);
    cudaGetSymbolAddress((void**)&sc3, g_sc3);  cudaGetSymbolAddress((void**)&sh3, g_sh3);
    cudaGetSymbolAddress((void**)&sc4, g_sc4);  cudaGetSymbolAddress((void**)&sh4, g_sh4);
    uint32_t* arenau = (uint32_t*)arena;

    const float* x   = (const float*)d_in[0];
    const float* W1  = (const float*)d_in[1];
    const float* b1  = (const float*)d_in[2];
    const float* g1  = (const float*)d_in[3];
    const float* be1 = (const float*)d_in[4];
    const float* m1  = (const float*)d_in[5];
    const float* v1  = (const float*)d_in[6];
    const float* W2  = (const float*)d_in[7];
    const float* b2  = (const float*)d_in[8];
    const float* g2  = (const float*)d_in[9];
    const float* be2 = (const float*)d_in[10];
    const float* m2  = (const float*)d_in[11];
    const float* v2  = (const float*)d_in[12];
    const float* W3  = (const float*)d_in[13];
    const float* b3  = (const float*)d_in[14];
    const float* g3  = (const float*)d_in[15];
    const float* be3 = (const float*)d_in[16];
    const float* m3  = (const float*)d_in[17];
    const float* v3  = (const float*)d_in[18];
    const float* W4  = (const float*)d_in[19];
    const float* b4  = (const float*)d_in[20];
    const float* g4  = (const float*)d_in[21];
    const float* be4 = (const float*)d_in[22];
    const float* m4  = (const float*)d_in[23];
    const float* v4  = (const float*)d_in[24];
    const float* Wa  = (const float*)d_in[25];
    const float* ba  = (const float*)d_in[26];
    const float* Wb  = (const float*)d_in[27];
    const float* bb  = (const float*)d_in[28];
    float* out = (float*)d_out;

    // prep: weight splits + BN folds (3,119,872 work items)
    prep_kernel<<<12187, NTHREADS>>>(W2, W3, W4, Wa,
        b2, g2, be2, m2, v2, b3, g3, be3, m3, v3, b4, g4, be4, m4, v4);

    // conv1 (float) + pool1 (split32)
    conv1_kernel<<<BATCH, NTHREADS>>>(x, W1, b1, g1, be1, m1, v1, arena + OFF_C1);
    {
        long long total = (long long)BATCH * 64 * 100;
        pool_split_kernel<<<(int)((total + NTHREADS - 1) / NTHREADS), NTHREADS>>>(
            arena + OFF_C1, arenau + OFF_P1, 64, 20, 10, total);
    }
    // conv2: implicit-im2col bf16 GEMM (K=576, nch=36) -> float c2
    gemm_bf16<0, 64, 10><<<dim3(1, 6400, 1), NTHREADS>>>(
        arenau + OFF_P1, nullptr, w2h, w2l, arena + OFF_C2, nullptr,
        sc2, sh2, nullptr, 576, 128, 128, 0, 0, 0);
    // pool2 (split32)
    {
        long long total = (long long)BATCH * 128 * 25;
        pool_split_kernel<<<(int)((total + NTHREADS - 1) / NTHREADS), NTHREADS>>>(
            arena + OFF_C2, arenau + OFF_P2, 128, 10, 5, total);
    }
    // conv3 (K=1152, nch=72) -> split32 c3
    gemm_bf16<1, 128, 5><<<dim3(2, 1600, 1), NTHREADS>>>(
        arenau + OFF_P2, nullptr, w3h, w3l, arenau + OFF_C3, nullptr,
        sc3, sh3, nullptr, 1152, 256, 256, 0, 0, 0);
    // conv4 (K=2304, nch=144) -> pair-packed feats h/l
    gemm_bf16<2, 256, 5><<<dim3(2, 1600, 1), NTHREADS>>>(
        arenau + OFF_C3, nullptr, w4h, w4l,
        arenau + OFF_FEATS_H, arenau + OFF_FEATS_L,
        sc4, sh4, nullptr, 2304, 256, 256, 0, 0, 0);
    // stage 1 MLP (K=256, nch=16, Wa rows 80:336 -> kpOff=40) -> float H
    gemm_bf16<3, 0, 0><<<dim3(5, 64, 25), NTHREADS>>>(
        arenau + OFF_FEATS_H, arenau + OFF_FEATS_L, wah, wal,
        arena + OFF_H, nullptr, nullptr, nullptr, ba,
        256, 600, 600, 128, 105600, 40);
    gemm2_softmax_kernel<<<dim3(1024, 25), NTHREADS>>>(arena + OFF_H, Wb, bb,
                                                       arena + OFF_PREDS);
    // gather -> pair-packed in2 h/l (176 words/row, zero pad)
    {
        long long total = 25LL * 8192 * 176;
        gather_kernel<<<(int)((total + NTHREADS - 1) / NTHREADS), NTHREADS>>>(
            arena + OFF_PREDS, arenau + OFF_FEATS_H, arenau + OFF_FEATS_L,
            arenau + OFF_IN2_H, arenau + OFF_IN2_L);
    }
    // stage 2 MLP (K padded 336->352, nch=22)
    gemm_bf16<3, 0, 0><<<dim3(5, 64, 25), NTHREADS>>>(
        arenau + OFF_IN2_H, arenau + OFF_IN2_L, wah, wal,
        arena + OFF_H, nullptr, nullptr, nullptr, ba,
        352, 600, 600, 176, 105600, 0);
    gemm2_softmax_kernel<<<dim3(1024, 25), NTHREADS>>>(arena + OFF_H, Wb, bb,
                                                       out + 81920);
    mean_kernel<<<320, NTHREADS>>>(out + 81920, out);
}

// round 14
// speedup vs baseline: 1.4633x; 1.0977x over previous
#include <cuda_runtime.h>
#include <cstdint>
#include <cstddef>

#define NTHREADS 256
#define BATCH 8192

// ---------------------------------------------------------------------------
// Scratch arena (word offsets, 4B words; lifetimes verified):
//  p1    [209715200, 262144000)    split32 pool1 out [b][64][10][10]
//  c2    [0, 104857600)            float   conv2 out [b][128][10][10]
//  p2    [104857600, 131072000)    split32 pool2 out
//  c3    [131072000, 183500800)    split32 conv3 out [b][256][5][5]
//  featsH[0, 26214400) featsL[26214400, 52428800)  pair-packed [25][8192][128w]
//  H     [52428800, 175308800)     float   [25][8192][600]
//  preds [183500800, 185548800)    float   [25][8192][10]
//  in2H  [185548800, 221593600) in2L [221593600, 257638400) [25][8192][176w]
// ---------------------------------------------------------------------------
__device__ float g_arena[262144000];     // 1.049 GB

static const size_t OFF_P1      = 209715200;
static const size_t OFF_C2      = 0;
static const size_t OFF_P2      = 104857600;
static const size_t OFF_C3      = 131072000;
static const size_t OFF_FEATS_H = 0;
static const size_t OFF_FEATS_L = 26214400;
static const size_t OFF_H       = 52428800;
static const size_t OFF_PREDS   = 183500800;
static const size_t OFF_IN2_H   = 185548800;
static const size_t OFF_IN2_L   = 221593600;

// pre-split weight planes, pair-packed along k: word(kp,n) = bf16(k=2kp+1)<<16 | bf16(k=2kp)
// wa planes padded to 176 kp-rows per node (rows 168..175 are zero) so MLP2 K=352 (even chunks)
__device__ uint32_t g_w2h[288 * 128],  g_w2l[288 * 128];
__device__ uint32_t g_w3h[576 * 256],  g_w3l[576 * 256];
__device__ uint32_t g_w4h[1152 * 256], g_w4l[1152 * 256];
__device__ uint32_t g_wah[25 * 176 * 600], g_wal[25 * 176 * 600];
__device__ float g_sc2[128], g_sh2[128];
__device__ float g_sc3[256], g_sh3[256];
__device__ float g_sc4[256], g_sh4[256];

// ---------------------------------------------------------------------------
// bf16 helpers
// ---------------------------------------------------------------------------
__device__ __forceinline__ uint32_t f2bf(float x)
{
    unsigned short h;
    asm("cvt.rn.bf16.f32 %0, %1;" : "=h"(h) : "f"(x));
    return (uint32_t)h;
}

// element-split32: hi bf16 in high halfword, lo bf16 in low halfword
__device__ __forceinline__ uint32_t split32(float x)
{
    uint32_t hb = f2bf(x);
    float r = x - __uint_as_float(hb << 16);
    uint32_t lb = f2bf(r);
    return (hb << 16) | lb;
}

// pair-pack two floats into (h-plane word, l-plane word)
__device__ __forceinline__ void packpair(float x0, float x1, uint32_t& wh, uint32_t& wl)
{
    uint32_t s0 = split32(x0), s1 = split32(x1);
    wh = __byte_perm(s0, s1, 0x7632);   // [s0.hi16, s1.hi16]
    wl = __byte_perm(s0, s1, 0x5410);   // [s0.lo16, s1.lo16]
}

__device__ __forceinline__ void mma16(float d[4], const uint32_t a[4], const uint32_t b[2])
{
    asm volatile(
        "mma.sync.aligned.m16n8k16.row.col.f32.bf16.bf16.f32 "
        "{%0,%1,%2,%3}, {%4,%5,%6,%7}, {%8,%9}, {%0,%1,%2,%3};\n"
        : "+f"(d[0]), "+f"(d[1]), "+f"(d[2]), "+f"(d[3])
        : "r"(a[0]), "r"(a[1]), "r"(a[2]), "r"(a[3]), "r"(b[0]), "r"(b[1]));
}

#define LDSM_X4(r0, r1, r2, r3, addr)                                            \
    asm volatile("ldmatrix.sync.aligned.m8n8.x4.shared.b16 {%0,%1,%2,%3}, [%4];" \
                 : "=r"(r0), "=r"(r1), "=r"(r2), "=r"(r3) : "r"(addr))

// ---------------------------------------------------------------------------
// prep: split+pack weights into bf16 planes + BN folds
// ---------------------------------------------------------------------------
__global__ __launch_bounds__(NTHREADS) void prep_kernel(
    const float* __restrict__ W2, const float* __restrict__ W3,
    const float* __restrict__ W4, const float* __restrict__ Wa,
    const float* __restrict__ b2, const float* __restrict__ g2, const float* __restrict__ be2,
    const float* __restrict__ m2, const float* __restrict__ v2,
    const float* __restrict__ b3, const float* __restrict__ g3, const float* __restrict__ be3,
    const float* __restrict__ m3, const float* __restrict__ v3,
    const float* __restrict__ b4, const float* __restrict__ g4, const float* __restrict__ be4,
    const float* __restrict__ m4, const float* __restrict__ v4)
{
    int i = blockIdx.x * NTHREADS + threadIdx.x;
    if (i < 36864) {                                   // w2: [288kp][128n]
        int kp = i >> 7, n = i & 127;
        packpair(W2[n * 576 + 2 * kp], W2[n * 576 + 2 * kp + 1], g_w2h[i], g_w2l[i]);
    }
    int i3 = i - 36864;
    if (i3 >= 0 && i3 < 147456) {                      // w3: [576kp][256n]
        int kp = i3 >> 8, n = i3 & 255;
        packpair(W3[n * 1152 + 2 * kp], W3[n * 1152 + 2 * kp + 1], g_w3h[i3], g_w3l[i3]);
    }
    int i4 = i - 36864 - 147456;
    if (i4 >= 0 && i4 < 294912) {                      // w4: [1152kp][256n]
        int kp = i4 >> 8, n = i4 & 255;
        packpair(W4[n * 2304 + 2 * kp], W4[n * 2304 + 2 * kp + 1], g_w4h[i4], g_w4l[i4]);
    }
    int ia = i - 36864 - 147456 - 294912;
    if (ia >= 0 && ia < 2640000) {                     // wa: [25z][176kp][600j]
        int z = ia / 105600, r = ia % 105600;
        int kp = r / 600, j = r % 600;
        if (kp < 168) {
            const float* w = Wa + ((size_t)z * 336 + 2 * kp) * 600 + j;
            packpair(w[0], w[600], g_wah[ia], g_wal[ia]);
        } else {
            g_wah[ia] = 0u; g_wal[ia] = 0u;
        }
    }
    int ib = i - 36864 - 147456 - 294912 - 2640000;
    if (ib >= 0 && ib < 128) {
        float s = g2[ib] * rsqrtf(v2[ib] + 1e-5f);
        g_sc2[ib] = s; g_sh2[ib] = (b2[ib] - m2[ib]) * s + be2[ib];
    } else if (ib >= 128 && ib < 384) {
        int c = ib - 128;
        float s = g3[c] * rsqrtf(v3[c] + 1e-5f);
        g_sc3[c] = s; g_sh3[c] = (b3[c] - m3[c]) * s + be3[c];
    } else if (ib >= 384 && ib < 640) {
        int c = ib - 384;
        float s = g4[c] * rsqrtf(v4[c] + 1e-5f);
        g_sc4[c] = s; g_sh4[c] = (b4[c] - m4[c]) * s + be4[c];
    }
}

// ---------------------------------------------------------------------------
// conv1 + pool1 FUSED: 3 -> 64, 20x20, BN+ReLU, then maxpool 3x3 s2 p1,
// split32 out [b][64][10][10]. One block per image; co processed in groups
// of 12 via a 12x20x20 smem staging buffer (no gmem round trip for c1).
// ---------------------------------------------------------------------------
__global__ __launch_bounds__(NTHREADS) void conv1_pool_kernel(
    const float* __restrict__ x, const float* __restrict__ W,
    const float* __restrict__ bias, const float* __restrict__ gam,
    const float* __restrict__ bet, const float* __restrict__ mu,
    const float* __restrict__ var, uint32_t* __restrict__ out)
{
    __shared__ float sIn[3 * 22 * 22];
    __shared__ float sW[64 * 27];
    __shared__ float sScale[64], sShift[64];
    __shared__ float sBuf[12 * 400];
    int b = blockIdx.x, tid = threadIdx.x;

    for (int i = tid; i < 3 * 22 * 22; i += NTHREADS) sIn[i] = 0.f;
    __syncthreads();
    const float* xb = x + (size_t)b * 1200;
    for (int i = tid; i < 1200; i += NTHREADS) {
        int ci = i / 400, p = i % 400, y = p / 20, xx = p % 20;
        sIn[ci * 484 + (y + 1) * 22 + (xx + 1)] = xb[i];
    }
    for (int i = tid; i < 1728; i += NTHREADS) sW[i] = W[i];
    if (tid < 64) {
        float sc = gam[tid] * rsqrtf(var[tid] + 1e-5f);
        sScale[tid] = sc;
        sShift[tid] = (bias[tid] - mu[tid]) * sc + bet[tid];
    }
    __syncthreads();

    int colT = tid / 20, yT = tid % 20;   // compute-phase mapping (threads 240..255 idle)
    #pragma unroll 1
    for (int g = 0; g < 6; g++) {
        int coBase = g * 12;
        int nco = (coBase + 12 <= 64) ? 12 : (64 - coBase);
        if (colT < nco) {
            int co = coBase + colT;
            float scale = sScale[co], shift = sShift[co];
            float acc[20];
            #pragma unroll
            for (int xx = 0; xx < 20; xx++) acc[xx] = 0.f;
            #pragma unroll
            for (int ci = 0; ci < 3; ci++) {
                float w[9];
                #pragma unroll
                for (int k = 0; k < 9; k++) w[k] = sW[co * 27 + ci * 9 + k];
                const float* base = sIn + ci * 484 + yT * 22;
                #pragma unroll
                for (int dy = 0; dy < 3; dy++) {
                    const float* row = base + dy * 22;
                    #pragma unroll
                    for (int xx = 0; xx < 20; xx++)
                        acc[xx] += row[xx] * w[dy * 3] + row[xx + 1] * w[dy * 3 + 1]
                                 + row[xx + 2] * w[dy * 3 + 2];
                }
            }
            #pragma unroll
            for (int xx = 0; xx < 20; xx++)
                sBuf[colT * 400 + yT * 20 + xx] = fmaxf(acc[xx] * scale + shift, 0.f);
        }
        __syncthreads();
        // pool 3x3 s2 p1: 20x20 -> 10x10 per channel
        for (int i = tid; i < nco * 100; i += NTHREADS) {
            int col = i / 100, p = i % 100, oy = p / 10, ox = p % 10;
            const float* bufc = sBuf + col * 400;
            float m = -3.402823466e38f;
            #pragma unroll
            for (int dy = 0; dy < 3; dy++) {
                int iy = 2 * oy - 1 + dy;
                if (iy < 0 || iy >= 20) continue;
                #pragma unroll
                for (int dx = 0; dx < 3; dx++) {
                    int ix = 2 * ox - 1 + dx;
                    if (ix < 0 || ix >= 20) continue;
                    m = fmaxf(m, bufc[iy * 20 + ix]);
                }
            }
            out[((size_t)b * 64 + coBase + col) * 100 + p] = split32(m);
        }
        __syncthreads();
    }
}

// ---------------------------------------------------------------------------
// maxpool 3x3 s2 p1, float in -> element-split32 out (pool2)
// ---------------------------------------------------------------------------
__global__ __launch_bounds__(NTHREADS) void pool_split_kernel(
    const float* __restrict__ in, uint32_t* __restrict__ out,
    int C, int H, int OH, long long total)
{
    long long idx = (long long)blockIdx.x * NTHREADS + threadIdx.x;
    if (idx >= total) return;
    int W = H, OW = OH;
    int ox = (int)(idx % OW); long long t = idx / OW;
    int oy = (int)(t % OH);  t /= OH;
    int c  = (int)(t % C);   int b = (int)(t / C);
    const float* p = in + ((size_t)b * C + c) * H * W;
    float m = -3.402823466e38f;
    #pragma unroll
    for (int dy = 0; dy < 3; dy++) {
        int iy = 2 * oy - 1 + dy;
        if (iy < 0 || iy >= H) continue;
        #pragma unroll
        for (int dx = 0; dx < 3; dx++) {
            int ix = 2 * ox - 1 + dx;
            if (ix < 0 || ix >= W) continue;
            m = fmaxf(m, p[iy * W + ix]);
        }
    }
    out[idx] = split32(m);
}

// ---------------------------------------------------------------------------
// bf16 tensor-core GEMM, 3-product (Ah·Bh + Al·Bh + Ah·Bl) scheme.
// Tile 128x128x16, 8 warps (4x2), m16n8k16, ldmatrix fragment loads.
// Double-buffered smem (compile-time buffer offsets via unroll-by-2),
// ONE __syncthreads per k-chunk. nch guaranteed EVEN for all call sites.
// EPI: 0 float [b][128][100]; 1 split32 [b][256][25];
//      2 pair-packed feats h/l [n][b][128w]; 3 float tanh H[z][8192][600]
// ---------------------------------------------------------------------------
#define GEMM_FETCH(kc_)                                                          \
    {                                                                            \
        int kc__ = (kc_);                                                        \
        if (CC == 0) {                                                           \
            uint4 h4 = *(const uint4*)(Abh + (size_t)(mBase + lm) * aw           \
                                       + (kc__ >> 1) + (lkq >> 1));              \
            uint4 l4 = *(const uint4*)(Abl + (size_t)(mBase + lm) * aw           \
                                       + (kc__ >> 1) + (lkq >> 1));              \
            avh[0] = h4.x; avh[1] = h4.y; avh[2] = h4.z; avh[3] = h4.w;          \
            avl[0] = l4.x; avl[1] = l4.y; avl[2] = l4.z; avl[3] = l4.w;          \
        } else {                                                                 \
            uint32_t e[8];                                                       \
            _Pragma("unroll")                                                    \
            for (int j = 0; j < 8; j++) {                                        \
                int k = kc__ + lkq + j;                                          \
                int ci = k / 9, q = k - ci * 9;                                  \
                int iy = py - 1 + q / 3, ix = px - 1 + q % 3;                    \
                uint32_t v = 0u;                                                 \
                if (iy >= 0 && iy < S && ix >= 0 && ix < S)                      \
                    v = A[ib_off + ci * S * S + iy * S + ix];                    \
                e[j] = v;                                                        \
            }                                                                    \
            _Pragma("unroll")                                                    \
            for (int tt = 0; tt < 4; tt++) {                                     \
                avh[tt] = __byte_perm(e[2 * tt], e[2 * tt + 1], 0x7632);         \
                avl[tt] = __byte_perm(e[2 * tt], e[2 * tt + 1], 0x5410);         \
            }                                                                    \
        }                                                                        \
        _Pragma("unroll")                                                        \
        for (int jj = 0; jj < 4; jj++) {                                         \
            int kp = (kc__ >> 1) + (lkq >> 1) + jj;                              \
            bvh[jj] = (gn < N) ? Bbh[(size_t)kp * ldb + gn] : 0u;                \
            bvl[jj] = (gn < N) ? Bbl[(size_t)kp * ldb + gn] : 0u;                \
        }                                                                        \
    }

// store staged regs into buffer at word offset BUFW (0 or 6144)
#define GEMM_STORE(BUFW)                                                         \
    {                                                                            \
        *(uint4*)&smemAll[(BUFW) + 0    + sIdx] = make_uint4(avh[0], avh[1], avh[2], avh[3]); \
        *(uint4*)&smemAll[(BUFW) + 1536 + sIdx] = make_uint4(avl[0], avl[1], avl[2], avl[3]); \
        *(uint4*)&smemAll[(BUFW) + 3072 + sIdx] = make_uint4(bvh[0], bvh[1], bvh[2], bvh[3]); \
        *(uint4*)&smemAll[(BUFW) + 4608 + sIdx] = make_uint4(bvl[0], bvl[1], bvl[2], bvl[3]); \
    }

// compute from buffer at byte offset BUFB (0u or 24576u)
#define GEMM_COMPUTE(BUFB)                                                       \
    {                                                                            \
        uint32_t fah[2][4], fal[2][4];                                           \
        LDSM_X4(fah[0][0], fah[0][1], fah[0][2], fah[0][3], adrAh + (BUFB));     \
        LDSM_X4(fah[1][0], fah[1][1], fah[1][2], fah[1][3], adrAh + (BUFB) + 768u); \
        LDSM_X4(fal[0][0], fal[0][1], fal[0][2], fal[0][3], adrAl + (BUFB));     \
        LDSM_X4(fal[1][0], fal[1][1], fal[1][2], fal[1][3], adrAl + (BUFB) + 768u); \
        _Pragma("unroll")                                                        \
        for (int bt = 0; bt < 2; bt++) {                                         \
            uint32_t bh[8], bl[8];                                               \
            LDSM_X4(bh[0], bh[1], bh[2], bh[3], adrBh + (BUFB) + bt * 1536u);    \
            LDSM_X4(bh[4], bh[5], bh[6], bh[7], adrBh + (BUFB) + bt * 1536u + 768u); \
            LDSM_X4(bl[0], bl[1], bl[2], bl[3], adrBl + (BUFB) + bt * 1536u);    \
            LDSM_X4(bl[4], bl[5], bl[6], bl[7], adrBl + (BUFB) + bt * 1536u + 768u); \
            _Pragma("unroll")                                                    \
            for (int n4 = 0; n4 < 4; n4++) {                                     \
                int nt = bt * 4 + n4;                                            \
                uint32_t bhf[2] = { bh[n4 * 2], bh[n4 * 2 + 1] };                \
                uint32_t blf[2] = { bl[n4 * 2], bl[n4 * 2 + 1] };                \
                _Pragma("unroll")                                                \
                for (int mt = 0; mt < 2; mt++) {                                 \
                    mma16(acc[mt][nt], fah[mt], bhf);                            \
                    mma16(acc[mt][nt], fal[mt], bhf);                            \
                    mma16(acc[mt][nt], fah[mt], blf);                            \
                }                                                                \
            }                                                                    \
        }                                                                        \
    }

template <int EPI, int CC, int S>
__global__ __launch_bounds__(NTHREADS, 2) void gemm_bf16(
    const uint32_t* __restrict__ A, const uint32_t* __restrict__ A2,
    const uint32_t* __restrict__ Bh, const uint32_t* __restrict__ Bl,
    void* __restrict__ Cv, void* __restrict__ C2v,
    const float* __restrict__ sc, const float* __restrict__ sh,
    const float* __restrict__ bias,
    int K, int N, int ldb, int aw, int bStrideZ, int kpOff)
{
    // plane order (1536 words each): Ah0 Al0 Bh0 Bl0 | Ah1 Al1 Bh1 Bl1
    __shared__ uint32_t smemAll[12288];   // 48 KB

    int z = blockIdx.z;
    const uint32_t* Abh = A;
    const uint32_t* Abl = A2;
    const uint32_t* Bbh = Bh + (size_t)kpOff * ldb;
    const uint32_t* Bbl = Bl + (size_t)kpOff * ldb;
    if (EPI == 3) {
        Abh += (size_t)z * 8192 * aw;
        Abl += (size_t)z * 8192 * aw;
        Bbh += (size_t)z * bStrideZ;
        Bbl += (size_t)z * bStrideZ;
    }
    int mBase = blockIdx.y * 128, nBase = blockIdx.x * 128;
    int t = threadIdx.x, lane = t & 31, wid = t >> 5;
    int wm = (wid & 3) * 32, wn = (wid >> 2) * 64;

    int lm = t & 127, lkq = (t >> 7) * 8;
    int gn = nBase + lm;
    uint32_t sIdx = (uint32_t)(lm * 12 + (lkq >> 1));

    int ib_off = 0, py = 0, px = 0;
    if (CC > 0) {
        const int SS = S * S;
        int r = mBase + lm;
        int b = r / SS, p = r - b * SS;
        py = p / S; px = p - py * S;
        ib_off = b * CC * SS;
    }

    // ldmatrix per-lane source addresses (buffer-0 bases; buffer 1 = +24576B)
    uint32_t base_u = (uint32_t)__cvta_generic_to_shared(smemAll);
    int lt = lane >> 3, lrow = lane & 7;
    uint32_t aOff = (uint32_t)(((wm + ((lt & 1) << 3) + lrow) * 12 + ((lt >> 1) << 2)) * 4);
    uint32_t bOff = (uint32_t)(((wn + ((lt >> 1) << 3) + lrow) * 12 + ((lt & 1) << 2)) * 4);
    uint32_t adrAh = base_u + aOff;
    uint32_t adrAl = base_u + 6144u + aOff;
    uint32_t adrBh = base_u + 12288u + bOff;
    uint32_t adrBl = base_u + 18432u + bOff;

    float acc[2][8][4];
    #pragma unroll
    for (int mt = 0; mt < 2; mt++)
        #pragma unroll
        for (int nt = 0; nt < 8; nt++)
            #pragma unroll
            for (int e = 0; e < 4; e++) acc[mt][nt][e] = 0.f;

    uint32_t avh[4], avl[4], bvh[4], bvl[4];
    GEMM_FETCH(0);

    int nch = K / 16;   // even by construction at every call site
    for (int ch = 0; ch < nch; ch += 2) {
        // chunk ch -> buffer 0
        GEMM_STORE(0);
        __syncthreads();
        GEMM_FETCH((ch + 1) * 16);
        GEMM_COMPUTE(0u);
        // chunk ch+1 -> buffer 1
        GEMM_STORE(6144);
        __syncthreads();
        {
            int kcn = (ch + 2 < nch) ? (ch + 2) * 16 : 0;
            GEMM_FETCH(kcn);
        }
        GEMM_COMPUTE(24576u);
    }

    // epilogue
    int elc = lane & 3, elr = lane >> 2;
    #pragma unroll
    for (int mt = 0; mt < 2; mt++) {
        #pragma unroll
        for (int nt = 0; nt < 8; nt++) {
            if (EPI == 2) {
                #pragma unroll
                for (int rr = 0; rr < 2; rr++) {
                    int row = mBase + wm + mt * 16 + elr + rr * 8;
                    int col = nBase + wn + nt * 8 + 2 * elc;
                    float v0 = acc[mt][nt][rr * 2 + 0];
                    float v1 = acc[mt][nt][rr * 2 + 1];
                    v0 = fmaxf(v0 * sc[col] + sh[col], 0.f);
                    v1 = fmaxf(v1 * sc[col + 1] + sh[col + 1], 0.f);
                    int b = row / 25, p = row - b * 25;
                    uint32_t wh, wl;
                    packpair(v0, v1, wh, wl);
                    size_t o = ((size_t)p * 8192 + b) * 128 + (col >> 1);
                    ((uint32_t*)Cv)[o]  = wh;
                    ((uint32_t*)C2v)[o] = wl;
                }
            } else {
                #pragma unroll
                for (int e = 0; e < 4; e++) {
                    int row = mBase + wm + mt * 16 + elr + (e >> 1) * 8;
                    int col = nBase + wn + nt * 8 + 2 * elc + (e & 1);
                    float v = acc[mt][nt][e];
                    if (EPI == 0) {
                        int b = row / 100, p = row - b * 100;
                        ((float*)Cv)[((size_t)b * 128 + col) * 100 + p] =
                            fmaxf(v * sc[col] + sh[col], 0.f);
                    } else if (EPI == 1) {
                        int b = row / 25, p = row - b * 25;
                        ((uint32_t*)Cv)[((size_t)b * 256 + col) * 25 + p] =
                            split32(fmaxf(v * sc[col] + sh[col], 0.f));
                    } else {
                        if (col < N)
                            ((float*)Cv)[((size_t)z * 8192 + row) * 600 + col] =
                                tanhf(v + bias[(size_t)z * 600 + col]);
                    }
                }
            }
        }
    }
}

// ---------------------------------------------------------------------------
// GEMM2 + softmax (600 -> 10), warp per row, Wb in smem (pad 11)
// ---------------------------------------------------------------------------
__global__ __launch_bounds__(NTHREADS) void gemm2_softmax_kernel(
    const float* __restrict__ H, const float* __restrict__ Wb,
    const float* __restrict__ bb, float* __restrict__ out)
{
    __shared__ float sW[600 * 11];
    __shared__ float sb[10];
    int n = blockIdx.y, tid = threadIdx.x;
    const float* Wn = Wb + (size_t)n * 6000;
    for (int i = tid; i < 6000; i += NTHREADS) {
        int k = i / 10, c = i % 10;
        sW[k * 11 + c] = Wn[i];
    }
    if (tid < 10) sb[tid] = bb[n * 10 + tid];
    __syncthreads();

    int warp = tid >> 5, lane = tid & 31;
    int b = blockIdx.x * 8 + warp;
    const float* hr = H + ((size_t)n * 8192 + b) * 600;
    float acc[10];
    #pragma unroll
    for (int c = 0; c < 10; c++) acc[c] = 0.f;
    for (int k = lane; k < 600; k += 32) {
        float v = hr[k];
        #pragma unroll
        for (int c = 0; c < 10; c++) acc[c] += v * sW[k * 11 + c];
    }
    #pragma unroll
    for (int c = 0; c < 10; c++) {
        #pragma unroll
        for (int off = 16; off > 0; off >>= 1)
            acc[c] += __shfl_down_sync(0xffffffffu, acc[c], off);
    }
    if (lane == 0) {
        float l[10], mx = -3.402823466e38f;
        #pragma unroll
        for (int c = 0; c < 10; c++) { l[c] = acc[c] + sb[c]; mx = fmaxf(mx, l[c]); }
        float s = 0.f;
        #pragma unroll
        for (int c = 0; c < 10; c++) { l[c] = expf(l[c] - mx); s += l[c]; }
        float inv = 1.f / s;
        float* o = out + ((size_t)n * 8192 + b) * 10;
        #pragma unroll
        for (int c = 0; c < 10; c++) o[c] = l[c] * inv;
    }
}

// ---------------------------------------------------------------------------
// neighbor gather -> pair-packed in2 planes (176 words/row; 168..175 zero pad)
// ---------------------------------------------------------------------------
__device__ __forceinline__ int nei_of(int i, int slot)
{
    int nb[8];
    #pragma unroll
    for (int t = 0; t < 8; t++) nb[t] = -1;
    int cnt = 0;
    bool l = (i % 5 != 0), r = ((i + 1) % 5 != 0), u = (i >= 5), d = (i + 5 < 25);
    if (u)      nb[cnt++] = i - 5;
    if (l)      nb[cnt++] = i - 1;
    if (r)      nb[cnt++] = i + 1;
    if (d)      nb[cnt++] = i + 5;
    if (u && l) nb[cnt++] = i - 6;
    if (u && r) nb[cnt++] = i - 4;
    if (d && l) nb[cnt++] = i + 4;
    if (d && r) nb[cnt++] = i + 6;
    return nb[slot];
}

__global__ __launch_bounds__(NTHREADS) void gather_kernel(
    const float* __restrict__ preds,
    const uint32_t* __restrict__ fh, const uint32_t* __restrict__ fl,
    uint32_t* __restrict__ ih, uint32_t* __restrict__ il)
{
    long long idx = (long long)blockIdx.x * NTHREADS + threadIdx.x;
    if (idx >= 25LL * 8192 * 176) return;
    int j = (int)(idx % 176);
    long long t = idx / 176;
    int b = (int)(t % 8192);
    int n = (int)(t / 8192);
    uint32_t wh = 0u, wl = 0u;
    if (j >= 168) {
        // zero pad
    } else if (j >= 40) {
        size_t src = ((size_t)n * 8192 + b) * 128 + (j - 40);
        wh = fh[src]; wl = fl[src];
    } else {
        int c0 = (2 * j) % 10, s = (2 * j) / 10;
        int nei = nei_of(n, s);
        float p0 = 0.f, p1 = 0.f;
        if (nei >= 0) {
            const float* pp = preds + ((size_t)nei * 8192 + b) * 10 + c0;
            p0 = pp[0]; p1 = pp[1];
        }
        packpair(p0, p1, wh, wl);
    }
    ih[idx] = wh;
    il[idx] = wl;
}

__global__ __launch_bounds__(NTHREADS) void mean_kernel(
    const float* __restrict__ second, float* __restrict__ mean)
{
    int idx = blockIdx.x * NTHREADS + threadIdx.x;
    if (idx >= 81920) return;
    float s = 0.f;
    #pragma unroll
    for (int n = 0; n < 25; n++) s += second[(size_t)n * 81920 + idx];
    mean[idx] = s * 0.04f;
}

// ---------------------------------------------------------------------------
// launch
// ---------------------------------------------------------------------------
extern "C" void kernel_launch(void* const* d_in, const int* in_sizes, int n_in,
                              void* d_out, int out_size)
{
    (void)in_sizes; (void)n_in; (void)out_size;
    float* arena = nullptr;
    uint32_t *w2h, *w2l, *w3h, *w3l, *w4h, *w4l, *wah, *wal;
    float *sc2, *sh2, *sc3, *sh3, *sc4, *sh4;
    cudaGetSymbolAddress((void**)&arena, g_arena);
    cudaGetSymbolAddress((void**)&w2h, g_w2h);  cudaGetSymbolAddress((void**)&w2l, g_w2l);
    cudaGetSymbolAddress((void**)&w3h, g_w3h);  cudaGetSymbolAddress((void**)&w3l, g_w3l);
    cudaGetSymbolAddress((void**)&w4h, g_w4h);  cudaGetSymbolAddress((void**)&w4l, g_w4l);
    cudaGetSymbolAddress((void**)&wah, g_wah);  cudaGetSymbolAddress((void**)&wal, g_wal);
    cudaGetSymbolAddress((void**)&sc2, g_sc2);  cudaGetSymbolAddress((void**)&sh2, g_sh2);
    cudaGetSymbolAddress((void**)&sc3, g_sc3);  cudaGetSymbolAddress((void**)&sh3, g_sh3);
    cudaGetSymbolAddress((void**)&sc4, g_sc4);  cudaGetSymbolAddress((void**)&sh4, g_sh4);
    uint32_t* arenau = (uint32_t*)arena;

    const float* x   = (const float*)d_in[0];
    const float* W1  = (const float*)d_in[1];
    const float* b1  = (const float*)d_in[2];
    const float* g1  = (const float*)d_in[3];
    const float* be1 = (const float*)d_in[4];
    const float* m1  = (const float*)d_in[5];
    const float* v1  = (const float*)d_in[6];
    const float* W2  = (const float*)d_in[7];
    const float* b2  = (const float*)d_in[8];
    const float* g2  = (const float*)d_in[9];
    const float* be2 = (const float*)d_in[10];
    const float* m2  = (const float*)d_in[11];
    const float* v2  = (const float*)d_in[12];
    const float* W3  = (const float*)d_in[13];
    const float* b3  = (const float*)d_in[14];
    const float* g3  = (const float*)d_in[15];
    const float* be3 = (const float*)d_in[16];
    const float* m3  = (const float*)d_in[17];
    const float* v3  = (const float*)d_in[18];
    const float* W4  = (const float*)d_in[19];
    const float* b4  = (const float*)d_in[20];
    const float* g4  = (const float*)d_in[21];
    const float* be4 = (const float*)d_in[22];
    const float* m4  = (const float*)d_in[23];
    const float* v4  = (const float*)d_in[24];
    const float* Wa  = (const float*)d_in[25];
    const float* ba  = (const float*)d_in[26];
    const float* Wb  = (const float*)d_in[27];
    const float* bb  = (const float*)d_in[28];
    float* out = (float*)d_out;

    // prep: weight splits + BN folds (3,119,872 work items)
    prep_kernel<<<12187, NTHREADS>>>(W2, W3, W4, Wa,
        b2, g2, be2, m2, v2, b3, g3, be3, m3, v3, b4, g4, be4, m4, v4);

    // conv1 + pool1 FUSED -> split32 p1 (no c1 gmem round trip)
    conv1_pool_kernel<<<BATCH, NTHREADS>>>(x, W1, b1, g1, be1, m1, v1,
                                           arenau + OFF_P1);
    // conv2: implicit-im2col bf16 GEMM (K=576, nch=36) -> float c2
    gemm_bf16<0, 64, 10><<<dim3(1, 6400, 1), NTHREADS>>>(
        arenau + OFF_P1, nullptr, w2h, w2l, arena + OFF_C2, nullptr,
        sc2, sh2, nullptr, 576, 128, 128, 0, 0, 0);
    // pool2 (split32)
    {
        long long total = (long long)BATCH * 128 * 25;
        pool_split_kernel<<<(int)((total + NTHREADS - 1) / NTHREADS), NTHREADS>>>(
            arena + OFF_C2, arenau + OFF_P2, 128, 10, 5, total);
    }
    // conv3 (K=1152, nch=72) -> split32 c3
    gemm_bf16<1, 128, 5><<<dim3(2, 1600, 1), NTHREADS>>>(
        arenau + OFF_P2, nullptr, w3h, w3l, arenau + OFF_C3, nullptr,
        sc3, sh3, nullptr, 1152, 256, 256, 0, 0, 0);
    // conv4 (K=2304, nch=144) -> pair-packed feats h/l
    gemm_bf16<2, 256, 5><<<dim3(2, 1600, 1), NTHREADS>>>(
        arenau + OFF_C3, nullptr, w4h, w4l,
        arenau + OFF_FEATS_H, arenau + OFF_FEATS_L,
        sc4, sh4, nullptr, 2304, 256, 256, 0, 0, 0);
    // stage 1 MLP (K=256, nch=16, Wa rows 80:336 -> kpOff=40) -> float H
    gemm_bf16<3, 0, 0><<<dim3(5, 64, 25), NTHREADS>>>(
        arenau + OFF_FEATS_H, arenau + OFF_FEATS_L, wah, wal,
        arena + OFF_H, nullptr, nullptr, nullptr, ba,
        256, 600, 600, 128, 105600, 40);
    gemm2_softmax_kernel<<<dim3(1024, 25), NTHREADS>>>(arena + OFF_H, Wb, bb,
                                                       arena + OFF_PREDS);
    // gather -> pair-packed in2 h/l (176 words/row, zero pad)
    {
        long long total = 25LL * 8192 * 176;
        gather_kernel<<<(int)((total + NTHREADS - 1) / NTHREADS), NTHREADS>>>(
            arena + OFF_PREDS, arenau + OFF_FEATS_H, arenau + OFF_FEATS_L,
            arenau + OFF_IN2_H, arenau + OFF_IN2_L);
    }
    // stage 2 MLP (K padded 336->352, nch=22)
    gemm_bf16<3, 0, 0><<<dim3(5, 64, 25), NTHREADS>>>(
        arenau + OFF_IN2_H, arenau + OFF_IN2_L, wah, wal,
        arena + OFF_H, nullptr, nullptr, nullptr, ba,
        352, 600, 600, 176, 105600, 0);
    gemm2_softmax_kernel<<<dim3(1024, 25), NTHREADS>>>(arena + OFF_H, Wb, bb,
                                                       out + 81920);
    mean_kernel<<<320, NTHREADS>>>(out + 81920, out);
}

// round 16
// speedup vs baseline: 1.5328x; 1.0475x over previous
#include <cuda_runtime.h>
#include <cstdint>
#include <cstddef>

#define NTHREADS 256
#define BATCH 8192

// ---------------------------------------------------------------------------
// Scratch arena (word offsets, 4B words; lifetimes verified):
//  p1    [209715200, 262144000)    split32 pool1 out [b][64][10][10]
//  c2    [0, 104857600)            float   conv2 out [b][128][10][10]
//  p2    [104857600, 131072000)    split32 pool2 out
//  c3    [131072000, 183500800)    split32 conv3 out [b][256][5][5]
//  featsH[0, 26214400) featsL[26214400, 52428800)  pair-packed [25][8192][128w]
//  H     [52428800, 175308800)     float   [25][8192][600]
//  preds [183500800, 185548800)    float   [25][8192][10]
//  in2H  [185548800, 221593600) in2L [221593600, 257638400) [25][8192][176w]
// ---------------------------------------------------------------------------
__device__ float g_arena[262144000];     // 1.049 GB

static const size_t OFF_P1      = 209715200;
static const size_t OFF_C2      = 0;
static const size_t OFF_P2      = 104857600;
static const size_t OFF_C3      = 131072000;
static const size_t OFF_FEATS_H = 0;
static const size_t OFF_FEATS_L = 26214400;
static const size_t OFF_H       = 52428800;
static const size_t OFF_PREDS   = 183500800;
static const size_t OFF_IN2_H   = 185548800;
static const size_t OFF_IN2_L   = 221593600;

// pre-split weight planes, pair-packed along k: word(kp,n) = bf16(k=2kp+1)<<16 | bf16(k=2kp)
// wa planes padded to 176 kp-rows per node (rows 168..175 are zero) so MLP2 K=352 (even chunks)
__device__ uint32_t g_w2h[288 * 128],  g_w2l[288 * 128];
__device__ uint32_t g_w3h[576 * 256],  g_w3l[576 * 256];
__device__ uint32_t g_w4h[1152 * 256], g_w4l[1152 * 256];
__device__ uint32_t g_wah[25 * 176 * 600], g_wal[25 * 176 * 600];
__device__ float g_sc2[128], g_sh2[128];
__device__ float g_sc3[256], g_sh3[256];
__device__ float g_sc4[256], g_sh4[256];

// ---------------------------------------------------------------------------
// bf16 helpers
// ---------------------------------------------------------------------------
__device__ __forceinline__ uint32_t f2bf(float x)
{
    unsigned short h;
    asm("cvt.rn.bf16.f32 %0, %1;" : "=h"(h) : "f"(x));
    return (uint32_t)h;
}

// element-split32: hi bf16 in high halfword, lo bf16 in low halfword
__device__ __forceinline__ uint32_t split32(float x)
{
    uint32_t hb = f2bf(x);
    float r = x - __uint_as_float(hb << 16);
    uint32_t lb = f2bf(r);
    return (hb << 16) | lb;
}

// pair-pack two floats into (h-plane word, l-plane word)
__device__ __forceinline__ void packpair(float x0, float x1, uint32_t& wh, uint32_t& wl)
{
    uint32_t s0 = split32(x0), s1 = split32(x1);
    wh = __byte_perm(s0, s1, 0x7632);   // [s0.hi16, s1.hi16]
    wl = __byte_perm(s0, s1, 0x5410);   // [s0.lo16, s1.lo16]
}

__device__ __forceinline__ void mma16(float d[4], const uint32_t a[4], const uint32_t b[2])
{
    asm volatile(
        "mma.sync.aligned.m16n8k16.row.col.f32.bf16.bf16.f32 "
        "{%0,%1,%2,%3}, {%4,%5,%6,%7}, {%8,%9}, {%0,%1,%2,%3};\n"
        : "+f"(d[0]), "+f"(d[1]), "+f"(d[2]), "+f"(d[3])
        : "r"(a[0]), "r"(a[1]), "r"(a[2]), "r"(a[3]), "r"(b[0]), "r"(b[1]));
}

#define LDSM_X4(r0, r1, r2, r3, addr)                                            \
    asm volatile("ldmatrix.sync.aligned.m8n8.x4.shared.b16 {%0,%1,%2,%3}, [%4];" \
                 : "=r"(r0), "=r"(r1), "=r"(r2), "=r"(r3) : "r"(addr))

// ---------------------------------------------------------------------------
// prep: split+pack weights into bf16 planes + BN folds
// ---------------------------------------------------------------------------
__global__ __launch_bounds__(NTHREADS) void prep_kernel(
    const float* __restrict__ W2, const float* __restrict__ W3,
    const float* __restrict__ W4, const float* __restrict__ Wa,
    const float* __restrict__ b2, const float* __restrict__ g2, const float* __restrict__ be2,
    const float* __restrict__ m2, const float* __restrict__ v2,
    const float* __restrict__ b3, const float* __restrict__ g3, const float* __restrict__ be3,
    const float* __restrict__ m3, const float* __restrict__ v3,
    const float* __restrict__ b4, const float* __restrict__ g4, const float* __restrict__ be4,
    const float* __restrict__ m4, const float* __restrict__ v4)
{
    int i = blockIdx.x * NTHREADS + threadIdx.x;
    if (i < 36864) {                                   // w2: [288kp][128n]
        int kp = i >> 7, n = i & 127;
        packpair(W2[n * 576 + 2 * kp], W2[n * 576 + 2 * kp + 1], g_w2h[i], g_w2l[i]);
    }
    int i3 = i - 36864;
    if (i3 >= 0 && i3 < 147456) {                      // w3: [576kp][256n]
        int kp = i3 >> 8, n = i3 & 255;
        packpair(W3[n * 1152 + 2 * kp], W3[n * 1152 + 2 * kp + 1], g_w3h[i3], g_w3l[i3]);
    }
    int i4 = i - 36864 - 147456;
    if (i4 >= 0 && i4 < 294912) {                      // w4: [1152kp][256n]
        int kp = i4 >> 8, n = i4 & 255;
        packpair(W4[n * 2304 + 2 * kp], W4[n * 2304 + 2 * kp + 1], g_w4h[i4], g_w4l[i4]);
    }
    int ia = i - 36864 - 147456 - 294912;
    if (ia >= 0 && ia < 2640000) {                     // wa: [25z][176kp][600j]
        int z = ia / 105600, r = ia % 105600;
        int kp = r / 600, j = r % 600;
        if (kp < 168) {
            const float* w = Wa + ((size_t)z * 336 + 2 * kp) * 600 + j;
            packpair(w[0], w[600], g_wah[ia], g_wal[ia]);
        } else {
            g_wah[ia] = 0u; g_wal[ia] = 0u;
        }
    }
    int ib = i - 36864 - 147456 - 294912 - 2640000;
    if (ib >= 0 && ib < 128) {
        float s = g2[ib] * rsqrtf(v2[ib] + 1e-5f);
        g_sc2[ib] = s; g_sh2[ib] = (b2[ib] - m2[ib]) * s + be2[ib];
    } else if (ib >= 128 && ib < 384) {
        int c = ib - 128;
        float s = g3[c] * rsqrtf(v3[c] + 1e-5f);
        g_sc3[c] = s; g_sh3[c] = (b3[c] - m3[c]) * s + be3[c];
    } else if (ib >= 384 && ib < 640) {
        int c = ib - 384;
        float s = g4[c] * rsqrtf(v4[c] + 1e-5f);
        g_sc4[c] = s; g_sh4[c] = (b4[c] - m4[c]) * s + be4[c];
    }
}

// ---------------------------------------------------------------------------
// conv1 + pool1 FUSED: 3 -> 64, 20x20, BN+ReLU, then maxpool 3x3 s2 p1,
// split32 out [b][64][10][10]. One block per image; co processed in groups
// of 12 via a 12x20x20 smem staging buffer (no gmem round trip for c1).
// ---------------------------------------------------------------------------
__global__ __launch_bounds__(NTHREADS) void conv1_pool_kernel(
    const float* __restrict__ x, const float* __restrict__ W,
    const float* __restrict__ bias, const float* __restrict__ gam,
    const float* __restrict__ bet, const float* __restrict__ mu,
    const float* __restrict__ var, uint32_t* __restrict__ out)
{
    __shared__ float sIn[3 * 22 * 22];
    __shared__ float sW[64 * 27];
    __shared__ float sScale[64], sShift[64];
    __shared__ float sBuf[12 * 400];
    int b = blockIdx.x, tid = threadIdx.x;

    for (int i = tid; i < 3 * 22 * 22; i += NTHREADS) sIn[i] = 0.f;
    __syncthreads();
    const float* xb = x + (size_t)b * 1200;
    for (int i = tid; i < 1200; i += NTHREADS) {
        int ci = i / 400, p = i % 400, y = p / 20, xx = p % 20;
        sIn[ci * 484 + (y + 1) * 22 + (xx + 1)] = xb[i];
    }
    for (int i = tid; i < 1728; i += NTHREADS) sW[i] = W[i];
    if (tid < 64) {
        float sc = gam[tid] * rsqrtf(var[tid] + 1e-5f);
        sScale[tid] = sc;
        sShift[tid] = (bias[tid] - mu[tid]) * sc + bet[tid];
    }
    __syncthreads();

    int colT = tid / 20, yT = tid % 20;   // compute-phase mapping (threads 240..255 idle)
    #pragma unroll 1
    for (int g = 0; g < 6; g++) {
        int coBase = g * 12;
        int nco = (coBase + 12 <= 64) ? 12 : (64 - coBase);
        if (colT < nco) {
            int co = coBase + colT;
            float scale = sScale[co], shift = sShift[co];
            float acc[20];
            #pragma unroll
            for (int xx = 0; xx < 20; xx++) acc[xx] = 0.f;
            #pragma unroll
            for (int ci = 0; ci < 3; ci++) {
                float w[9];
                #pragma unroll
                for (int k = 0; k < 9; k++) w[k] = sW[co * 27 + ci * 9 + k];
                const float* base = sIn + ci * 484 + yT * 22;
                #pragma unroll
                for (int dy = 0; dy < 3; dy++) {
                    const float* row = base + dy * 22;
                    #pragma unroll
                    for (int xx = 0; xx < 20; xx++)
                        acc[xx] += row[xx] * w[dy * 3] + row[xx + 1] * w[dy * 3 + 1]
                                 + row[xx + 2] * w[dy * 3 + 2];
                }
            }
            #pragma unroll
            for (int xx = 0; xx < 20; xx++)
                sBuf[colT * 400 + yT * 20 + xx] = fmaxf(acc[xx] * scale + shift, 0.f);
        }
        __syncthreads();
        // pool 3x3 s2 p1: 20x20 -> 10x10 per channel
        for (int i = tid; i < nco * 100; i += NTHREADS) {
            int col = i / 100, p = i % 100, oy = p / 10, ox = p % 10;
            const float* bufc = sBuf + col * 400;
            float m = -3.402823466e38f;
            #pragma unroll
            for (int dy = 0; dy < 3; dy++) {
                int iy = 2 * oy - 1 + dy;
                if (iy < 0 || iy >= 20) continue;
                #pragma unroll
                for (int dx = 0; dx < 3; dx++) {
                    int ix = 2 * ox - 1 + dx;
                    if (ix < 0 || ix >= 20) continue;
                    m = fmaxf(m, bufc[iy * 20 + ix]);
                }
            }
            out[((size_t)b * 64 + coBase + col) * 100 + p] = split32(m);
        }
        __syncthreads();
    }
}

// ---------------------------------------------------------------------------
// pool2: maxpool 3x3 s2 p1 over 10x10 planes, float in -> split32 out.
// Block-tiled: 256 threads load 64 contiguous (b,c) planes (6400 floats,
// fully coalesced) into smem, pool from smem, coalesced word writes.
// grid = 8192*128/64 = 16384 blocks.
// ---------------------------------------------------------------------------
__global__ __launch_bounds__(NTHREADS) void pool2_kernel(
    const float* __restrict__ in, uint32_t* __restrict__ out)
{
    __shared__ float s[64 * 100];
    int blk = blockIdx.x, tid = threadIdx.x;
    size_t base = (size_t)blk * 6400;
    for (int i = tid; i < 6400; i += NTHREADS)
        s[i] = in[base + i];
    __syncthreads();
    size_t obase = (size_t)blk * 1600;
    for (int i = tid; i < 1600; i += NTHREADS) {
        int pl = i / 25, p = i % 25, oy = p / 5, ox = p % 5;
        const float* sp = s + pl * 100;
        float m = -3.402823466e38f;
        #pragma unroll
        for (int dy = 0; dy < 3; dy++) {
            int iy = 2 * oy - 1 + dy;
            if (iy < 0 || iy >= 10) continue;
            #pragma unroll
            for (int dx = 0; dx < 3; dx++) {
                int ix = 2 * ox - 1 + dx;
                if (ix < 0 || ix >= 10) continue;
                m = fmaxf(m, sp[iy * 10 + ix]);
            }
        }
        out[obase + i] = split32(m);
    }
}

// ---------------------------------------------------------------------------
// bf16 tensor-core GEMM, 3-product (Ah·Bh + Al·Bh + Ah·Bl) scheme.
// Tile 128x128x16, 8 warps (4x2), m16n8k16, ldmatrix fragment loads.
// Double-buffered smem (compile-time buffer offsets via unroll-by-2),
// ONE __syncthreads per k-chunk. nch guaranteed EVEN for all call sites.
// im2col decode is incremental (no per-element /9).
// EPI: 0 float [b][128][100]; 1 split32 [b][256][25];
//      2 pair-packed feats h/l [n][b][128w]; 3 float tanh H[z][8192][600]
// ---------------------------------------------------------------------------
#define GEMM_FETCH(kc_)                                                          \
    {                                                                            \
        int kc__ = (kc_);                                                        \
        if (CC == 0) {                                                           \
            uint4 h4 = *(const uint4*)(Abh + (size_t)(mBase + lm) * aw           \
                                       + (kc__ >> 1) + (lkq >> 1));              \
            uint4 l4 = *(const uint4*)(Abl + (size_t)(mBase + lm) * aw           \
                                       + (kc__ >> 1) + (lkq >> 1));              \
            avh[0] = h4.x; avh[1] = h4.y; avh[2] = h4.z; avh[3] = h4.w;          \
            avl[0] = l4.x; avl[1] = l4.y; avl[2] = l4.z; avl[3] = l4.w;          \
        } else {                                                                 \
            uint32_t e[8];                                                       \
            int k0__ = kc__ + lkq;                                               \
            int ci__ = k0__ / 9;                                                 \
            int q__  = k0__ - ci__ * 9;                                          \
            _Pragma("unroll")                                                    \
            for (int j = 0; j < 8; j++) {                                        \
                int qy = (q__ * 11) >> 5, qx = q__ - qy * 3;                     \
                int iy = py - 1 + qy, ix = px - 1 + qx;                          \
                uint32_t v = 0u;                                                 \
                if (iy >= 0 && iy < S && ix >= 0 && ix < S)                      \
                    v = A[ib_off + ci__ * S * S + iy * S + ix];                  \
                e[j] = v;                                                        \
                q__++;                                                           \
                if (q__ == 9) { q__ = 0; ci__++; }                               \
            }                                                                    \
            _Pragma("unroll")                                                    \
            for (int tt = 0; tt < 4; tt++) {                                     \
                avh[tt] = __byte_perm(e[2 * tt], e[2 * tt + 1], 0x7632);         \
                avl[tt] = __byte_perm(e[2 * tt], e[2 * tt + 1], 0x5410);         \
            }                                                                    \
        }                                                                        \
        _Pragma("unroll")                                                        \
        for (int jj = 0; jj < 4; jj++) {                                         \
            int kp = (kc__ >> 1) + (lkq >> 1) + jj;                              \
            bvh[jj] = (gn < N) ? Bbh[(size_t)kp * ldb + gn] : 0u;                \
            bvl[jj] = (gn < N) ? Bbl[(size_t)kp * ldb + gn] : 0u;                \
        }                                                                        \
    }

// store staged regs into buffer at word offset BUFW (0 or 6144)
#define GEMM_STORE(BUFW)                                                         \
    {                                                                            \
        *(uint4*)&smemAll[(BUFW) + 0    + sIdx] = make_uint4(avh[0], avh[1], avh[2], avh[3]); \
        *(uint4*)&smemAll[(BUFW) + 1536 + sIdx] = make_uint4(avl[0], avl[1], avl[2], avl[3]); \
        *(uint4*)&smemAll[(BUFW) + 3072 + sIdx] = make_uint4(bvh[0], bvh[1], bvh[2], bvh[3]); \
        *(uint4*)&smemAll[(BUFW) + 4608 + sIdx] = make_uint4(bvl[0], bvl[1], bvl[2], bvl[3]); \
    }

// compute from buffer at byte offset BUFB (0u or 24576u)
#define GEMM_COMPUTE(BUFB)                                                       \
    {                                                                            \
        uint32_t fah[2][4], fal[2][4];                                           \
        LDSM_X4(fah[0][0], fah[0][1], fah[0][2], fah[0][3], adrAh + (BUFB));     \
        LDSM_X4(fah[1][0], fah[1][1], fah[1][2], fah[1][3], adrAh + (BUFB) + 768u); \
        LDSM_X4(fal[0][0], fal[0][1], fal[0][2], fal[0][3], adrAl + (BUFB));     \
        LDSM_X4(fal[1][0], fal[1][1], fal[1][2], fal[1][3], adrAl + (BUFB) + 768u); \
        _Pragma("unroll")                                                        \
        for (int bt = 0; bt < 2; bt++) {                                         \
            uint32_t bh[8], bl[8];                                               \
            LDSM_X4(bh[0], bh[1], bh[2], bh[3], adrBh + (BUFB) + bt * 1536u);    \
            LDSM_X4(bh[4], bh[5], bh[6], bh[7], adrBh + (BUFB) + bt * 1536u + 768u); \
            LDSM_X4(bl[0], bl[1], bl[2], bl[3], adrBl + (BUFB) + bt * 1536u);    \
            LDSM_X4(bl[4], bl[5], bl[6], bl[7], adrBl + (BUFB) + bt * 1536u + 768u); \
            _Pragma("unroll")                                                    \
            for (int n4 = 0; n4 < 4; n4++) {                                     \
                int nt = bt * 4 + n4;                                            \
                uint32_t bhf[2] = { bh[n4 * 2], bh[n4 * 2 + 1] };                \
                uint32_t blf[2] = { bl[n4 * 2], bl[n4 * 2 + 1] };                \
                _Pragma("unroll")                                                \
                for (int mt = 0; mt < 2; mt++) {                                 \
                    mma16(acc[mt][nt], fah[mt], bhf);                            \
                    mma16(acc[mt][nt], fal[mt], bhf);                            \
                    mma16(acc[mt][nt], fah[mt], blf);                            \
                }                                                                \
            }                                                                    \
        }                                                                        \
    }

template <int EPI, int CC, int S>
__global__ __launch_bounds__(NTHREADS, 2) void gemm_bf16(
    const uint32_t* __restrict__ A, const uint32_t* __restrict__ A2,
    const uint32_t* __restrict__ Bh, const uint32_t* __restrict__ Bl,
    void* __restrict__ Cv, void* __restrict__ C2v,
    const float* __restrict__ sc, const float* __restrict__ sh,
    const float* __restrict__ bias,
    int K, int N, int ldb, int aw, int bStrideZ, int kpOff)
{
    // plane order (1536 words each): Ah0 Al0 Bh0 Bl0 | Ah1 Al1 Bh1 Bl1
    __shared__ uint32_t smemAll[12288];   // 48 KB

    int z = blockIdx.z;
    const uint32_t* Abh = A;
    const uint32_t* Abl = A2;
    const uint32_t* Bbh = Bh + (size_t)kpOff * ldb;
    const uint32_t* Bbl = Bl + (size_t)kpOff * ldb;
    if (EPI == 3) {
        Abh += (size_t)z * 8192 * aw;
        Abl += (size_t)z * 8192 * aw;
        Bbh += (size_t)z * bStrideZ;
        Bbl += (size_t)z * bStrideZ;
    }
    int mBase = blockIdx.y * 128, nBase = blockIdx.x * 128;
    int t = threadIdx.x, lane = t & 31, wid = t >> 5;
    int wm = (wid & 3) * 32, wn = (wid >> 2) * 64;

    int lm = t & 127, lkq = (t >> 7) * 8;
    int gn = nBase + lm;
    uint32_t sIdx = (uint32_t)(lm * 12 + (lkq >> 1));

    int ib_off = 0, py = 0, px = 0;
    if (CC > 0) {
        const int SS = S * S;
        int r = mBase + lm;
        int b = r / SS, p = r - b * SS;
        py = p / S; px = p - py * S;
        ib_off = b * CC * SS;
    }

    // ldmatrix per-lane source addresses (buffer-0 bases; buffer 1 = +24576B)
    uint32_t base_u = (uint32_t)__cvta_generic_to_shared(smemAll);
    int lt = lane >> 3, lrow = lane & 7;
    uint32_t aOff = (uint32_t)(((wm + ((lt & 1) << 3) + lrow) * 12 + ((lt >> 1) << 2)) * 4);
    uint32_t bOff = (uint32_t)(((wn + ((lt >> 1) << 3) + lrow) * 12 + ((lt & 1) << 2)) * 4);
    uint32_t adrAh = base_u + aOff;
    uint32_t adrAl = base_u + 6144u + aOff;
    uint32_t adrBh = base_u + 12288u + bOff;
    uint32_t adrBl = base_u + 18432u + bOff;

    float acc[2][8][4];
    #pragma unroll
    for (int mt = 0; mt < 2; mt++)
        #pragma unroll
        for (int nt = 0; nt < 8; nt++)
            #pragma unroll
            for (int e = 0; e < 4; e++) acc[mt][nt][e] = 0.f;

    uint32_t avh[4], avl[4], bvh[4], bvl[4];
    GEMM_FETCH(0);

    int nch = K / 16;   // even by construction at every call site
    for (int ch = 0; ch < nch; ch += 2) {
        // chunk ch -> buffer 0
        GEMM_STORE(0);
        __syncthreads();
        GEMM_FETCH((ch + 1) * 16);
        GEMM_COMPUTE(0u);
        // chunk ch+1 -> buffer 1
        GEMM_STORE(6144);
        __syncthreads();
        {
            int kcn = (ch + 2 < nch) ? (ch + 2) * 16 : 0;
            GEMM_FETCH(kcn);
        }
        GEMM_COMPUTE(24576u);
    }

    // epilogue
    int elc = lane & 3, elr = lane >> 2;
    #pragma unroll
    for (int mt = 0; mt < 2; mt++) {
        #pragma unroll
        for (int nt = 0; nt < 8; nt++) {
            if (EPI == 2) {
                #pragma unroll
                for (int rr = 0; rr < 2; rr++) {
                    int row = mBase + wm + mt * 16 + elr + rr * 8;
                    int col = nBase + wn + nt * 8 + 2 * elc;
                    float v0 = acc[mt][nt][rr * 2 + 0];
                    float v1 = acc[mt][nt][rr * 2 + 1];
                    v0 = fmaxf(v0 * sc[col] + sh[col], 0.f);
                    v1 = fmaxf(v1 * sc[col + 1] + sh[col + 1], 0.f);
                    int b = row / 25, p = row - b * 25;
                    uint32_t wh, wl;
                    packpair(v0, v1, wh, wl);
                    size_t o = ((size_t)p * 8192 + b) * 128 + (col >> 1);
                    ((uint32_t*)Cv)[o]  = wh;
                    ((uint32_t*)C2v)[o] = wl;
                }
            } else {
                #pragma unroll
                for (int e = 0; e < 4; e++) {
                    int row = mBase + wm + mt * 16 + elr + (e >> 1) * 8;
                    int col = nBase + wn + nt * 8 + 2 * elc + (e & 1);
                    float v = acc[mt][nt][e];
                    if (EPI == 0) {
                        int b = row / 100, p = row - b * 100;
                        ((float*)Cv)[((size_t)b * 128 + col) * 100 + p] =
                            fmaxf(v * sc[col] + sh[col], 0.f);
                    } else if (EPI == 1) {
                        int b = row / 25, p = row - b * 25;
                        ((uint32_t*)Cv)[((size_t)b * 256 + col) * 25 + p] =
                            split32(fmaxf(v * sc[col] + sh[col], 0.f));
                    } else {
                        if (col < N)
                            ((float*)Cv)[((size_t)z * 8192 + row) * 600 + col] =
                                tanhf(v + bias[(size_t)z * 600 + col]);
                    }
                }
            }
        }
    }
}

// ---------------------------------------------------------------------------
// GEMM2 + softmax (600 -> 10), warp per row, Wb in smem (pad 11)
// ---------------------------------------------------------------------------
__global__ __launch_bounds__(NTHREADS) void gemm2_softmax_kernel(
    const float* __restrict__ H, const float* __restrict__ Wb,
    const float* __restrict__ bb, float* __restrict__ out)
{
    __shared__ float sW[600 * 11];
    __shared__ float sb[10];
    int n = blockIdx.y, tid = threadIdx.x;
    const float* Wn = Wb + (size_t)n * 6000;
    for (int i = tid; i < 6000; i += NTHREADS) {
        int k = i / 10, c = i % 10;
        sW[k * 11 + c] = Wn[i];
    }
    if (tid < 10) sb[tid] = bb[n * 10 + tid];
    __syncthreads();

    int warp = tid >> 5, lane = tid & 31;
    int b = blockIdx.x * 8 + warp;
    const float* hr = H + ((size_t)n * 8192 + b) * 600;
    float acc[10];
    #pragma unroll
    for (int c = 0; c < 10; c++) acc[c] = 0.f;
    for (int k = lane; k < 600; k += 32) {
        float v = hr[k];
        #pragma unroll
        for (int c = 0; c < 10; c++) acc[c] += v * sW[k * 11 + c];
    }
    #pragma unroll
    for (int c = 0; c < 10; c++) {
        #pragma unroll
        for (int off = 16; off > 0; off >>= 1)
            acc[c] += __shfl_down_sync(0xffffffffu, acc[c], off);
    }
    if (lane == 0) {
        float l[10], mx = -3.402823466e38f;
        #pragma unroll
        for (int c = 0; c < 10; c++) { l[c] = acc[c] + sb[c]; mx = fmaxf(mx, l[c]); }
        float s = 0.f;
        #pragma unroll
        for (int c = 0; c < 10; c++) { l[c] = expf(l[c] - mx); s += l[c]; }
        float inv = 1.f / s;
        float* o = out + ((size_t)n * 8192 + b) * 10;
        #pragma unroll
        for (int c = 0; c < 10; c++) o[c] = l[c] * inv;
    }
}

// ---------------------------------------------------------------------------
// neighbor gather -> pair-packed in2 planes (176 words/row; 168..175 zero pad)
// ---------------------------------------------------------------------------
__device__ __forceinline__ int nei_of(int i, int slot)
{
    int nb[8];
    #pragma unroll
    for (int t = 0; t < 8; t++) nb[t] = -1;
    int cnt = 0;
    bool l = (i % 5 != 0), r = ((i + 1) % 5 != 0), u = (i >= 5), d = (i + 5 < 25);
    if (u)      nb[cnt++] = i - 5;
    if (l)      nb[cnt++] = i - 1;
    if (r)      nb[cnt++] = i + 1;
    if (d)      nb[cnt++] = i + 5;
    if (u && l) nb[cnt++] = i - 6;
    if (u && r) nb[cnt++] = i - 4;
    if (d && l) nb[cnt++] = i + 4;
    if (d && r) nb[cnt++] = i + 6;
    return nb[slot];
}

__global__ __launch_bounds__(NTHREADS) void gather_kernel(
    const float* __restrict__ preds,
    const uint32_t* __restrict__ fh, const uint32_t* __restrict__ fl,
    uint32_t* __restrict__ ih, uint32_t* __restrict__ il)
{
    long long idx = (long long)blockIdx.x * NTHREADS + threadIdx.x;
    if (idx >= 25LL * 8192 * 176) return;
    int j = (int)(idx % 176);
    long long t = idx / 176;
    int b = (int)(t % 8192);
    int n = (int)(t / 8192);
    uint32_t wh = 0u, wl = 0u;
    if (j >= 168) {
        // zero pad
    } else if (j >= 40) {
        size_t src = ((size_t)n * 8192 + b) * 128 + (j - 40);
        wh = fh[src]; wl = fl[src];
    } else {
        int c0 = (2 * j) % 10, s = (2 * j) / 10;
        int nei = nei_of(n, s);
        float p0 = 0.f, p1 = 0.f;
        if (nei >= 0) {
            const float* pp = preds + ((size_t)nei * 8192 + b) * 10 + c0;
            p0 = pp[0]; p1 = pp[1];
        }
        packpair(p0, p1, wh, wl);
    }
    ih[idx] = wh;
    il[idx] = wl;
}

__global__ __launch_bounds__(NTHREADS) void mean_kernel(
    const float* __restrict__ second, float* __restrict__ mean)
{
    int idx = blockIdx.x * NTHREADS + threadIdx.x;
    if (idx >= 81920) return;
    float s = 0.f;
    #pragma unroll
    for (int n = 0; n < 25; n++) s += second[(size_t)n * 81920 + idx];
    mean[idx] = s * 0.04f;
}

// ---------------------------------------------------------------------------
// launch
// ---------------------------------------------------------------------------
extern "C" void kernel_launch(void* const* d_in, const int* in_sizes, int n_in,
                              void* d_out, int out_size)
{
    (void)in_sizes; (void)n_in; (void)out_size;
    float* arena = nullptr;
    uint32_t *w2h, *w2l, *w3h, *w3l, *w4h, *w4l, *wah, *wal;
    float *sc2, *sh2, *sc3, *sh3, *sc4, *sh4;
    cudaGetSymbolAddress((void**)&arena, g_arena);
    cudaGetSymbolAddress((void**)&w2h, g_w2h);  cudaGetSymbolAddress((void**)&w2l, g_w2l);
    cudaGetSymbolAddress((void**)&w3h, g_w3h);  cudaGetSymbolAddress((void**)&w3l, g_w3l);
    cudaGetSymbolAddress((void**)&w4h, g_w4h);  cudaGetSymbolAddress((void**)&w4l, g_w4l);
    cudaGetSymbolAddress((void**)&wah, g_wah);  cudaGetSymbolAddress((void**)&wal, g_wal);
    cudaGetSymbolAddress((void**)&sc2, g_sc2);  cudaGetSymbolAddress((void**)&sh2, g_sh2);
    cudaGetSymbolAddress((void**)&sc3, g_sc3);  cudaGetSymbolAddress((void**)&sh3, g_sh3);
    cudaGetSymbolAddress((void**)&sc4, g_sc4);  cudaGetSymbolAddress((void**)&sh4, g_sh4);
    uint32_t* arenau = (uint32_t*)arena;

    const float* x   = (const float*)d_in[0];
    const float* W1  = (const float*)d_in[1];
    const float* b1  = (const float*)d_in[2];
    const float* g1  = (const float*)d_in[3];
    const float* be1 = (const float*)d_in[4];
    const float* m1  = (const float*)d_in[5];
    const float* v1  = (const float*)d_in[6];
    const float* W2  = (const float*)d_in[7];
    const float* b2  = (const float*)d_in[8];
    const float* g2  = (const float*)d_in[9];
    const float* be2 = (const float*)d_in[10];
    const float* m2  = (const float*)d_in[11];
    const float* v2  = (const float*)d_in[12];
    const float* W3  = (const float*)d_in[13];
    const float* b3  = (const float*)d_in[14];
    const float* g3  = (const float*)d_in[15];
    const float* be3 = (const float*)d_in[16];
    const float* m3  = (const float*)d_in[17];
    const float* v3  = (const float*)d_in[18];
    const float* W4  = (const float*)d_in[19];
    const float* b4  = (const float*)d_in[20];
    const float* g4  = (const float*)d_in[21];
    const float* be4 = (const float*)d_in[22];
    const float* m4  = (const float*)d_in[23];
    const float* v4  = (const float*)d_in[24];
    const float* Wa  = (const float*)d_in[25];
    const float* ba  = (const float*)d_in[26];
    const float* Wb  = (const float*)d_in[27];
    const float* bb  = (const float*)d_in[28];
    float* out = (float*)d_out;

    // prep: weight splits + BN folds (3,119,872 work items)
    prep_kernel<<<12187, NTHREADS>>>(W2, W3, W4, Wa,
        b2, g2, be2, m2, v2, b3, g3, be3, m3, v3, b4, g4, be4, m4, v4);

    // conv1 + pool1 FUSED -> split32 p1 (no c1 gmem round trip)
    conv1_pool_kernel<<<BATCH, NTHREADS>>>(x, W1, b1, g1, be1, m1, v1,
                                           arenau + OFF_P1);
    // conv2: implicit-im2col bf16 GEMM (K=576, nch=36) -> float c2
    gemm_bf16<0, 64, 10><<<dim3(1, 6400, 1), NTHREADS>>>(
        arenau + OFF_P1, nullptr, w2h, w2l, arena + OFF_C2, nullptr,
        sc2, sh2, nullptr, 576, 128, 128, 0, 0, 0);
    // pool2 (split32, block-tiled smem)
    pool2_kernel<<<16384, NTHREADS>>>(arena + OFF_C2, arenau + OFF_P2);
    // conv3 (K=1152, nch=72) -> split32 c3
    gemm_bf16<1, 128, 5><<<dim3(2, 1600, 1), NTHREADS>>>(
        arenau + OFF_P2, nullptr, w3h, w3l, arenau + OFF_C3, nullptr,
        sc3, sh3, nullptr, 1152, 256, 256, 0, 0, 0);
    // conv4 (K=2304, nch=144) -> pair-packed feats h/l
    gemm_bf16<2, 256, 5><<<dim3(2, 1600, 1), NTHREADS>>>(
        arenau + OFF_C3, nullptr, w4h, w4l,
        arenau + OFF_FEATS_H, arenau + OFF_FEATS_L,
        sc4, sh4, nullptr, 2304, 256, 256, 0, 0, 0);
    // stage 1 MLP (K=256, nch=16, Wa rows 80:336 -> kpOff=40) -> float H
    gemm_bf16<3, 0, 0><<<dim3(5, 64, 25), NTHREADS>>>(
        arenau + OFF_FEATS_H, arenau + OFF_FEATS_L, wah, wal,
        arena + OFF_H, nullptr, nullptr, nullptr, ba,
        256, 600, 600, 128, 105600, 40);
    gemm2_softmax_kernel<<<dim3(1024, 25), NTHREADS>>>(arena + OFF_H, Wb, bb,
                                                       arena + OFF_PREDS);
    // gather -> pair-packed in2 h/l (176 words/row, zero pad)
    {
        long long total = 25LL * 8192 * 176;
        gather_kernel<<<(int)((total + NTHREADS - 1) / NTHREADS), NTHREADS>>>(
            arena + OFF_PREDS, arenau + OFF_FEATS_H, arenau + OFF_FEATS_L,
            arenau + OFF_IN2_H, arenau + OFF_IN2_L);
    }
    // stage 2 MLP (K padded 336->352, nch=22)
    gemm_bf16<3, 0, 0><<<dim3(5, 64, 25), NTHREADS>>>(
        arenau + OFF_IN2_H, arenau + OFF_IN2_L, wah, wal,
        arena + OFF_H, nullptr, nullptr, nullptr, ba,
        352, 600, 600, 176, 105600, 0);
    gemm2_softmax_kernel<<<dim3(1024, 25), NTHREADS>>>(arena + OFF_H, Wb, bb,
                                                       out + 81920);
    mean_kernel<<<320, NTHREADS>>>(out + 81920, out);
}

// round 17
// speedup vs baseline: 1.5558x; 1.0150x over previous
#include <cuda_runtime.h>
#include <cstdint>
#include <cstddef>

#define NTHREADS 256
#define BATCH 8192

// ---------------------------------------------------------------------------
// Scratch arena (word offsets, 4B words; lifetimes verified):
//  p1    [209715200, 262144000)    split32 pool1 out [b][64][10][10]
//  c2    [0, 104857600)            float   conv2 out [b][128][10][10]
//  p2    [104857600, 131072000)    split32 pool2 out
//  c3    [131072000, 183500800)    split32 conv3 out [b][256][5][5]
//  featsH[0, 26214400) featsL[26214400, 52428800)  pair-packed [25][8192][128w]
//  part  [52428800, 62668800)      float   [5][25][8192][10] logit partials
//  preds [183500800, 185548800)    float   [25][8192][10]
//  in2H  [185548800, 221593600) in2L [221593600, 257638400) [25][8192][176w]
// ---------------------------------------------------------------------------
__device__ float g_arena[262144000];     // 1.049 GB

static const size_t OFF_P1      = 209715200;
static const size_t OFF_C2      = 0;
static const size_t OFF_P2      = 104857600;
static const size_t OFF_C3      = 131072000;
static const size_t OFF_FEATS_H = 0;
static const size_t OFF_FEATS_L = 26214400;
static const size_t OFF_PART    = 52428800;
static const size_t OFF_PREDS   = 183500800;
static const size_t OFF_IN2_H   = 185548800;
static const size_t OFF_IN2_L   = 221593600;

// pre-split weight planes, pair-packed along k: word(kp,n) = bf16(k=2kp+1)<<16 | bf16(k=2kp)
// wa planes padded to 176 kp-rows per node (rows 168..175 are zero) so MLP2 K=352 (even chunks)
__device__ uint32_t g_w2h[288 * 128],  g_w2l[288 * 128];
__device__ uint32_t g_w3h[576 * 256],  g_w3l[576 * 256];
__device__ uint32_t g_w4h[1152 * 256], g_w4l[1152 * 256];
__device__ uint32_t g_wah[25 * 176 * 600], g_wal[25 * 176 * 600];
__device__ float g_sc2[128], g_sh2[128];
__device__ float g_sc3[256], g_sh3[256];
__device__ float g_sc4[256], g_sh4[256];

// ---------------------------------------------------------------------------
// bf16 helpers
// ---------------------------------------------------------------------------
__device__ __forceinline__ uint32_t f2bf(float x)
{
    unsigned short h;
    asm("cvt.rn.bf16.f32 %0, %1;" : "=h"(h) : "f"(x));
    return (uint32_t)h;
}

// element-split32: hi bf16 in high halfword, lo bf16 in low halfword
__device__ __forceinline__ uint32_t split32(float x)
{
    uint32_t hb = f2bf(x);
    float r = x - __uint_as_float(hb << 16);
    uint32_t lb = f2bf(r);
    return (hb << 16) | lb;
}

// pair-pack two floats into (h-plane word, l-plane word)
__device__ __forceinline__ void packpair(float x0, float x1, uint32_t& wh, uint32_t& wl)
{
    uint32_t s0 = split32(x0), s1 = split32(x1);
    wh = __byte_perm(s0, s1, 0x7632);   // [s0.hi16, s1.hi16]
    wl = __byte_perm(s0, s1, 0x5410);   // [s0.lo16, s1.lo16]
}

__device__ __forceinline__ void mma16(float d[4], const uint32_t a[4], const uint32_t b[2])
{
    asm volatile(
        "mma.sync.aligned.m16n8k16.row.col.f32.bf16.bf16.f32 "
        "{%0,%1,%2,%3}, {%4,%5,%6,%7}, {%8,%9}, {%0,%1,%2,%3};\n"
        : "+f"(d[0]), "+f"(d[1]), "+f"(d[2]), "+f"(d[3])
        : "r"(a[0]), "r"(a[1]), "r"(a[2]), "r"(a[3]), "r"(b[0]), "r"(b[1]));
}

#define LDSM_X4(r0, r1, r2, r3, addr)                                            \
    asm volatile("ldmatrix.sync.aligned.m8n8.x4.shared.b16 {%0,%1,%2,%3}, [%4];" \
                 : "=r"(r0), "=r"(r1), "=r"(r2), "=r"(r3) : "r"(addr))

// ---------------------------------------------------------------------------
// prep: split+pack weights into bf16 planes + BN folds
// ---------------------------------------------------------------------------
__global__ __launch_bounds__(NTHREADS) void prep_kernel(
    const float* __restrict__ W2, const float* __restrict__ W3,
    const float* __restrict__ W4, const float* __restrict__ Wa,
    const float* __restrict__ b2, const float* __restrict__ g2, const float* __restrict__ be2,
    const float* __restrict__ m2, const float* __restrict__ v2,
    const float* __restrict__ b3, const float* __restrict__ g3, const float* __restrict__ be3,
    const float* __restrict__ m3, const float* __restrict__ v3,
    const float* __restrict__ b4, const float* __restrict__ g4, const float* __restrict__ be4,
    const float* __restrict__ m4, const float* __restrict__ v4)
{
    int i = blockIdx.x * NTHREADS + threadIdx.x;
    if (i < 36864) {                                   // w2: [288kp][128n]
        int kp = i >> 7, n = i & 127;
        packpair(W2[n * 576 + 2 * kp], W2[n * 576 + 2 * kp + 1], g_w2h[i], g_w2l[i]);
    }
    int i3 = i - 36864;
    if (i3 >= 0 && i3 < 147456) {                      // w3: [576kp][256n]
        int kp = i3 >> 8, n = i3 & 255;
        packpair(W3[n * 1152 + 2 * kp], W3[n * 1152 + 2 * kp + 1], g_w3h[i3], g_w3l[i3]);
    }
    int i4 = i - 36864 - 147456;
    if (i4 >= 0 && i4 < 294912) {                      // w4: [1152kp][256n]
        int kp = i4 >> 8, n = i4 & 255;
        packpair(W4[n * 2304 + 2 * kp], W4[n * 2304 + 2 * kp + 1], g_w4h[i4], g_w4l[i4]);
    }
    int ia = i - 36864 - 147456 - 294912;
    if (ia >= 0 && ia < 2640000) {                     // wa: [25z][176kp][600j]
        int z = ia / 105600, r = ia % 105600;
        int kp = r / 600, j = r % 600;
        if (kp < 168) {
            const float* w = Wa + ((size_t)z * 336 + 2 * kp) * 600 + j;
            packpair(w[0], w[600], g_wah[ia], g_wal[ia]);
        } else {
            g_wah[ia] = 0u; g_wal[ia] = 0u;
        }
    }
    int ib = i - 36864 - 147456 - 294912 - 2640000;
    if (ib >= 0 && ib < 128) {
        float s = g2[ib] * rsqrtf(v2[ib] + 1e-5f);
        g_sc2[ib] = s; g_sh2[ib] = (b2[ib] - m2[ib]) * s + be2[ib];
    } else if (ib >= 128 && ib < 384) {
        int c = ib - 128;
        float s = g3[c] * rsqrtf(v3[c] + 1e-5f);
        g_sc3[c] = s; g_sh3[c] = (b3[c] - m3[c]) * s + be3[c];
    } else if (ib >= 384 && ib < 640) {
        int c = ib - 384;
        float s = g4[c] * rsqrtf(v4[c] + 1e-5f);
        g_sc4[c] = s; g_sh4[c] = (b4[c] - m4[c]) * s + be4[c];
    }
}

// ---------------------------------------------------------------------------
// conv1 + pool1 FUSED: 3 -> 64, 20x20, BN+ReLU, then maxpool 3x3 s2 p1,
// split32 out [b][64][10][10]. One block per image; co processed in groups
// of 12 via a 12x20x20 smem staging buffer (no gmem round trip for c1).
// ---------------------------------------------------------------------------
__global__ __launch_bounds__(NTHREADS) void conv1_pool_kernel(
    const float* __restrict__ x, const float* __restrict__ W,
    const float* __restrict__ bias, const float* __restrict__ gam,
    const float* __restrict__ bet, const float* __restrict__ mu,
    const float* __restrict__ var, uint32_t* __restrict__ out)
{
    __shared__ float sIn[3 * 22 * 22];
    __shared__ float sW[64 * 27];
    __shared__ float sScale[64], sShift[64];
    __shared__ float sBuf[12 * 400];
    int b = blockIdx.x, tid = threadIdx.x;

    for (int i = tid; i < 3 * 22 * 22; i += NTHREADS) sIn[i] = 0.f;
    __syncthreads();
    const float* xb = x + (size_t)b * 1200;
    for (int i = tid; i < 1200; i += NTHREADS) {
        int ci = i / 400, p = i % 400, y = p / 20, xx = p % 20;
        sIn[ci * 484 + (y + 1) * 22 + (xx + 1)] = xb[i];
    }
    for (int i = tid; i < 1728; i += NTHREADS) sW[i] = W[i];
    if (tid < 64) {
        float sc = gam[tid] * rsqrtf(var[tid] + 1e-5f);
        sScale[tid] = sc;
        sShift[tid] = (bias[tid] - mu[tid]) * sc + bet[tid];
    }
    __syncthreads();

    int colT = tid / 20, yT = tid % 20;   // compute-phase mapping (threads 240..255 idle)
    #pragma unroll 1
    for (int g = 0; g < 6; g++) {
        int coBase = g * 12;
        int nco = (coBase + 12 <= 64) ? 12 : (64 - coBase);
        if (colT < nco) {
            int co = coBase + colT;
            float scale = sScale[co], shift = sShift[co];
            float acc[20];
            #pragma unroll
            for (int xx = 0; xx < 20; xx++) acc[xx] = 0.f;
            #pragma unroll
            for (int ci = 0; ci < 3; ci++) {
                float w[9];
                #pragma unroll
                for (int k = 0; k < 9; k++) w[k] = sW[co * 27 + ci * 9 + k];
                const float* base = sIn + ci * 484 + yT * 22;
                #pragma unroll
                for (int dy = 0; dy < 3; dy++) {
                    const float* row = base + dy * 22;
                    #pragma unroll
                    for (int xx = 0; xx < 20; xx++)
                        acc[xx] += row[xx] * w[dy * 3] + row[xx + 1] * w[dy * 3 + 1]
                                 + row[xx + 2] * w[dy * 3 + 2];
                }
            }
            #pragma unroll
            for (int xx = 0; xx < 20; xx++)
                sBuf[colT * 400 + yT * 20 + xx] = fmaxf(acc[xx] * scale + shift, 0.f);
        }
        __syncthreads();
        // pool 3x3 s2 p1: 20x20 -> 10x10 per channel
        for (int i = tid; i < nco * 100; i += NTHREADS) {
            int col = i / 100, p = i % 100, oy = p / 10, ox = p % 10;
            const float* bufc = sBuf + col * 400;
            float m = -3.402823466e38f;
            #pragma unroll
            for (int dy = 0; dy < 3; dy++) {
                int iy = 2 * oy - 1 + dy;
                if (iy < 0 || iy >= 20) continue;
                #pragma unroll
                for (int dx = 0; dx < 3; dx++) {
                    int ix = 2 * ox - 1 + dx;
                    if (ix < 0 || ix >= 20) continue;
                    m = fmaxf(m, bufc[iy * 20 + ix]);
                }
            }
            out[((size_t)b * 64 + coBase + col) * 100 + p] = split32(m);
        }
        __syncthreads();
    }
}

// ---------------------------------------------------------------------------
// pool2: maxpool 3x3 s2 p1 over 10x10 planes, float in -> split32 out.
// Block-tiled: 256 threads load 64 contiguous (b,c) planes into smem.
// ---------------------------------------------------------------------------
__global__ __launch_bounds__(NTHREADS) void pool2_kernel(
    const float* __restrict__ in, uint32_t* __restrict__ out)
{
    __shared__ float s[64 * 100];
    int blk = blockIdx.x, tid = threadIdx.x;
    size_t base = (size_t)blk * 6400;
    for (int i = tid; i < 6400; i += NTHREADS)
        s[i] = in[base + i];
    __syncthreads();
    size_t obase = (size_t)blk * 1600;
    for (int i = tid; i < 1600; i += NTHREADS) {
        int pl = i / 25, p = i % 25, oy = p / 5, ox = p % 5;
        const float* sp = s + pl * 100;
        float m = -3.402823466e38f;
        #pragma unroll
        for (int dy = 0; dy < 3; dy++) {
            int iy = 2 * oy - 1 + dy;
            if (iy < 0 || iy >= 10) continue;
            #pragma unroll
            for (int dx = 0; dx < 3; dx++) {
                int ix = 2 * ox - 1 + dx;
                if (ix < 0 || ix >= 10) continue;
                m = fmaxf(m, sp[iy * 10 + ix]);
            }
        }
        out[obase + i] = split32(m);
    }
}

// ---------------------------------------------------------------------------
// bf16 tensor-core GEMM, 3-product (Ah·Bh + Al·Bh + Ah·Bl) scheme.
// Tile 128x128x16, 8 warps (4x2), m16n8k16, ldmatrix fragment loads.
// Double-buffered smem, ONE __syncthreads per k-chunk. nch EVEN everywhere.
// EPI: 0 float [b][128][100]; 1 split32 [b][256][25];
//      2 pair-packed feats h/l [n][b][128w];
//      3 FUSED MLP logits: tanh + project to 10 classes, deterministic
//        CTA reduction -> partial[bx][z][row][10] (no H materialization).
//        For EPI3: sc = Wb [25][600][10], bias = ba [25][600], Cv = partial.
// ---------------------------------------------------------------------------
#define GEMM_FETCH(kc_)                                                          \
    {                                                                            \
        int kc__ = (kc_);                                                        \
        if (CC == 0) {                                                           \
            uint4 h4 = *(const uint4*)(Abh + (size_t)(mBase + lm) * aw           \
                                       + (kc__ >> 1) + (lkq >> 1));              \
            uint4 l4 = *(const uint4*)(Abl + (size_t)(mBase + lm) * aw           \
                                       + (kc__ >> 1) + (lkq >> 1));              \
            avh[0] = h4.x; avh[1] = h4.y; avh[2] = h4.z; avh[3] = h4.w;          \
            avl[0] = l4.x; avl[1] = l4.y; avl[2] = l4.z; avl[3] = l4.w;          \
        } else {                                                                 \
            uint32_t e[8];                                                       \
            int k0__ = kc__ + lkq;                                               \
            int ci__ = k0__ / 9;                                                 \
            int q__  = k0__ - ci__ * 9;                                          \
            _Pragma("unroll")                                                    \
            for (int j = 0; j < 8; j++) {                                        \
                int qy = (q__ * 11) >> 5, qx = q__ - qy * 3;                     \
                int iy = py - 1 + qy, ix = px - 1 + qx;                          \
                uint32_t v = 0u;                                                 \
                if (iy >= 0 && iy < S && ix >= 0 && ix < S)                      \
                    v = A[ib_off + ci__ * S * S + iy * S + ix];                  \
                e[j] = v;                                                        \
                q__++;                                                           \
                if (q__ == 9) { q__ = 0; ci__++; }                               \
            }                                                                    \
            _Pragma("unroll")                                                    \
            for (int tt = 0; tt < 4; tt++) {                                     \
                avh[tt] = __byte_perm(e[2 * tt], e[2 * tt + 1], 0x7632);         \
                avl[tt] = __byte_perm(e[2 * tt], e[2 * tt + 1], 0x5410);         \
            }                                                                    \
        }                                                                        \
        _Pragma("unroll")                                                        \
        for (int jj = 0; jj < 4; jj++) {                                         \
            int kp = (kc__ >> 1) + (lkq >> 1) + jj;                              \
            bvh[jj] = (gn < N) ? Bbh[(size_t)kp * ldb + gn] : 0u;                \
            bvl[jj] = (gn < N) ? Bbl[(size_t)kp * ldb + gn] : 0u;                \
        }                                                                        \
    }

// store staged regs into buffer at word offset BUFW (0 or 6144)
#define GEMM_STORE(BUFW)                                                         \
    {                                                                            \
        *(uint4*)&smemAll[(BUFW) + 0    + sIdx] = make_uint4(avh[0], avh[1], avh[2], avh[3]); \
        *(uint4*)&smemAll[(BUFW) + 1536 + sIdx] = make_uint4(avl[0], avl[1], avl[2], avl[3]); \
        *(uint4*)&smemAll[(BUFW) + 3072 + sIdx] = make_uint4(bvh[0], bvh[1], bvh[2], bvh[3]); \
        *(uint4*)&smemAll[(BUFW) + 4608 + sIdx] = make_uint4(bvl[0], bvl[1], bvl[2], bvl[3]); \
    }

// compute from buffer at byte offset BUFB (0u or 24576u)
#define GEMM_COMPUTE(BUFB)                                                       \
    {                                                                            \
        uint32_t fah[2][4], fal[2][4];                                           \
        LDSM_X4(fah[0][0], fah[0][1], fah[0][2], fah[0][3], adrAh + (BUFB));     \
        LDSM_X4(fah[1][0], fah[1][1], fah[1][2], fah[1][3], adrAh + (BUFB) + 768u); \
        LDSM_X4(fal[0][0], fal[0][1], fal[0][2], fal[0][3], adrAl + (BUFB));     \
        LDSM_X4(fal[1][0], fal[1][1], fal[1][2], fal[1][3], adrAl + (BUFB) + 768u); \
        _Pragma("unroll")                                                        \
        for (int bt = 0; bt < 2; bt++) {                                         \
            uint32_t bh[8], bl[8];                                               \
            LDSM_X4(bh[0], bh[1], bh[2], bh[3], adrBh + (BUFB) + bt * 1536u);    \
            LDSM_X4(bh[4], bh[5], bh[6], bh[7], adrBh + (BUFB) + bt * 1536u + 768u); \
            LDSM_X4(bl[0], bl[1], bl[2], bl[3], adrBl + (BUFB) + bt * 1536u);    \
            LDSM_X4(bl[4], bl[5], bl[6], bl[7], adrBl + (BUFB) + bt * 1536u + 768u); \
            _Pragma("unroll")                                                    \
            for (int n4 = 0; n4 < 4; n4++) {                                     \
                int nt = bt * 4 + n4;                                            \
                uint32_t bhf[2] = { bh[n4 * 2], bh[n4 * 2 + 1] };                \
                uint32_t blf[2] = { bl[n4 * 2], bl[n4 * 2 + 1] };                \
                _Pragma("unroll")                                                \
                for (int mt = 0; mt < 2; mt++) {                                 \
                    mma16(acc[mt][nt], fah[mt], bhf);                            \
                    mma16(acc[mt][nt], fal[mt], bhf);                            \
                    mma16(acc[mt][nt], fah[mt], blf);                            \
                }                                                                \
            }                                                                    \
        }                                                                        \
    }

template <int EPI, int CC, int S>
__global__ __launch_bounds__(NTHREADS, 2) void gemm_bf16(
    const uint32_t* __restrict__ A, const uint32_t* __restrict__ A2,
    const uint32_t* __restrict__ Bh, const uint32_t* __restrict__ Bl,
    void* __restrict__ Cv, void* __restrict__ C2v,
    const float* __restrict__ sc, const float* __restrict__ sh,
    const float* __restrict__ bias,
    int K, int N, int ldb, int aw, int bStrideZ, int kpOff)
{
    // plane order (1536 words each): Ah0 Al0 Bh0 Bl0 | Ah1 Al1 Bh1 Bl1
    __shared__ uint32_t smemAll[12288];   // 48 KB

    int z = blockIdx.z;
    const uint32_t* Abh = A;
    const uint32_t* Abl = A2;
    const uint32_t* Bbh = Bh + (size_t)kpOff * ldb;
    const uint32_t* Bbl = Bl + (size_t)kpOff * ldb;
    if (EPI == 3) {
        Abh += (size_t)z * 8192 * aw;
        Abl += (size_t)z * 8192 * aw;
        Bbh += (size_t)z * bStrideZ;
        Bbl += (size_t)z * bStrideZ;
    }
    int mBase = blockIdx.y * 128, nBase = blockIdx.x * 128;
    int t = threadIdx.x, lane = t & 31, wid = t >> 5;
    int wm = (wid & 3) * 32, wn = (wid >> 2) * 64;

    int lm = t & 127, lkq = (t >> 7) * 8;
    int gn = nBase + lm;
    uint32_t sIdx = (uint32_t)(lm * 12 + (lkq >> 1));

    int ib_off = 0, py = 0, px = 0;
    if (CC > 0) {
        const int SS = S * S;
        int r = mBase + lm;
        int b = r / SS, p = r - b * SS;
        py = p / S; px = p - py * S;
        ib_off = b * CC * SS;
    }

    // ldmatrix per-lane source addresses (buffer-0 bases; buffer 1 = +24576B)
    uint32_t base_u = (uint32_t)__cvta_generic_to_shared(smemAll);
    int lt = lane >> 3, lrow = lane & 7;
    uint32_t aOff = (uint32_t)(((wm + ((lt & 1) << 3) + lrow) * 12 + ((lt >> 1) << 2)) * 4);
    uint32_t bOff = (uint32_t)(((wn + ((lt >> 1) << 3) + lrow) * 12 + ((lt & 1) << 2)) * 4);
    uint32_t adrAh = base_u + aOff;
    uint32_t adrAl = base_u + 6144u + aOff;
    uint32_t adrBh = base_u + 12288u + bOff;
    uint32_t adrBl = base_u + 18432u + bOff;

    float acc[2][8][4];
    #pragma unroll
    for (int mt = 0; mt < 2; mt++)
        #pragma unroll
        for (int nt = 0; nt < 8; nt++)
            #pragma unroll
            for (int e = 0; e < 4; e++) acc[mt][nt][e] = 0.f;

    uint32_t avh[4], avl[4], bvh[4], bvl[4];
    GEMM_FETCH(0);

    int nch = K / 16;   // even by construction at every call site
    for (int ch = 0; ch < nch; ch += 2) {
        // chunk ch -> buffer 0
        GEMM_STORE(0);
        __syncthreads();
        GEMM_FETCH((ch + 1) * 16);
        GEMM_COMPUTE(0u);
        // chunk ch+1 -> buffer 1
        GEMM_STORE(6144);
        __syncthreads();
        {
            int kcn = (ch + 2 < nch) ? (ch + 2) * 16 : 0;
            GEMM_FETCH(kcn);
        }
        GEMM_COMPUTE(24576u);
    }

    // epilogue
    int elc = lane & 3, elr = lane >> 2;
    if (EPI == 3) {
        // fused logits: tanh + project 10 classes, deterministic reduction.
        // smem reuse (buffer-0 region; safe: last buf0 reads preceded the
        // final __syncthreads of the mainloop):
        float* sWb  = (float*)smemAll;           // [128 cols][10]
        float* sLog = (float*)smemAll + 1280;    // [128 rows][10]
        float* sBa  = (float*)smemAll + 2560;    // [128 cols]
        int ncols = N - nBase; if (ncols > 128) ncols = 128;
        const float* WbZ = sc + (size_t)z * (N * 10) + (size_t)nBase * 10;
        const float* baZ = bias + (size_t)z * N + nBase;
        for (int i = t; i < ncols * 10; i += NTHREADS) sWb[i] = WbZ[i];
        for (int i = t; i < ncols; i += NTHREADS) sBa[i] = baZ[i];
        for (int i = t; i < 1280; i += NTHREADS) sLog[i] = 0.f;
        __syncthreads();

        #pragma unroll
        for (int mt = 0; mt < 2; mt++) {
            #pragma unroll
            for (int rr = 0; rr < 2; rr++) {
                float part[10];
                #pragma unroll
                for (int c = 0; c < 10; c++) part[c] = 0.f;
                #pragma unroll
                for (int nt = 0; nt < 8; nt++) {
                    #pragma unroll
                    for (int eo = 0; eo < 2; eo++) {
                        int col = wn + nt * 8 + 2 * elc + eo;   // tile-local
                        if (nBase + col < N) {
                            float v = tanhf(acc[mt][nt][rr * 2 + eo] + sBa[col]);
                            const float* wrow = sWb + col * 10;
                            #pragma unroll
                            for (int c = 0; c < 10; c++) part[c] += v * wrow[c];
                        }
                    }
                }
                // reduce across the 4 lanes sharing this row (elc bits)
                #pragma unroll
                for (int c = 0; c < 10; c++) {
                    part[c] += __shfl_xor_sync(0xffffffffu, part[c], 1);
                    part[c] += __shfl_xor_sync(0xffffffffu, part[c], 2);
                }
                int row = wm + mt * 16 + elr + rr * 8;          // tile-local
                // two-stage deterministic combine across warp-columns
                if ((wid >> 2) == 0 && elc == 0) {
                    #pragma unroll
                    for (int c = 0; c < 10; c++) sLog[row * 10 + c] = part[c];
                }
                __syncthreads();
                if ((wid >> 2) == 1 && elc == 0) {
                    #pragma unroll
                    for (int c = 0; c < 10; c++) sLog[row * 10 + c] += part[c];
                }
                __syncthreads();
            }
        }
        // write partial block: partial[bx][z][mBase..mBase+127][10]
        size_t pbase = ((size_t)blockIdx.x * 25 + z) * 81920 + (size_t)mBase * 10;
        for (int i = t; i < 1280; i += NTHREADS)
            ((float*)Cv)[pbase + i] = sLog[i];
    } else {
        #pragma unroll
        for (int mt = 0; mt < 2; mt++) {
            #pragma unroll
            for (int nt = 0; nt < 8; nt++) {
                if (EPI == 2) {
                    #pragma unroll
                    for (int rr = 0; rr < 2; rr++) {
                        int row = mBase + wm + mt * 16 + elr + rr * 8;
                        int col = nBase + wn + nt * 8 + 2 * elc;
                        float v0 = acc[mt][nt][rr * 2 + 0];
                        float v1 = acc[mt][nt][rr * 2 + 1];
                        v0 = fmaxf(v0 * sc[col] + sh[col], 0.f);
                        v1 = fmaxf(v1 * sc[col + 1] + sh[col + 1], 0.f);
                        int b = row / 25, p = row - b * 25;
                        uint32_t wh, wl;
                        packpair(v0, v1, wh, wl);
                        size_t o = ((size_t)p * 8192 + b) * 128 + (col >> 1);
                        ((uint32_t*)Cv)[o]  = wh;
                        ((uint32_t*)C2v)[o] = wl;
                    }
                } else {
                    #pragma unroll
                    for (int e = 0; e < 4; e++) {
                        int row = mBase + wm + mt * 16 + elr + (e >> 1) * 8;
                        int col = nBase + wn + nt * 8 + 2 * elc + (e & 1);
                        float v = acc[mt][nt][e];
                        if (EPI == 0) {
                            int b = row / 100, p = row - b * 100;
                            ((float*)Cv)[((size_t)b * 128 + col) * 100 + p] =
                                fmaxf(v * sc[col] + sh[col], 0.f);
                        } else {
                            int b = row / 25, p = row - b * 25;
                            ((uint32_t*)Cv)[((size_t)b * 256 + col) * 25 + p] =
                                split32(fmaxf(v * sc[col] + sh[col], 0.f));
                        }
                    }
                }
            }
        }
    }
}

// ---------------------------------------------------------------------------
// finalize: sum 5 bx-partials (fixed order) + bb, softmax -> out [25][8192][10]
// ---------------------------------------------------------------------------
__global__ __launch_bounds__(NTHREADS) void finalize_softmax_kernel(
    const float* __restrict__ partial, const float* __restrict__ bb,
    float* __restrict__ out)
{
    int idx = blockIdx.x * NTHREADS + threadIdx.x;
    if (idx >= 204800) return;
    int z = idx / 8192, b = idx - z * 8192;
    float l[10];
    #pragma unroll
    for (int c = 0; c < 10; c++) l[c] = bb[z * 10 + c];
    #pragma unroll
    for (int bx = 0; bx < 5; bx++) {
        const float* p = partial + ((size_t)bx * 25 + z) * 81920 + (size_t)b * 10;
        #pragma unroll
        for (int c = 0; c < 10; c++) l[c] += p[c];
    }
    float mx = -3.402823466e38f;
    #pragma unroll
    for (int c = 0; c < 10; c++) mx = fmaxf(mx, l[c]);
    float s = 0.f;
    #pragma unroll
    for (int c = 0; c < 10; c++) { l[c] = expf(l[c] - mx); s += l[c]; }
    float inv = 1.f / s;
    float* o = out + ((size_t)z * 8192 + b) * 10;
    #pragma unroll
    for (int c = 0; c < 10; c++) o[c] = l[c] * inv;
}

// ---------------------------------------------------------------------------
// neighbor gather -> pair-packed in2 planes (176 words/row; 168..175 zero pad)
// ---------------------------------------------------------------------------
__device__ __forceinline__ int nei_of(int i, int slot)
{
    int nb[8];
    #pragma unroll
    for (int t = 0; t < 8; t++) nb[t] = -1;
    int cnt = 0;
    bool l = (i % 5 != 0), r = ((i + 1) % 5 != 0), u = (i >= 5), d = (i + 5 < 25);
    if (u)      nb[cnt++] = i - 5;
    if (l)      nb[cnt++] = i - 1;
    if (r)      nb[cnt++] = i + 1;
    if (d)      nb[cnt++] = i + 5;
    if (u && l) nb[cnt++] = i - 6;
    if (u && r) nb[cnt++] = i - 4;
    if (d && l) nb[cnt++] = i + 4;
    if (d && r) nb[cnt++] = i + 6;
    return nb[slot];
}

__global__ __launch_bounds__(NTHREADS) void gather_kernel(
    const float* __restrict__ preds,
    const uint32_t* __restrict__ fh, const uint32_t* __restrict__ fl,
    uint32_t* __restrict__ ih, uint32_t* __restrict__ il)
{
    long long idx = (long long)blockIdx.x * NTHREADS + threadIdx.x;
    if (idx >= 25LL * 8192 * 176) return;
    int j = (int)(idx % 176);
    long long t = idx / 176;
    int b = (int)(t % 8192);
    int n = (int)(t / 8192);
    uint32_t wh = 0u, wl = 0u;
    if (j >= 168) {
        // zero pad
    } else if (j >= 40) {
        size_t src = ((size_t)n * 8192 + b) * 128 + (j - 40);
        wh = fh[src]; wl = fl[src];
    } else {
        int c0 = (2 * j) % 10, s = (2 * j) / 10;
        int nei = nei_of(n, s);
        float p0 = 0.f, p1 = 0.f;
        if (nei >= 0) {
            const float* pp = preds + ((size_t)nei * 8192 + b) * 10 + c0;
            p0 = pp[0]; p1 = pp[1];
        }
        packpair(p0, p1, wh, wl);
    }
    ih[idx] = wh;
    il[idx] = wl;
}

__global__ __launch_bounds__(NTHREADS) void mean_kernel(
    const float* __restrict__ second, float* __restrict__ mean)
{
    int idx = blockIdx.x * NTHREADS + threadIdx.x;
    if (idx >= 81920) return;
    float s = 0.f;
    #pragma unroll
    for (int n = 0; n < 25; n++) s += second[(size_t)n * 81920 + idx];
    mean[idx] = s * 0.04f;
}

// ---------------------------------------------------------------------------
// launch
// ---------------------------------------------------------------------------
extern "C" void kernel_launch(void* const* d_in, const int* in_sizes, int n_in,
                              void* d_out, int out_size)
{
    (void)in_sizes; (void)n_in; (void)out_size;
    float* arena = nullptr;
    uint32_t *w2h, *w2l, *w3h, *w3l, *w4h, *w4l, *wah, *wal;
    float *sc2, *sh2, *sc3, *sh3, *sc4, *sh4;
    cudaGetSymbolAddress((void**)&arena, g_arena);
    cudaGetSymbolAddress((void**)&w2h, g_w2h);  cudaGetSymbolAddress((void**)&w2l, g_w2l);
    cudaGetSymbolAddress((void**)&w3h, g_w3h);  cudaGetSymbolAddress((void**)&w3l, g_w3l);
    cudaGetSymbolAddress((void**)&w4h, g_w4h);  cudaGetSymbolAddress((void**)&w4l, g_w4l);
    cudaGetSymbolAddress((void**)&wah, g_wah);  cudaGetSymbolAddress((void**)&wal, g_wal);
    cudaGetSymbolAddress((void**)&sc2, g_sc2);  cudaGetSymbolAddress((void**)&sh2, g_sh2);
    cudaGetSymbolAddress((void**)&sc3, g_sc3);  cudaGetSymbolAddress((void**)&sh3, g_sh3);
    cudaGetSymbolAddress((void**)&sc4, g_sc4);  cudaGetSymbolAddress((void**)&sh4, g_sh4);
    uint32_t* arenau = (uint32_t*)arena;

    const float* x   = (const float*)d_in[0];
    const float* W1  = (const float*)d_in[1];
    const float* b1  = (const float*)d_in[2];
    const float* g1  = (const float*)d_in[3];
    const float* be1 = (const float*)d_in[4];
    const float* m1  = (const float*)d_in[5];
    const float* v1  = (const float*)d_in[6];
    const float* W2  = (const float*)d_in[7];
    const float* b2  = (const float*)d_in[8];
    const float* g2  = (const float*)d_in[9];
    const float* be2 = (const float*)d_in[10];
    const float* m2  = (const float*)d_in[11];
    const float* v2  = (const float*)d_in[12];
    const float* W3  = (const float*)d_in[13];
    const float* b3  = (const float*)d_in[14];
    const float* g3  = (const float*)d_in[15];
    const float* be3 = (const float*)d_in[16];
    const float* m3  = (const float*)d_in[17];
    const float* v3  = (const float*)d_in[18];
    const float* W4  = (const float*)d_in[19];
    const float* b4  = (const float*)d_in[20];
    const float* g4  = (const float*)d_in[21];
    const float* be4 = (const float*)d_in[22];
    const float* m4  = (const float*)d_in[23];
    const float* v4  = (const float*)d_in[24];
    const float* Wa  = (const float*)d_in[25];
    const float* ba  = (const float*)d_in[26];
    const float* Wb  = (const float*)d_in[27];
    const float* bb  = (const float*)d_in[28];
    float* out = (float*)d_out;

    // prep: weight splits + BN folds
    prep_kernel<<<12187, NTHREADS>>>(W2, W3, W4, Wa,
        b2, g2, be2, m2, v2, b3, g3, be3, m3, v3, b4, g4, be4, m4, v4);

    // conv1 + pool1 FUSED -> split32 p1
    conv1_pool_kernel<<<BATCH, NTHREADS>>>(x, W1, b1, g1, be1, m1, v1,
                                           arenau + OFF_P1);
    // conv2: implicit-im2col bf16 GEMM (K=576, nch=36) -> float c2
    gemm_bf16<0, 64, 10><<<dim3(1, 6400, 1), NTHREADS>>>(
        arenau + OFF_P1, nullptr, w2h, w2l, arena + OFF_C2, nullptr,
        sc2, sh2, nullptr, 576, 128, 128, 0, 0, 0);
    // pool2 (split32, block-tiled smem)
    pool2_kernel<<<16384, NTHREADS>>>(arena + OFF_C2, arenau + OFF_P2);
    // conv3 (K=1152, nch=72) -> split32 c3
    gemm_bf16<1, 128, 5><<<dim3(2, 1600, 1), NTHREADS>>>(
        arenau + OFF_P2, nullptr, w3h, w3l, arenau + OFF_C3, nullptr,
        sc3, sh3, nullptr, 1152, 256, 256, 0, 0, 0);
    // conv4 (K=2304, nch=144) -> pair-packed feats h/l
    gemm_bf16<2, 256, 5><<<dim3(2, 1600, 1), NTHREADS>>>(
        arenau + OFF_C3, nullptr, w4h, w4l,
        arenau + OFF_FEATS_H, arenau + OFF_FEATS_L,
        sc4, sh4, nullptr, 2304, 256, 256, 0, 0, 0);
    // stage 1 MLP (K=256, nch=16, Wa rows 80:336 -> kpOff=40)
    //   fused logits -> partial, then finalize -> preds
    gemm_bf16<3, 0, 0><<<dim3(5, 64, 25), NTHREADS>>>(
        arenau + OFF_FEATS_H, arenau + OFF_FEATS_L, wah, wal,
        arena + OFF_PART, nullptr, Wb, nullptr, ba,
        256, 600, 600, 128, 105600, 40);
    finalize_softmax_kernel<<<800, NTHREADS>>>(arena + OFF_PART, bb,
                                               arena + OFF_PREDS);
    // gather -> pair-packed in2 h/l (176 words/row, zero pad)
    {
        long long total = 25LL * 8192 * 176;
        gather_kernel<<<(int)((total + NTHREADS - 1) / NTHREADS), NTHREADS>>>(
            arena + OFF_PREDS, arenau + OFF_FEATS_H, arenau + OFF_FEATS_L,
            arenau + OFF_IN2_H, arenau + OFF_IN2_L);
    }
    // stage 2 MLP (K padded 336->352, nch=22) fused logits -> partial
    gemm_bf16<3, 0, 0><<<dim3(5, 64, 25), NTHREADS>>>(
        arenau + OFF_IN2_H, arenau + OFF_IN2_L, wah, wal,
        arena + OFF_PART, nullptr, Wb, nullptr, ba,
        352, 600, 600, 176, 105600, 0);
    finalize_softmax_kernel<<<800, NTHREADS>>>(arena + OFF_PART, bb,
                                               out + 81920);
    mean_kernel<<<320, NTHREADS>>>(out + 81920, out);
}